// round 11
// baseline (speedup 1.0000x reference)
#include <cuda_runtime.h>
#include <cuda_fp16.h>
#include <math.h>
#include <stdint.h>

#define BD 4096
#define HD 512
#define G4 2048    // 4*H
#define NS 16
#define NTILES 512 // (BD/128) * (G4/128)

// ======================= device scratch (allocation-free) =======================
__device__ __half g_Whh_hi[G4*HD], g_Whh_lo[G4*HD];     // permuted n'=4j+g, K-major
__device__ __half g_Wih_hi[G4*HD], g_Wih_lo[G4*HD];
__device__ __half g_Wout_hi[HD*HD], g_Wout_lo[HD*HD];
__device__ __half g_x_hi[(size_t)BD*HD], g_x_lo[(size_t)BD*HD];
__device__ __half g_h_hi[2][(size_t)BD*HD], g_h_lo[2][(size_t)BD*HD];
__device__ __half g_hf_hi[(size_t)BD*HD], g_hf_lo[(size_t)BD*HD];
__device__ float g_wflag[G4], g_bias[G4];
__device__ float g_xb[(size_t)BD*G4];
__device__ float g_hs[(size_t)NS*BD*HD];
__device__ float g_cs[(size_t)NS*BD*HD];
// ---- ACT state ----
__device__ float g_halt[NS*BD];     // halt prob per (step,row)
__device__ float g_cum[BD];         // running cumsum of halt
__device__ int   g_cnt[NS];         // halted-row counts per step
__device__ int   g_bar[2*NS];       // grid-barrier arrival counters

// ======================= helpers =======================
__device__ __forceinline__ float sigf(float x) {
    return __fdividef(1.f, 1.f + __expf(-x));
}
__device__ __forceinline__ float tanh_acc(float x) {
    float ax = fabsf(x);
    float e  = __expf(-2.f * ax);
    float t  = __fdividef(1.f - e, 1.f + e);
    return copysignf(t, x);
}
__device__ __forceinline__ uint32_t smem_u32(const void* p) {
    uint32_t a;
    asm("{ .reg .u64 t; cvta.to.shared.u64 t, %1; cvt.u32.u64 %0, t; }" : "=r"(a) : "l"(p));
    return a;
}
__device__ __forceinline__ void cpa16(uint32_t d, const void* s) {
    asm volatile("cp.async.cg.shared.global [%0], [%1], 16;" :: "r"(d), "l"(s));
}
__device__ __forceinline__ void cpa_commit() { asm volatile("cp.async.commit_group;"); }
template <int N> __device__ __forceinline__ void cpa_wait() {
    asm volatile("cp.async.wait_group %0;" :: "n"(N));
}
__device__ __forceinline__ void ldsm4(uint32_t* r, uint32_t a) {
    asm volatile("ldmatrix.sync.aligned.m8n8.x4.shared.b16 {%0,%1,%2,%3}, [%4];"
        : "=r"(r[0]), "=r"(r[1]), "=r"(r[2]), "=r"(r[3]) : "r"(a));
}
__device__ __forceinline__ void mma16816(float* c, const uint32_t* a, const uint32_t* b) {
    asm volatile("mma.sync.aligned.m16n8k16.row.col.f32.f16.f16.f32 "
        "{%0,%1,%2,%3}, {%4,%5,%6,%7}, {%8,%9}, {%0,%1,%2,%3};"
        : "+f"(c[0]), "+f"(c[1]), "+f"(c[2]), "+f"(c[3])
        : "r"(a[0]), "r"(a[1]), "r"(a[2]), "r"(a[3]), "r"(b[0]), "r"(b[1]));
}

// smem tile layout: 128 rows x 64B (4 x 16B chunks), XOR-swizzled:
//   phys_chunk = c ^ ((row>>1)&3)  -> conflict-free ldmatrix row sets
#define TILE_BYTES 8192
#define STAGE_BYTES 32768           // Ahi | Alo | Bhi | Blo
#define NSTAGE 3
#define DSMEM_BYTES (NSTAGE * STAGE_BYTES)   // 96KB; C-tile (67.6KB) reuses it
#define CSTRIDE 132

// ======================= prep kernels =======================
__global__ void prep_weights(const float* __restrict__ Wih, const float* __restrict__ Whh,
                             const float* __restrict__ bih, const float* __restrict__ bhh) {
    int idx = blockIdx.x * blockDim.x + threadIdx.x;
    if (idx >= G4 * HD) return;
    int np = idx >> 9, k = idx & 511;
    int j = np >> 2, g = np & 3;
    int row = g * HD + j;
    float wh = Whh[row * HD + k];
    __half h1 = __float2half(wh);
    g_Whh_hi[idx] = h1;
    g_Whh_lo[idx] = __float2half(wh - __half2float(h1));
    float wi = Wih[row * (HD + 1) + 1 + k];
    __half i1 = __float2half(wi);
    g_Wih_hi[idx] = i1;
    g_Wih_lo[idx] = __float2half(wi - __half2float(i1));
    if (k == 0) {
        g_wflag[np] = Wih[row * (HD + 1)];
        g_bias [np] = bih[row] + bhh[row];
    }
}

__global__ void prep_data(const float* __restrict__ x, const float* __restrict__ h0,
                          const float* __restrict__ Wout) {
    size_t idx = (size_t)blockIdx.x * blockDim.x + threadIdx.x;
    if (idx < (size_t)BD * HD) {
        float v = x[idx];
        __half hv = __float2half(v);
        g_x_hi[idx] = hv;
        g_x_lo[idx] = __float2half(v - __half2float(hv));
        float h = h0[idx];
        __half hh = __float2half(h);
        g_h_hi[0][idx] = hh;
        g_h_lo[0][idx] = __float2half(h - __half2float(hh));
    }
    if (idx < (size_t)HD * HD) {
        float w = Wout[idx];
        __half wh = __float2half(w);
        g_Wout_hi[idx] = wh;
        g_Wout_lo[idx] = __float2half(w - __half2float(wh));
    }
    // ---- per-launch ACT state reset ----
    if (idx < BD) g_cum[idx] = 0.f;
    if (idx < NS) g_cnt[idx] = 0;
    if (idx < 2 * NS) g_bar[idx] = 0;
}

// ======================= plain GEMM + bias (x-part & output GEMMs) =======================
__global__ void __launch_bounds__(256, 2)
gemm_bias(const __half* __restrict__ Ahi, const __half* __restrict__ Alo,
          const __half* __restrict__ Bhi, const __half* __restrict__ Blo,
          int Ntot, const float* __restrict__ bias, float* __restrict__ Cout)
{
    extern __shared__ char dsm[];
    const int tid  = threadIdx.x;
    const int wid  = tid >> 5;
    const int lane = tid & 31;
    const int m0 = blockIdx.y * 128;
    const int n0 = blockIdx.x * 128;
    const int wm = (wid & 3) * 32;
    const int wn = (wid >> 2) * 64;
    const uint32_t sbase = smem_u32(dsm);

    float acc[2][8][4];
#pragma unroll
    for (int a = 0; a < 2; a++)
#pragma unroll
        for (int b = 0; b < 8; b++)
#pragma unroll
            for (int q = 0; q < 4; q++) acc[a][b][q] = 0.f;

    auto load_stage = [&](int kc, int s) {
        uint32_t st = sbase + s * STAGE_BYTES;
#pragma unroll
        for (int i = 0; i < 2; i++) {
            int cid = tid + i * 256;
            int row = cid >> 2, c = cid & 3;
            uint32_t off = row * 64 + ((c ^ ((row >> 1) & 3)) << 4);
            size_t ga = (size_t)(m0 + row) * 512 + kc * 32 + c * 8;
            size_t gb = (size_t)(n0 + row) * 512 + kc * 32 + c * 8;
            cpa16(st + off,                  Ahi + ga);
            cpa16(st + TILE_BYTES + off,     Alo + ga);
            cpa16(st + 2 * TILE_BYTES + off, Bhi + gb);
            cpa16(st + 3 * TILE_BYTES + off, Blo + gb);
        }
        cpa_commit();
    };
    auto compute = [&](int s) {
        uint32_t st = sbase + s * STAGE_BYTES;
#pragma unroll
        for (int k16 = 0; k16 < 2; k16++) {
            uint32_t ahi[2][4], alo[2][4];
#pragma unroll
            for (int mt = 0; mt < 2; mt++) {
                int row = wm + mt * 16 + (lane & 7) + ((lane >> 3) & 1) * 8;
                int ch  = k16 * 2 + (lane >> 4);
                uint32_t off = row * 64 + ((ch ^ ((row >> 1) & 3)) << 4);
                ldsm4(ahi[mt], st + off);
                ldsm4(alo[mt], st + TILE_BYTES + off);
            }
#pragma unroll
            for (int ng = 0; ng < 4; ng++) {
                uint32_t bh[4], bl[4];
                int row = wn + ng * 16 + (lane & 7) + ((lane >> 4) & 1) * 8;
                int ch  = k16 * 2 + ((lane >> 3) & 1);
                uint32_t off = row * 64 + ((ch ^ ((row >> 1) & 3)) << 4);
                ldsm4(bh, st + 2 * TILE_BYTES + off);
                ldsm4(bl, st + 3 * TILE_BYTES + off);
#pragma unroll
                for (int mt = 0; mt < 2; mt++)
#pragma unroll
                    for (int nf = 0; nf < 2; nf++)
                        mma16816(acc[mt][ng * 2 + nf], ahi[mt], &bh[nf * 2]);
#pragma unroll
                for (int mt = 0; mt < 2; mt++)
#pragma unroll
                    for (int nf = 0; nf < 2; nf++)
                        mma16816(acc[mt][ng * 2 + nf], ahi[mt], &bl[nf * 2]);
#pragma unroll
                for (int mt = 0; mt < 2; mt++)
#pragma unroll
                    for (int nf = 0; nf < 2; nf++)
                        mma16816(acc[mt][ng * 2 + nf], alo[mt], &bh[nf * 2]);
            }
        }
    };

    load_stage(0, 0);
    load_stage(1, 1);
    for (int kc = 0; kc < 16; kc++) {
        cpa_wait<1>();
        __syncthreads();
        if (kc + 2 < 16) load_stage(kc + 2, (kc + 2) % NSTAGE);
        compute(kc % NSTAGE);
    }
    __syncthreads();

    float* Cs = (float*)dsm;
#pragma unroll
    for (int mt = 0; mt < 2; mt++)
#pragma unroll
        for (int nf = 0; nf < 8; nf++) {
            int row = wm + mt * 16 + (lane >> 2);
            int col = wn + nf * 8 + (lane & 3) * 2;
            Cs[row * CSTRIDE + col]           = acc[mt][nf][0];
            Cs[row * CSTRIDE + col + 1]       = acc[mt][nf][1];
            Cs[(row + 8) * CSTRIDE + col]     = acc[mt][nf][2];
            Cs[(row + 8) * CSTRIDE + col + 1] = acc[mt][nf][3];
        }
    __syncthreads();

    const int ml = tid >> 1;
    const int colbase = (tid & 1) * 64;
    const int m = m0 + ml;
#pragma unroll
    for (int q = 0; q < 16; q++) {
        int ncol = colbase + q * 4;
        float4 v  = *(float4*)&Cs[ml * CSTRIDE + ncol];
        float4 bv = *(const float4*)&bias[n0 + ncol];
        v.x += bv.x; v.y += bv.y; v.z += bv.z; v.w += bv.w;
        *(float4*)&Cout[(size_t)m * Ntot + n0 + ncol] = v;
    }
}

// ======================= persistent ACT step loop =======================
__device__ __forceinline__ void grid_barrier(int idx) {
    __syncthreads();
    if (threadIdx.x == 0) {
        __threadfence();
        atomicAdd(&g_bar[idx], 1);
        while (*(volatile int*)&g_bar[idx] < (int)gridDim.x) { }
    }
    __syncthreads();
}

__global__ void __launch_bounds__(256, 2)
act_steps(const float* __restrict__ c0,
          const float* __restrict__ Whalt, const float* __restrict__ bhalt)
{
    extern __shared__ char dsm[];
    const int tid  = threadIdx.x;
    const int wid  = tid >> 5;
    const int lane = tid & 31;
    const int wm = (wid & 3) * 32;
    const int wn = (wid >> 2) * 64;
    const uint32_t sbase = smem_u32(dsm);
    const size_t HBUF = (size_t)BD * HD;

    for (int n = 0; n < NS; n++) {
        const __half* Ahi = g_h_hi[n & 1];
        const __half* Alo = g_h_lo[n & 1];
        const float* c_in = (n == 0) ? c0 : (g_cs + (size_t)(n - 1) * HBUF);
        float* h_out = g_hs + (size_t)n * HBUF;
        float* c_out = g_cs + (size_t)n * HBUF;
        __half* hhi_out = g_h_hi[(n + 1) & 1];
        __half* hlo_out = g_h_lo[(n + 1) & 1];
        const int step0 = (n == 0);

        for (int t = blockIdx.x; t < NTILES; t += gridDim.x) {
            const int m0 = (t >> 4) * 128;
            const int n0 = (t & 15) * 128;

            float acc[2][8][4];
#pragma unroll
            for (int a = 0; a < 2; a++)
#pragma unroll
                for (int b = 0; b < 8; b++)
#pragma unroll
                    for (int q = 0; q < 4; q++) acc[a][b][q] = 0.f;

            auto load_stage = [&](int kc, int s) {
                uint32_t st = sbase + s * STAGE_BYTES;
#pragma unroll
                for (int i = 0; i < 2; i++) {
                    int cid = tid + i * 256;
                    int row = cid >> 2, c = cid & 3;
                    uint32_t off = row * 64 + ((c ^ ((row >> 1) & 3)) << 4);
                    size_t ga = (size_t)(m0 + row) * 512 + kc * 32 + c * 8;
                    size_t gb = (size_t)(n0 + row) * 512 + kc * 32 + c * 8;
                    cpa16(st + off,                  Ahi + ga);
                    cpa16(st + TILE_BYTES + off,     Alo + ga);
                    cpa16(st + 2 * TILE_BYTES + off, g_Whh_hi + gb);
                    cpa16(st + 3 * TILE_BYTES + off, g_Whh_lo + gb);
                }
                cpa_commit();
            };
            auto compute = [&](int s) {
                uint32_t st = sbase + s * STAGE_BYTES;
#pragma unroll
                for (int k16 = 0; k16 < 2; k16++) {
                    uint32_t ahi[2][4], alo[2][4];
#pragma unroll
                    for (int mt = 0; mt < 2; mt++) {
                        int row = wm + mt * 16 + (lane & 7) + ((lane >> 3) & 1) * 8;
                        int ch  = k16 * 2 + (lane >> 4);
                        uint32_t off = row * 64 + ((ch ^ ((row >> 1) & 3)) << 4);
                        ldsm4(ahi[mt], st + off);
                        ldsm4(alo[mt], st + TILE_BYTES + off);
                    }
#pragma unroll
                    for (int ng = 0; ng < 4; ng++) {
                        uint32_t bh[4], bl[4];
                        int row = wn + ng * 16 + (lane & 7) + ((lane >> 4) & 1) * 8;
                        int ch  = k16 * 2 + ((lane >> 3) & 1);
                        uint32_t off = row * 64 + ((ch ^ ((row >> 1) & 3)) << 4);
                        ldsm4(bh, st + 2 * TILE_BYTES + off);
                        ldsm4(bl, st + 3 * TILE_BYTES + off);
#pragma unroll
                        for (int mt = 0; mt < 2; mt++)
#pragma unroll
                            for (int nf = 0; nf < 2; nf++)
                                mma16816(acc[mt][ng * 2 + nf], ahi[mt], &bh[nf * 2]);
#pragma unroll
                        for (int mt = 0; mt < 2; mt++)
#pragma unroll
                            for (int nf = 0; nf < 2; nf++)
                                mma16816(acc[mt][ng * 2 + nf], ahi[mt], &bl[nf * 2]);
#pragma unroll
                        for (int mt = 0; mt < 2; mt++)
#pragma unroll
                            for (int nf = 0; nf < 2; nf++)
                                mma16816(acc[mt][ng * 2 + nf], alo[mt], &bh[nf * 2]);
                    }
                }
            };

            load_stage(0, 0);
            load_stage(1, 1);
            for (int kc = 0; kc < 16; kc++) {
                cpa_wait<1>();
                __syncthreads();
                if (kc + 2 < 16) load_stage(kc + 2, (kc + 2) % NSTAGE);
                compute(kc % NSTAGE);
            }
            __syncthreads();

            float* Cs = (float*)dsm;
#pragma unroll
            for (int mt = 0; mt < 2; mt++)
#pragma unroll
                for (int nf = 0; nf < 8; nf++) {
                    int row = wm + mt * 16 + (lane >> 2);
                    int col = wn + nf * 8 + (lane & 3) * 2;
                    Cs[row * CSTRIDE + col]           = acc[mt][nf][0];
                    Cs[row * CSTRIDE + col + 1]       = acc[mt][nf][1];
                    Cs[(row + 8) * CSTRIDE + col]     = acc[mt][nf][2];
                    Cs[(row + 8) * CSTRIDE + col + 1] = acc[mt][nf][3];
                }
            __syncthreads();

            const int ml = tid >> 1;
            const int colbase = (tid & 1) * 64;
            const int m = m0 + ml;
            const int j0 = (n0 + colbase) >> 2;
            float cold[16];
#pragma unroll
            for (int q = 0; q < 16; q += 4) {
                float4 cv = *(const float4*)&c_in[(size_t)m * HD + j0 + q];
                cold[q] = cv.x; cold[q + 1] = cv.y; cold[q + 2] = cv.z; cold[q + 3] = cv.w;
            }
            float hbuf[16], cbuf[16];
#pragma unroll
            for (int q = 0; q < 16; q++) {
                int ncol = colbase + q * 4;
                float4 a  = *(float4*)&Cs[ml * CSTRIDE + ncol];
                float4 xv = *(const float4*)&g_xb[(size_t)m * G4 + n0 + ncol];
                float gi = a.x + xv.x, gf = a.y + xv.y, gg = a.z + xv.z, go = a.w + xv.w;
                if (step0) {
                    float4 wf = *(const float4*)&g_wflag[n0 + ncol];
                    gi += wf.x; gf += wf.y; gg += wf.z; go += wf.w;
                }
                float cn = sigf(gf) * cold[q] + sigf(gi) * tanh_acc(gg);
                float hn = sigf(go) * tanh_acc(cn);
                hbuf[q] = hn; cbuf[q] = cn;
            }
#pragma unroll
            for (int q = 0; q < 16; q += 4) {
                *(float4*)&h_out[(size_t)m * HD + j0 + q] = make_float4(hbuf[q], hbuf[q+1], hbuf[q+2], hbuf[q+3]);
                *(float4*)&c_out[(size_t)m * HD + j0 + q] = make_float4(cbuf[q], cbuf[q+1], cbuf[q+2], cbuf[q+3]);
            }
            __half hh[16], hl[16];
#pragma unroll
            for (int q = 0; q < 16; q++) {
                hh[q] = __float2half(hbuf[q]);
                hl[q] = __float2half(hbuf[q] - __half2float(hh[q]));
            }
            *(uint4*)&hhi_out[(size_t)m * HD + j0]     = *(uint4*)&hh[0];
            *(uint4*)&hhi_out[(size_t)m * HD + j0 + 8] = *(uint4*)&hh[8];
            *(uint4*)&hlo_out[(size_t)m * HD + j0]     = *(uint4*)&hl[0];
            *(uint4*)&hlo_out[(size_t)m * HD + j0 + 8] = *(uint4*)&hl[8];
            __syncthreads();   // dsm reuse by next tile
        }

        // ---- h for step n complete chip-wide ----
        grid_barrier(2 * n);

        // ---- halt GEMV: CTAs 0..31, warp-per-row fixed order (deterministic) ----
        if (blockIdx.x < 32) {
            const int base = blockIdx.x * 128;
            const float4* w4 = (const float4*)Whalt;
#pragma unroll 1
            for (int r = 0; r < 16; r++) {
                int m = base + wid * 16 + r;
                const float4* h4 = (const float4*)(g_hs + ((size_t)n * BD + m) * HD);
                float sdot = 0.f;
#pragma unroll
                for (int it = 0; it < 4; it++) {
                    float4 a = h4[lane + it * 32];
                    float4 w = w4[lane + it * 32];
                    sdot += a.x * w.x + a.y * w.y + a.z * w.z + a.w * w.w;
                }
#pragma unroll
                for (int off = 16; off; off >>= 1) sdot += __shfl_xor_sync(0xffffffffu, sdot, off);
                if (lane == 0) {
                    float halt = sigf(sdot + bhalt[0]);
                    float cum = g_cum[m] + halt;
                    g_cum[m] = cum;
                    g_halt[n * BD + m] = halt;
                    if (cum >= 1.0f - 0.01f) atomicAdd(&g_cnt[n], 1);
                }
            }
        }

        grid_barrier(2 * n + 1);

        __shared__ int s_done;
        if (tid == 0) {
            __threadfence();
            s_done = (*(volatile int*)&g_cnt[n] == BD);
        }
        __syncthreads();
        if (s_done) break;   // all rows halted: remaining steps are dead work
    }
}

// ======= pfin: halting scan + weighted reduce + fp16 split =======
__global__ void pfin(float* __restrict__ hfin, float* __restrict__ cfin,
                     float* __restrict__ ponder_out)
{
    int m = blockIdx.x;
    int j = threadIdx.x;   // 512 threads
    __shared__ float ps[NS];
    if (j == 0) {
        const float thresh = 1.0f - 0.01f;
        float halts[NS];
        float cum = 0.f; int nh = NS - 1; bool found = false;
#pragma unroll
        for (int n = 0; n < NS; n++) {
            halts[n] = g_halt[n * BD + m];   // stale beyond break step: p=0 there
            cum += halts[n];
            if (!found && cum >= thresh) { nh = n; found = true; }
        }
        float s = 0.f;
#pragma unroll
        for (int n = 0; n < NS; n++) {
            float p = (n < nh) ? halts[n] : 0.f;
            if (n < nh) s += p;
            ps[n] = p;
        }
        float r = 1.f - s;
        ps[nh] = r;
        ponder_out[m] = (float)nh + 1.f + r;
    }
    __syncthreads();
    float ah = 0.f, ac = 0.f;
#pragma unroll
    for (int n = 0; n < NS; n++) {
        float p = ps[n];
        if (p != 0.f) {
            size_t o = ((size_t)n * BD + m) * HD + j;
            ah += p * g_hs[o];
            ac += p * g_cs[o];
        }
    }
    hfin[(size_t)m * HD + j] = ah;
    cfin[(size_t)m * HD + j] = ac;
    __half hh = __float2half(ah);
    g_hf_hi[(size_t)m * HD + j] = hh;
    g_hf_lo[(size_t)m * HD + j] = __float2half(ah - __half2float(hh));
}

// ======================= launcher =======================
extern "C" void kernel_launch(void* const* d_in, const int* in_sizes, int n_in,
                              void* d_out, int out_size)
{
    const float* x     = (const float*)d_in[0];
    const float* h0    = (const float*)d_in[1];
    const float* c0    = (const float*)d_in[2];
    const float* Wih   = (const float*)d_in[3];
    const float* bih   = (const float*)d_in[4];
    const float* Whh   = (const float*)d_in[5];
    const float* bhh   = (const float*)d_in[6];
    const float* Whalt = (const float*)d_in[7];
    const float* bhalt = (const float*)d_in[8];
    const float* Wout  = (const float*)d_in[9];
    const float* bout  = (const float*)d_in[10];
    (void)in_sizes; (void)n_in; (void)out_size;

    float* out   = (float*)d_out;
    float* out_y = out;
    float* out_h = out + (size_t)BD * HD;
    float* out_c = out + (size_t)BD * HD * 2;
    float* out_p = out + (size_t)BD * HD * 3;

    cudaFuncSetAttribute(gemm_bias, cudaFuncAttributeMaxDynamicSharedMemorySize, DSMEM_BYTES);
    cudaFuncSetAttribute(act_steps, cudaFuncAttributeMaxDynamicSharedMemorySize, DSMEM_BYTES);

    __half *Wih_hi, *Wih_lo, *Wout_hi, *Wout_lo;
    __half *x_hi, *x_lo, *hf_hi, *hf_lo;
    float *biasp, *xb;
    cudaGetSymbolAddress((void**)&Wih_hi, g_Wih_hi);
    cudaGetSymbolAddress((void**)&Wih_lo, g_Wih_lo);
    cudaGetSymbolAddress((void**)&Wout_hi, g_Wout_hi);
    cudaGetSymbolAddress((void**)&Wout_lo, g_Wout_lo);
    cudaGetSymbolAddress((void**)&x_hi, g_x_hi);
    cudaGetSymbolAddress((void**)&x_lo, g_x_lo);
    cudaGetSymbolAddress((void**)&hf_hi, g_hf_hi);
    cudaGetSymbolAddress((void**)&hf_lo, g_hf_lo);
    cudaGetSymbolAddress((void**)&biasp, g_bias);
    cudaGetSymbolAddress((void**)&xb, g_xb);

    // persistent grid: 2 CTAs/SM, all resident (regs 128*256*2 = 64K RF, smem 192KB)
    int nsm = 148;
    cudaDeviceGetAttribute(&nsm, cudaDevAttrMultiProcessorCount, 0);
    int G = nsm * 2;
    if (G > NTILES) G = NTILES;

    // 1) prep (also resets ACT state + barriers per launch)
    prep_weights<<<(G4 * HD + 255) / 256, 256>>>(Wih, Whh, bih, bhh);
    prep_data<<<(BD * HD + 255) / 256, 256>>>(x, h0, Wout);

    // 2) x-part: xb = x @ Wih_p^T + (b_ih + b_hh)
    dim3 gridG(G4 / 128, BD / 128);
    gemm_bias<<<gridG, 256, DSMEM_BYTES>>>(x_hi, x_lo, Wih_hi, Wih_lo, G4, biasp, xb);

    // 3) all recurrent steps + halting in ONE persistent kernel (early exit)
    act_steps<<<G, 256, DSMEM_BYTES>>>(c0, Whalt, bhalt);

    // 4) halting scan + h_fin / c_fin (+ fp16 split)
    pfin<<<BD, HD>>>(out_h, out_c, out_p);

    // 5) output = h_fin @ W_out^T + b_out
    dim3 gridO(HD / 128, BD / 128);
    gemm_bias<<<gridO, 256, DSMEM_BYTES>>>(hf_hi, hf_lo, Wout_hi, Wout_lo, HD, bout, out_y);
}

// round 12
// speedup vs baseline: 1.0875x; 1.0875x over previous
#include <cuda_runtime.h>
#include <cuda_fp16.h>
#include <math.h>
#include <stdint.h>

#define BD 4096
#define HD 512
#define G4 2048    // 4*H
#define NS 16

// ======================= device scratch (allocation-free) =======================
__device__ __half g_Whh_hi[G4*HD], g_Whh_lo[G4*HD];     // permuted n'=4j+g, K-major
__device__ __half g_Wih_hi[G4*HD], g_Wih_lo[G4*HD];
__device__ __half g_Wout_hi[HD*HD], g_Wout_lo[HD*HD];
__device__ __half g_x_hi[(size_t)BD*HD], g_x_lo[(size_t)BD*HD];
__device__ __half g_h_hi[2][(size_t)BD*HD], g_h_lo[2][(size_t)BD*HD];
__device__ __half g_hf_hi[(size_t)BD*HD], g_hf_lo[(size_t)BD*HD];
__device__ float g_wflag[G4], g_bias[G4];
__device__ float g_xb[(size_t)BD*G4];
__device__ float g_hs[(size_t)NS*BD*HD];
__device__ float g_cs[(size_t)NS*BD*HD];
// ---- ACT state: active-row compaction ----
__device__ float g_halt[NS*BD];     // halt prob per (step,row)
__device__ float g_cum[BD];         // running cumsum of halt
__device__ int   g_list[2][BD];     // active-row lists (ping-pong by step parity)
__device__ int   g_mact[NS+1];      // active-row counts per step
__device__ int   g_seg[BD];         // per-block compacted segments
__device__ int   g_bcnt[32];        // per-block active counts
__device__ int   g_arrive[NS];      // last-block arrival counters

// ======================= helpers =======================
__device__ __forceinline__ float sigf(float x) {
    return __fdividef(1.f, 1.f + __expf(-x));
}
__device__ __forceinline__ float tanh_acc(float x) {
    float ax = fabsf(x);
    float e  = __expf(-2.f * ax);
    float t  = __fdividef(1.f - e, 1.f + e);
    return copysignf(t, x);
}
__device__ __forceinline__ uint32_t smem_u32(const void* p) {
    uint32_t a;
    asm("{ .reg .u64 t; cvta.to.shared.u64 t, %1; cvt.u32.u64 %0, t; }" : "=r"(a) : "l"(p));
    return a;
}
__device__ __forceinline__ void cpa16(uint32_t d, const void* s) {
    asm volatile("cp.async.cg.shared.global [%0], [%1], 16;" :: "r"(d), "l"(s));
}
__device__ __forceinline__ void cpa_commit() { asm volatile("cp.async.commit_group;"); }
template <int N> __device__ __forceinline__ void cpa_wait() {
    asm volatile("cp.async.wait_group %0;" :: "n"(N));
}
__device__ __forceinline__ void ldsm4(uint32_t* r, uint32_t a) {
    asm volatile("ldmatrix.sync.aligned.m8n8.x4.shared.b16 {%0,%1,%2,%3}, [%4];"
        : "=r"(r[0]), "=r"(r[1]), "=r"(r[2]), "=r"(r[3]) : "r"(a));
}
__device__ __forceinline__ void mma16816(float* c, const uint32_t* a, const uint32_t* b) {
    asm volatile("mma.sync.aligned.m16n8k16.row.col.f32.f16.f16.f32 "
        "{%0,%1,%2,%3}, {%4,%5,%6,%7}, {%8,%9}, {%0,%1,%2,%3};"
        : "+f"(c[0]), "+f"(c[1]), "+f"(c[2]), "+f"(c[3])
        : "r"(a[0]), "r"(a[1]), "r"(a[2]), "r"(a[3]), "r"(b[0]), "r"(b[1]));
}

// smem tile layout: 128 rows x 64B (4 x 16B chunks), XOR-swizzled
#define TILE_BYTES 8192
#define STAGE_BYTES 32768           // Ahi | Alo | Bhi | Blo
#define NSTAGE 3
#define DSMEM_BYTES (NSTAGE * STAGE_BYTES)   // 96KB; C-tile reuses it
#define CSTRIDE 132

// ======================= prep kernels =======================
__global__ void prep_weights(const float* __restrict__ Wih, const float* __restrict__ Whh,
                             const float* __restrict__ bih, const float* __restrict__ bhh) {
    int idx = blockIdx.x * blockDim.x + threadIdx.x;
    if (idx >= G4 * HD) return;
    int np = idx >> 9, k = idx & 511;
    int j = np >> 2, g = np & 3;
    int row = g * HD + j;
    float wh = Whh[row * HD + k];
    __half h1 = __float2half(wh);
    g_Whh_hi[idx] = h1;
    g_Whh_lo[idx] = __float2half(wh - __half2float(h1));
    float wi = Wih[row * (HD + 1) + 1 + k];
    __half i1 = __float2half(wi);
    g_Wih_hi[idx] = i1;
    g_Wih_lo[idx] = __float2half(wi - __half2float(i1));
    if (k == 0) {
        g_wflag[np] = Wih[row * (HD + 1)];
        g_bias [np] = bih[row] + bhh[row];
    }
}

__global__ void prep_data(const float* __restrict__ x, const float* __restrict__ h0,
                          const float* __restrict__ Wout) {
    size_t idx = (size_t)blockIdx.x * blockDim.x + threadIdx.x;
    if (idx < (size_t)BD * HD) {
        float v = x[idx];
        __half hv = __float2half(v);
        g_x_hi[idx] = hv;
        g_x_lo[idx] = __float2half(v - __half2float(hv));
        float h = h0[idx];
        __half hh = __float2half(h);
        g_h_hi[0][idx] = hh;
        g_h_lo[0][idx] = __float2half(h - __half2float(hh));
    }
    if (idx < (size_t)HD * HD) {
        float w = Wout[idx];
        __half wh = __float2half(w);
        g_Wout_hi[idx] = wh;
        g_Wout_lo[idx] = __float2half(w - __half2float(wh));
    }
    // ---- per-launch ACT state reset ----
    if (idx < BD) { g_cum[idx] = 0.f; g_list[0][idx] = (int)idx; }
    if (idx < NS) g_arrive[idx] = 0;
    if (idx < NS + 1) g_mact[idx] = (idx == 0) ? BD : 0;
}

// ======================= mma.sync GEMM + fused epilogue =======================
// MODE 0: Cout = acc + bias (dense, full M)
// MODE 1: LSTM gate epilogue over ACTIVE rows only (gathered via list);
//         tiles beyond g_mact[sidx] exit (dead steps: mact==0 -> all exit)
template <int MODE>
__global__ void __launch_bounds__(256, 2)
mma_gemm(const __half* __restrict__ Ahi, const __half* __restrict__ Alo,
         const __half* __restrict__ Bhi, const __half* __restrict__ Blo,
         int Ntot, const float* __restrict__ bias, float* __restrict__ Cout,
         const float* __restrict__ xb, const float* __restrict__ wflag, int sidx,
         const float* __restrict__ c_in, float* __restrict__ h_out, float* __restrict__ c_out,
         __half* __restrict__ hhi_out, __half* __restrict__ hlo_out,
         const int* __restrict__ list)
{
    extern __shared__ char dsm[];
    __shared__ int ridx_s[128];

    const int tid  = threadIdx.x;
    const int wid  = tid >> 5;
    const int lane = tid & 31;
    const int m0 = blockIdx.y * 128;
    const int n0 = blockIdx.x * 128;
    const int wm = (wid & 3) * 32;
    const int wn = (wid >> 2) * 64;

    if (MODE == 1) {
        const int mact = g_mact[sidx];
        if (m0 >= mact) return;           // dead step or tile beyond active rows
        if (tid < 128) {
            int g = m0 + tid;
            ridx_s[tid] = list[g < mact ? g : mact - 1];   // clamp: duplicate rows write identical data
        }
        __syncthreads();
    }

    const uint32_t sbase = smem_u32(dsm);

    float acc[2][8][4];
#pragma unroll
    for (int a = 0; a < 2; a++)
#pragma unroll
        for (int b = 0; b < 8; b++)
#pragma unroll
            for (int q = 0; q < 4; q++) acc[a][b][q] = 0.f;

    auto load_stage = [&](int kc, int s) {
        uint32_t st = sbase + s * STAGE_BYTES;
#pragma unroll
        for (int i = 0; i < 2; i++) {
            int cid = tid + i * 256;
            int row = cid >> 2, c = cid & 3;
            uint32_t off = row * 64 + ((c ^ ((row >> 1) & 3)) << 4);
            int arow = (MODE == 1) ? ridx_s[row] : (m0 + row);
            size_t ga = (size_t)arow * 512 + kc * 32 + c * 8;
            size_t gb = (size_t)(n0 + row) * 512 + kc * 32 + c * 8;
            cpa16(st + off,                  Ahi + ga);
            cpa16(st + TILE_BYTES + off,     Alo + ga);
            cpa16(st + 2 * TILE_BYTES + off, Bhi + gb);
            cpa16(st + 3 * TILE_BYTES + off, Blo + gb);
        }
        cpa_commit();
    };

    auto compute = [&](int s) {
        uint32_t st = sbase + s * STAGE_BYTES;
#pragma unroll
        for (int k16 = 0; k16 < 2; k16++) {
            uint32_t ahi[2][4], alo[2][4];
#pragma unroll
            for (int mt = 0; mt < 2; mt++) {
                int row = wm + mt * 16 + (lane & 7) + ((lane >> 3) & 1) * 8;
                int ch  = k16 * 2 + (lane >> 4);
                uint32_t off = row * 64 + ((ch ^ ((row >> 1) & 3)) << 4);
                ldsm4(ahi[mt], st + off);
                ldsm4(alo[mt], st + TILE_BYTES + off);
            }
#pragma unroll
            for (int ng = 0; ng < 4; ng++) {
                uint32_t bh[4], bl[4];
                int row = wn + ng * 16 + (lane & 7) + ((lane >> 4) & 1) * 8;
                int ch  = k16 * 2 + ((lane >> 3) & 1);
                uint32_t off = row * 64 + ((ch ^ ((row >> 1) & 3)) << 4);
                ldsm4(bh, st + 2 * TILE_BYTES + off);
                ldsm4(bl, st + 3 * TILE_BYTES + off);
#pragma unroll
                for (int mt = 0; mt < 2; mt++)
#pragma unroll
                    for (int nf = 0; nf < 2; nf++)
                        mma16816(acc[mt][ng * 2 + nf], ahi[mt], &bh[nf * 2]);
#pragma unroll
                for (int mt = 0; mt < 2; mt++)
#pragma unroll
                    for (int nf = 0; nf < 2; nf++)
                        mma16816(acc[mt][ng * 2 + nf], ahi[mt], &bl[nf * 2]);
#pragma unroll
                for (int mt = 0; mt < 2; mt++)
#pragma unroll
                    for (int nf = 0; nf < 2; nf++)
                        mma16816(acc[mt][ng * 2 + nf], alo[mt], &bh[nf * 2]);
            }
        }
    };

    load_stage(0, 0);
    load_stage(1, 1);
    for (int kc = 0; kc < 16; kc++) {
        cpa_wait<1>();
        __syncthreads();
        if (kc + 2 < 16) load_stage(kc + 2, (kc + 2) % NSTAGE);
        compute(kc % NSTAGE);
    }
    __syncthreads();   // stage smem reads done -> reuse as C tile

    float* Cs = (float*)dsm;
#pragma unroll
    for (int mt = 0; mt < 2; mt++)
#pragma unroll
        for (int nf = 0; nf < 8; nf++) {
            int row = wm + mt * 16 + (lane >> 2);
            int col = wn + nf * 8 + (lane & 3) * 2;
            Cs[row * CSTRIDE + col]           = acc[mt][nf][0];
            Cs[row * CSTRIDE + col + 1]       = acc[mt][nf][1];
            Cs[(row + 8) * CSTRIDE + col]     = acc[mt][nf][2];
            Cs[(row + 8) * CSTRIDE + col + 1] = acc[mt][nf][3];
        }
    __syncthreads();

    const int ml = tid >> 1;
    const int colbase = (tid & 1) * 64;

    if (MODE == 0) {
        const int m = m0 + ml;
#pragma unroll
        for (int q = 0; q < 16; q++) {
            int ncol = colbase + q * 4;
            float4 v  = *(float4*)&Cs[ml * CSTRIDE + ncol];
            float4 bv = *(const float4*)&bias[n0 + ncol];
            v.x += bv.x; v.y += bv.y; v.z += bv.z; v.w += bv.w;
            *(float4*)&Cout[(size_t)m * Ntot + n0 + ncol] = v;
        }
    } else {
        const int m = ridx_s[ml];        // real (scattered) row
        const int j0 = (n0 + colbase) >> 2;
        const int step0 = (sidx == 0);
        float cold[16];
#pragma unroll
        for (int q = 0; q < 16; q += 4) {
            float4 cv = *(const float4*)&c_in[(size_t)m * HD + j0 + q];
            cold[q] = cv.x; cold[q + 1] = cv.y; cold[q + 2] = cv.z; cold[q + 3] = cv.w;
        }
        float hbuf[16], cbuf[16];
#pragma unroll
        for (int q = 0; q < 16; q++) {
            int ncol = colbase + q * 4;
            float4 a  = *(float4*)&Cs[ml * CSTRIDE + ncol];
            float4 xv = *(const float4*)&xb[(size_t)m * G4 + n0 + ncol];
            float gi = a.x + xv.x, gf = a.y + xv.y, gg = a.z + xv.z, go = a.w + xv.w;
            if (step0) {
                float4 wf = *(const float4*)&wflag[n0 + ncol];
                gi += wf.x; gf += wf.y; gg += wf.z; go += wf.w;
            }
            float cn = sigf(gf) * cold[q] + sigf(gi) * tanh_acc(gg);
            float hn = sigf(go) * tanh_acc(cn);
            hbuf[q] = hn; cbuf[q] = cn;
        }
#pragma unroll
        for (int q = 0; q < 16; q += 4) {
            *(float4*)&h_out[(size_t)m * HD + j0 + q] = make_float4(hbuf[q], hbuf[q+1], hbuf[q+2], hbuf[q+3]);
            *(float4*)&c_out[(size_t)m * HD + j0 + q] = make_float4(cbuf[q], cbuf[q+1], cbuf[q+2], cbuf[q+3]);
        }
        __half hh[16], hl[16];
#pragma unroll
        for (int q = 0; q < 16; q++) {
            hh[q] = __float2half(hbuf[q]);
            hl[q] = __float2half(hbuf[q] - __half2float(hh[q]));
        }
        *(uint4*)&hhi_out[(size_t)m * HD + j0]     = *(uint4*)&hh[0];
        *(uint4*)&hhi_out[(size_t)m * HD + j0 + 8] = *(uint4*)&hh[8];
        *(uint4*)&hlo_out[(size_t)m * HD + j0]     = *(uint4*)&hl[0];
        *(uint4*)&hlo_out[(size_t)m * HD + j0 + 8] = *(uint4*)&hl[8];
    }
}

// ============ halt + compact: halts for active rows, build next active list ============
// 32 blocks x 256 threads. Warp-per-list-position (8 warps x 16). Deterministic:
// ascending ballot compaction per block; last-arriving block stitches segments.
__global__ void halt_compact(int n, const float* __restrict__ Whalt,
                             const float* __restrict__ bhalt)
{
    __shared__ int s_flags[128];
    __shared__ int s_rows[128];
    __shared__ int s_off[32];
    __shared__ int s_cnt[32];
    __shared__ int s_last;

    const int tid = threadIdx.x;
    const int wid = tid >> 5;
    const int lane = tid & 31;
    const int b = blockIdx.x;

    const int mact = g_mact[n];
    if (mact == 0) {
        if (b == 0 && tid == 0) g_mact[n + 1] = 0;
        return;
    }
    const int* list = g_list[n & 1];
    const float thresh = 1.0f - 0.01f;
    const float4* w4 = (const float4*)Whalt;

#pragma unroll 1
    for (int r = 0; r < 16; r++) {
        int i = b * 128 + wid * 16 + r;
        int flag = 0, m = -1;
        if (i < mact) {
            m = list[i];
            const float4* h4 = (const float4*)(g_hs + ((size_t)n * BD + m) * HD);
            float sdot = 0.f;
#pragma unroll
            for (int it = 0; it < 4; it++) {
                float4 a = h4[lane + it * 32];
                float4 w = w4[lane + it * 32];
                sdot += a.x * w.x + a.y * w.y + a.z * w.z + a.w * w.w;
            }
#pragma unroll
            for (int off = 16; off; off >>= 1) sdot += __shfl_xor_sync(0xffffffffu, sdot, off);
            if (lane == 0) {
                float halt = sigf(sdot + bhalt[0]);
                float cum = g_cum[m] + halt;
                g_cum[m] = cum;
                g_halt[n * BD + m] = halt;
                flag = (cum < thresh) ? 1 : 0;   // still active next step
            }
        }
        if (lane == 0) { s_flags[wid * 16 + r] = flag; s_rows[wid * 16 + r] = m; }
    }
    __syncthreads();

    // warp 0: ascending compaction of this block's 128 entries into g_seg
    if (wid == 0) {
        int base = 0;
#pragma unroll
        for (int c = 0; c < 4; c++) {
            int f = s_flags[c * 32 + lane];
            unsigned mask = __ballot_sync(0xffffffffu, f);
            int pre = __popc(mask & ((1u << lane) - 1u));
            if (f) g_seg[b * 128 + base + pre] = s_rows[c * 32 + lane];
            base += __popc(mask);
        }
        if (lane == 0) g_bcnt[b] = base;
    }
    __syncthreads();

    if (tid == 0) {
        __threadfence();
        int old = atomicAdd(&g_arrive[n], 1);
        s_last = (old == (int)gridDim.x - 1) ? 1 : 0;
    }
    __syncthreads();

    if (s_last) {
        if (tid == 0) {
            __threadfence();
            int off = 0;
            for (int s2 = 0; s2 < 32; s2++) {
                s_off[s2] = off;
                int c = __ldcg(&g_bcnt[s2]);   // L2 read: other SMs' writes
                s_cnt[s2] = c;
                off += c;
            }
            g_mact[n + 1] = off;
        }
        __syncthreads();
        int* outl = g_list[(n + 1) & 1];
        for (int s2 = 0; s2 < 32; s2++) {
            int c = s_cnt[s2], o = s_off[s2];
            for (int i = tid; i < c; i += blockDim.x)
                outl[o + i] = __ldcg(&g_seg[s2 * 128 + i]);
        }
    }
}

// ======= pfin: halting scan + weighted reduce + fp16 split =======
__global__ void pfin(float* __restrict__ hfin, float* __restrict__ cfin,
                     float* __restrict__ ponder_out)
{
    int m = blockIdx.x;
    int j = threadIdx.x;   // 512 threads
    __shared__ float ps[NS];
    if (j == 0) {
        const float thresh = 1.0f - 0.01f;
        float halts[NS];
        float cum = 0.f; int nh = NS - 1; bool found = false;
#pragma unroll
        for (int n = 0; n < NS; n++) {
            halts[n] = g_halt[n * BD + m];   // entries past nh: never written -> 0, harmless
            cum += halts[n];
            if (!found && cum >= thresh) { nh = n; found = true; }
        }
        float s = 0.f;
#pragma unroll
        for (int n = 0; n < NS; n++) {
            float p = (n < nh) ? halts[n] : 0.f;
            if (n < nh) s += p;
            ps[n] = p;
        }
        float r = 1.f - s;
        ps[nh] = r;
        ponder_out[m] = (float)nh + 1.f + r;
    }
    __syncthreads();
    float ah = 0.f, ac = 0.f;
#pragma unroll
    for (int n = 0; n < NS; n++) {
        float p = ps[n];
        if (p != 0.f) {
            size_t o = ((size_t)n * BD + m) * HD + j;
            ah += p * g_hs[o];
            ac += p * g_cs[o];
        }
    }
    hfin[(size_t)m * HD + j] = ah;
    cfin[(size_t)m * HD + j] = ac;
    __half hh = __float2half(ah);
    g_hf_hi[(size_t)m * HD + j] = hh;
    g_hf_lo[(size_t)m * HD + j] = __float2half(ah - __half2float(hh));
}

// ======================= launcher =======================
extern "C" void kernel_launch(void* const* d_in, const int* in_sizes, int n_in,
                              void* d_out, int out_size)
{
    const float* x     = (const float*)d_in[0];
    const float* h0    = (const float*)d_in[1];
    const float* c0    = (const float*)d_in[2];
    const float* Wih   = (const float*)d_in[3];
    const float* bih   = (const float*)d_in[4];
    const float* Whh   = (const float*)d_in[5];
    const float* bhh   = (const float*)d_in[6];
    const float* Whalt = (const float*)d_in[7];
    const float* bhalt = (const float*)d_in[8];
    const float* Wout  = (const float*)d_in[9];
    const float* bout  = (const float*)d_in[10];
    (void)in_sizes; (void)n_in; (void)out_size;

    float* out   = (float*)d_out;
    float* out_y = out;
    float* out_h = out + (size_t)BD * HD;
    float* out_c = out + (size_t)BD * HD * 2;
    float* out_p = out + (size_t)BD * HD * 3;

    cudaFuncSetAttribute(mma_gemm<0>, cudaFuncAttributeMaxDynamicSharedMemorySize, DSMEM_BYTES);
    cudaFuncSetAttribute(mma_gemm<1>, cudaFuncAttributeMaxDynamicSharedMemorySize, DSMEM_BYTES);

    __half *Whh_hi, *Whh_lo, *Wih_hi, *Wih_lo, *Wout_hi, *Wout_lo;
    __half *x_hi, *x_lo, *h_hi, *h_lo, *hf_hi, *hf_lo;
    float *wflag, *biasp, *xb, *hs, *cs;
    int *listb;
    cudaGetSymbolAddress((void**)&Whh_hi, g_Whh_hi);
    cudaGetSymbolAddress((void**)&Whh_lo, g_Whh_lo);
    cudaGetSymbolAddress((void**)&Wih_hi, g_Wih_hi);
    cudaGetSymbolAddress((void**)&Wih_lo, g_Wih_lo);
    cudaGetSymbolAddress((void**)&Wout_hi, g_Wout_hi);
    cudaGetSymbolAddress((void**)&Wout_lo, g_Wout_lo);
    cudaGetSymbolAddress((void**)&x_hi, g_x_hi);
    cudaGetSymbolAddress((void**)&x_lo, g_x_lo);
    cudaGetSymbolAddress((void**)&h_hi, g_h_hi);
    cudaGetSymbolAddress((void**)&h_lo, g_h_lo);
    cudaGetSymbolAddress((void**)&hf_hi, g_hf_hi);
    cudaGetSymbolAddress((void**)&hf_lo, g_hf_lo);
    cudaGetSymbolAddress((void**)&wflag, g_wflag);
    cudaGetSymbolAddress((void**)&biasp, g_bias);
    cudaGetSymbolAddress((void**)&xb, g_xb);
    cudaGetSymbolAddress((void**)&hs, g_hs);
    cudaGetSymbolAddress((void**)&cs, g_cs);
    cudaGetSymbolAddress((void**)&listb, g_list);

    const size_t HBUF = (size_t)BD * HD;

    // 1) prep (also resets ACT state + identity list per launch)
    prep_weights<<<(G4 * HD + 255) / 256, 256>>>(Wih, Whh, bih, bhh);
    prep_data<<<(BD * HD + 255) / 256, 256>>>(x, h0, Wout);

    // 2) x-part: xb = x @ Wih_p^T + (b_ih + b_hh)
    dim3 gridG(G4 / 128, BD / 128);
    mma_gemm<0><<<gridG, 256, DSMEM_BYTES>>>(x_hi, x_lo, Wih_hi, Wih_lo, G4, biasp, xb,
                                             nullptr, nullptr, -1, nullptr, nullptr, nullptr,
                                             nullptr, nullptr, nullptr);

    // 3) recurrent steps over ACTIVE rows only; halt+compact builds next list.
    for (int n = 0; n < NS; n++) {
        const float* c_i = (n == 0) ? c0 : (cs + (size_t)(n - 1) * HBUF);
        mma_gemm<1><<<gridG, 256, DSMEM_BYTES>>>(
            h_hi + (size_t)(n & 1) * HBUF, h_lo + (size_t)(n & 1) * HBUF,
            Whh_hi, Whh_lo, G4, nullptr, nullptr,
            xb, wflag, n,
            c_i, hs + (size_t)n * HBUF, cs + (size_t)n * HBUF,
            h_hi + (size_t)((n + 1) & 1) * HBUF, h_lo + (size_t)((n + 1) & 1) * HBUF,
            listb + (size_t)(n & 1) * BD);
        halt_compact<<<32, 256>>>(n, Whalt, bhalt);
    }

    // 4) halting scan + h_fin / c_fin (+ fp16 split)
    pfin<<<BD, HD>>>(out_h, out_c, out_p);

    // 5) output = h_fin @ W_out^T + b_out
    dim3 gridO(HD / 128, BD / 128);
    mma_gemm<0><<<gridO, 256, DSMEM_BYTES>>>(hf_hi, hf_lo, Wout_hi, Wout_lo, HD, bout, out_y,
                                             nullptr, nullptr, -1, nullptr, nullptr, nullptr,
                                             nullptr, nullptr, nullptr);
}

// round 13
// speedup vs baseline: 1.1616x; 1.0682x over previous
#include <cuda_runtime.h>
#include <cuda_fp16.h>
#include <math.h>
#include <stdint.h>

#define BD 4096
#define HD 512
#define G4 2048    // 4*H
#define NS 16
#define NCB 128    // compaction blocks (32 list positions each)

// ======================= device scratch (allocation-free) =======================
__device__ __half g_Whh_hi[G4*HD], g_Whh_lo[G4*HD];     // permuted n'=4j+g, K-major
__device__ __half g_Wih_hi[G4*HD], g_Wih_lo[G4*HD];
__device__ __half g_Wout_hi[HD*HD], g_Wout_lo[HD*HD];
__device__ __half g_x_hi[(size_t)BD*HD], g_x_lo[(size_t)BD*HD];
__device__ __half g_h_hi[2][(size_t)BD*HD], g_h_lo[2][(size_t)BD*HD];
__device__ __half g_hf_hi[(size_t)BD*HD], g_hf_lo[(size_t)BD*HD];
__device__ float g_wflag[G4], g_bias[G4];
__device__ float g_xb[(size_t)BD*G4];
__device__ float g_hs[(size_t)NS*BD*HD];
__device__ float g_cs[(size_t)NS*BD*HD];
// ---- ACT state: active-row compaction ----
__device__ float g_halt[NS*BD];     // halt prob per (step,row)
__device__ float g_cum[BD];         // running cumsum of halt
__device__ int   g_list[2][BD];     // active-row lists (ping-pong by step parity)
__device__ int   g_mact[NS+1];      // active-row counts per step
__device__ int   g_seg[BD];         // per-block compacted segments (NCB x 32)
__device__ int   g_bcnt[NCB];       // per-block active counts
__device__ int   g_arrive[NS];      // last-block arrival counters

// ======================= helpers =======================
__device__ __forceinline__ float sigf(float x) {
    return __fdividef(1.f, 1.f + __expf(-x));
}
__device__ __forceinline__ float tanh_acc(float x) {
    float ax = fabsf(x);
    float e  = __expf(-2.f * ax);
    float t  = __fdividef(1.f - e, 1.f + e);
    return copysignf(t, x);
}
__device__ __forceinline__ uint32_t smem_u32(const void* p) {
    uint32_t a;
    asm("{ .reg .u64 t; cvta.to.shared.u64 t, %1; cvt.u32.u64 %0, t; }" : "=r"(a) : "l"(p));
    return a;
}
__device__ __forceinline__ void cpa16(uint32_t d, const void* s) {
    asm volatile("cp.async.cg.shared.global [%0], [%1], 16;" :: "r"(d), "l"(s));
}
__device__ __forceinline__ void cpa_commit() { asm volatile("cp.async.commit_group;"); }
template <int N> __device__ __forceinline__ void cpa_wait() {
    asm volatile("cp.async.wait_group %0;" :: "n"(N));
}
__device__ __forceinline__ void ldsm4(uint32_t* r, uint32_t a) {
    asm volatile("ldmatrix.sync.aligned.m8n8.x4.shared.b16 {%0,%1,%2,%3}, [%4];"
        : "=r"(r[0]), "=r"(r[1]), "=r"(r[2]), "=r"(r[3]) : "r"(a));
}
__device__ __forceinline__ void mma16816(float* c, const uint32_t* a, const uint32_t* b) {
    asm volatile("mma.sync.aligned.m16n8k16.row.col.f32.f16.f16.f32 "
        "{%0,%1,%2,%3}, {%4,%5,%6,%7}, {%8,%9}, {%0,%1,%2,%3};"
        : "+f"(c[0]), "+f"(c[1]), "+f"(c[2]), "+f"(c[3])
        : "r"(a[0]), "r"(a[1]), "r"(a[2]), "r"(a[3]), "r"(b[0]), "r"(b[1]));
}

// smem tile layout: 128 rows x 64B (4 x 16B chunks), XOR-swizzled
#define TILE_BYTES 8192
#define STAGE_BYTES 32768           // Ahi | Alo | Bhi | Blo
#define NSTAGE 3
#define DSMEM_BYTES (NSTAGE * STAGE_BYTES)   // 96KB; C-tile reuses it
#define CSTRIDE 132

// ======================= prep kernels =======================
__global__ void prep_weights(const float* __restrict__ Wih, const float* __restrict__ Whh,
                             const float* __restrict__ bih, const float* __restrict__ bhh) {
    int idx = blockIdx.x * blockDim.x + threadIdx.x;
    if (idx >= G4 * HD) return;
    int np = idx >> 9, k = idx & 511;
    int j = np >> 2, g = np & 3;
    int row = g * HD + j;
    float wh = Whh[row * HD + k];
    __half h1 = __float2half(wh);
    g_Whh_hi[idx] = h1;
    g_Whh_lo[idx] = __float2half(wh - __half2float(h1));
    float wi = Wih[row * (HD + 1) + 1 + k];
    __half i1 = __float2half(wi);
    g_Wih_hi[idx] = i1;
    g_Wih_lo[idx] = __float2half(wi - __half2float(i1));
    if (k == 0) {
        g_wflag[np] = Wih[row * (HD + 1)];
        g_bias [np] = bih[row] + bhh[row];
    }
}

__global__ void prep_data(const float* __restrict__ x, const float* __restrict__ h0,
                          const float* __restrict__ Wout) {
    size_t idx = (size_t)blockIdx.x * blockDim.x + threadIdx.x;
    if (idx < (size_t)BD * HD) {
        float v = x[idx];
        __half hv = __float2half(v);
        g_x_hi[idx] = hv;
        g_x_lo[idx] = __float2half(v - __half2float(hv));
        float h = h0[idx];
        __half hh = __float2half(h);
        g_h_hi[0][idx] = hh;
        g_h_lo[0][idx] = __float2half(h - __half2float(hh));
    }
    if (idx < (size_t)HD * HD) {
        float w = Wout[idx];
        __half wh = __float2half(w);
        g_Wout_hi[idx] = wh;
        g_Wout_lo[idx] = __float2half(w - __half2float(wh));
    }
    // ---- per-launch ACT state reset ----
    if (idx < BD) { g_cum[idx] = 0.f; g_list[0][idx] = (int)idx; }
    if (idx < NS) g_arrive[idx] = 0;
    if (idx < NS + 1) g_mact[idx] = (idx == 0) ? BD : 0;
}

// ======================= mma.sync GEMM + fused epilogue =======================
// MODE 0: Cout = acc + bias (dense, full M)
// MODE 1: LSTM gate epilogue over ACTIVE rows only (gathered via list);
//         tiles beyond g_mact[sidx] exit (dead steps: mact==0 -> all exit)
template <int MODE>
__global__ void __launch_bounds__(256, 2)
mma_gemm(const __half* __restrict__ Ahi, const __half* __restrict__ Alo,
         const __half* __restrict__ Bhi, const __half* __restrict__ Blo,
         int Ntot, const float* __restrict__ bias, float* __restrict__ Cout,
         const float* __restrict__ xb, const float* __restrict__ wflag, int sidx,
         const float* __restrict__ c_in, float* __restrict__ h_out, float* __restrict__ c_out,
         __half* __restrict__ hhi_out, __half* __restrict__ hlo_out,
         const int* __restrict__ list)
{
    extern __shared__ char dsm[];
    __shared__ int ridx_s[128];

    const int tid  = threadIdx.x;
    const int wid  = tid >> 5;
    const int lane = tid & 31;
    const int m0 = blockIdx.y * 128;
    const int n0 = blockIdx.x * 128;
    const int wm = (wid & 3) * 32;
    const int wn = (wid >> 2) * 64;

    if (MODE == 1) {
        const int mact = g_mact[sidx];
        if (m0 >= mact) return;           // dead step or tile beyond active rows
        if (tid < 128) {
            int g = m0 + tid;
            ridx_s[tid] = list[g < mact ? g : mact - 1];   // clamp: duplicate rows write identical data
        }
        __syncthreads();
    }

    const uint32_t sbase = smem_u32(dsm);

    float acc[2][8][4];
#pragma unroll
    for (int a = 0; a < 2; a++)
#pragma unroll
        for (int b = 0; b < 8; b++)
#pragma unroll
            for (int q = 0; q < 4; q++) acc[a][b][q] = 0.f;

    auto load_stage = [&](int kc, int s) {
        uint32_t st = sbase + s * STAGE_BYTES;
#pragma unroll
        for (int i = 0; i < 2; i++) {
            int cid = tid + i * 256;
            int row = cid >> 2, c = cid & 3;
            uint32_t off = row * 64 + ((c ^ ((row >> 1) & 3)) << 4);
            int arow = (MODE == 1) ? ridx_s[row] : (m0 + row);
            size_t ga = (size_t)arow * 512 + kc * 32 + c * 8;
            size_t gb = (size_t)(n0 + row) * 512 + kc * 32 + c * 8;
            cpa16(st + off,                  Ahi + ga);
            cpa16(st + TILE_BYTES + off,     Alo + ga);
            cpa16(st + 2 * TILE_BYTES + off, Bhi + gb);
            cpa16(st + 3 * TILE_BYTES + off, Blo + gb);
        }
        cpa_commit();
    };

    auto compute = [&](int s) {
        uint32_t st = sbase + s * STAGE_BYTES;
#pragma unroll
        for (int k16 = 0; k16 < 2; k16++) {
            uint32_t ahi[2][4], alo[2][4];
#pragma unroll
            for (int mt = 0; mt < 2; mt++) {
                int row = wm + mt * 16 + (lane & 7) + ((lane >> 3) & 1) * 8;
                int ch  = k16 * 2 + (lane >> 4);
                uint32_t off = row * 64 + ((ch ^ ((row >> 1) & 3)) << 4);
                ldsm4(ahi[mt], st + off);
                ldsm4(alo[mt], st + TILE_BYTES + off);
            }
#pragma unroll
            for (int ng = 0; ng < 4; ng++) {
                uint32_t bh[4], bl[4];
                int row = wn + ng * 16 + (lane & 7) + ((lane >> 4) & 1) * 8;
                int ch  = k16 * 2 + ((lane >> 3) & 1);
                uint32_t off = row * 64 + ((ch ^ ((row >> 1) & 3)) << 4);
                ldsm4(bh, st + 2 * TILE_BYTES + off);
                ldsm4(bl, st + 3 * TILE_BYTES + off);
#pragma unroll
                for (int mt = 0; mt < 2; mt++)
#pragma unroll
                    for (int nf = 0; nf < 2; nf++)
                        mma16816(acc[mt][ng * 2 + nf], ahi[mt], &bh[nf * 2]);
#pragma unroll
                for (int mt = 0; mt < 2; mt++)
#pragma unroll
                    for (int nf = 0; nf < 2; nf++)
                        mma16816(acc[mt][ng * 2 + nf], ahi[mt], &bl[nf * 2]);
#pragma unroll
                for (int mt = 0; mt < 2; mt++)
#pragma unroll
                    for (int nf = 0; nf < 2; nf++)
                        mma16816(acc[mt][ng * 2 + nf], alo[mt], &bh[nf * 2]);
            }
        }
    };

    load_stage(0, 0);
    load_stage(1, 1);
    for (int kc = 0; kc < 16; kc++) {
        cpa_wait<1>();
        __syncthreads();
        if (kc + 2 < 16) load_stage(kc + 2, (kc + 2) % NSTAGE);
        compute(kc % NSTAGE);
    }
    __syncthreads();   // stage smem reads done -> reuse as C tile

    float* Cs = (float*)dsm;
#pragma unroll
    for (int mt = 0; mt < 2; mt++)
#pragma unroll
        for (int nf = 0; nf < 8; nf++) {
            int row = wm + mt * 16 + (lane >> 2);
            int col = wn + nf * 8 + (lane & 3) * 2;
            Cs[row * CSTRIDE + col]           = acc[mt][nf][0];
            Cs[row * CSTRIDE + col + 1]       = acc[mt][nf][1];
            Cs[(row + 8) * CSTRIDE + col]     = acc[mt][nf][2];
            Cs[(row + 8) * CSTRIDE + col + 1] = acc[mt][nf][3];
        }
    __syncthreads();

    const int ml = tid >> 1;
    const int colbase = (tid & 1) * 64;

    if (MODE == 0) {
        const int m = m0 + ml;
#pragma unroll
        for (int q = 0; q < 16; q++) {
            int ncol = colbase + q * 4;
            float4 v  = *(float4*)&Cs[ml * CSTRIDE + ncol];
            float4 bv = *(const float4*)&bias[n0 + ncol];
            v.x += bv.x; v.y += bv.y; v.z += bv.z; v.w += bv.w;
            *(float4*)&Cout[(size_t)m * Ntot + n0 + ncol] = v;
        }
    } else {
        const int m = ridx_s[ml];        // real (scattered) row
        const int j0 = (n0 + colbase) >> 2;
        const int step0 = (sidx == 0);
        float cold[16];
#pragma unroll
        for (int q = 0; q < 16; q += 4) {
            float4 cv = *(const float4*)&c_in[(size_t)m * HD + j0 + q];
            cold[q] = cv.x; cold[q + 1] = cv.y; cold[q + 2] = cv.z; cold[q + 3] = cv.w;
        }
        float hbuf[16], cbuf[16];
#pragma unroll
        for (int q = 0; q < 16; q++) {
            int ncol = colbase + q * 4;
            float4 a  = *(float4*)&Cs[ml * CSTRIDE + ncol];
            float4 xv = *(const float4*)&xb[(size_t)m * G4 + n0 + ncol];
            float gi = a.x + xv.x, gf = a.y + xv.y, gg = a.z + xv.z, go = a.w + xv.w;
            if (step0) {
                float4 wf = *(const float4*)&wflag[n0 + ncol];
                gi += wf.x; gf += wf.y; gg += wf.z; go += wf.w;
            }
            float cn = sigf(gf) * cold[q] + sigf(gi) * tanh_acc(gg);
            float hn = sigf(go) * tanh_acc(cn);
            hbuf[q] = hn; cbuf[q] = cn;
        }
#pragma unroll
        for (int q = 0; q < 16; q += 4) {
            *(float4*)&h_out[(size_t)m * HD + j0 + q] = make_float4(hbuf[q], hbuf[q+1], hbuf[q+2], hbuf[q+3]);
            *(float4*)&c_out[(size_t)m * HD + j0 + q] = make_float4(cbuf[q], cbuf[q+1], cbuf[q+2], cbuf[q+3]);
        }
        __half hh[16], hl[16];
#pragma unroll
        for (int q = 0; q < 16; q++) {
            hh[q] = __float2half(hbuf[q]);
            hl[q] = __float2half(hbuf[q] - __half2float(hh[q]));
        }
        *(uint4*)&hhi_out[(size_t)m * HD + j0]     = *(uint4*)&hh[0];
        *(uint4*)&hhi_out[(size_t)m * HD + j0 + 8] = *(uint4*)&hh[8];
        *(uint4*)&hlo_out[(size_t)m * HD + j0]     = *(uint4*)&hl[0];
        *(uint4*)&hlo_out[(size_t)m * HD + j0 + 8] = *(uint4*)&hl[8];
    }
}

// ============ halt + compact: parallel GEMV (128 blocks) + parallel stitch ============
// NCB=128 blocks x 256 threads; block b owns 32 list positions. 8 warps x 4 serial
// row-GEMVs. Ascending ballot compaction per block; last-arriving block does a
// parallel count load + smem prefix + parallel segment copy. Deterministic.
__global__ void halt_compact(int n, const float* __restrict__ Whalt,
                             const float* __restrict__ bhalt)
{
    __shared__ int s_flags[32];
    __shared__ int s_rows[32];
    __shared__ int s_cnt[NCB];
    __shared__ int s_off[NCB];
    __shared__ int s_last;

    const int tid = threadIdx.x;
    const int wid = tid >> 5;
    const int lane = tid & 31;
    const int b = blockIdx.x;

    const int mact = g_mact[n];
    if (mact == 0) {
        if (b == 0 && tid == 0) g_mact[n + 1] = 0;
        return;
    }
    const int* list = g_list[n & 1];
    const float thresh = 1.0f - 0.01f;
    const float4* w4 = (const float4*)Whalt;

#pragma unroll
    for (int r = 0; r < 4; r++) {
        int i = b * 32 + wid * 4 + r;
        int flag = 0, m = -1;
        if (i < mact) {
            m = list[i];
            const float4* h4 = (const float4*)(g_hs + ((size_t)n * BD + m) * HD);
            float sdot = 0.f;
#pragma unroll
            for (int it = 0; it < 4; it++) {
                float4 a = h4[lane + it * 32];
                float4 w = w4[lane + it * 32];
                sdot += a.x * w.x + a.y * w.y + a.z * w.z + a.w * w.w;
            }
#pragma unroll
            for (int off = 16; off; off >>= 1) sdot += __shfl_xor_sync(0xffffffffu, sdot, off);
            if (lane == 0) {
                float halt = sigf(sdot + bhalt[0]);
                float cum = g_cum[m] + halt;
                g_cum[m] = cum;
                g_halt[n * BD + m] = halt;
                flag = (cum < thresh) ? 1 : 0;   // still active next step
            }
        }
        if (lane == 0) { s_flags[wid * 4 + r] = flag; s_rows[wid * 4 + r] = m; }
    }
    __syncthreads();

    // warp 0: ascending compaction of this block's 32 entries (one ballot)
    if (wid == 0) {
        int f = s_flags[lane];
        unsigned mask = __ballot_sync(0xffffffffu, f);
        int pre = __popc(mask & ((1u << lane) - 1u));
        if (f) g_seg[b * 32 + pre] = s_rows[lane];
        if (lane == 0) g_bcnt[b] = __popc(mask);
    }
    __syncthreads();

    if (tid == 0) {
        __threadfence();
        int old = atomicAdd(&g_arrive[n], 1);
        s_last = (old == (int)gridDim.x - 1) ? 1 : 0;
    }
    __syncthreads();

    if (s_last) {
        // parallel count load (L2-coherent reads of other SMs' writes)
        if (tid < NCB) s_cnt[tid] = __ldcg(&g_bcnt[tid]);
        __syncthreads();
        if (tid == 0) {
            int off = 0;
#pragma unroll 8
            for (int s2 = 0; s2 < NCB; s2++) { s_off[s2] = off; off += s_cnt[s2]; }
            g_mact[n + 1] = off;
        }
        __syncthreads();
        // parallel segment copy: thread t copies segment t (<=32 independent loads)
        int* outl = g_list[(n + 1) & 1];
        if (tid < NCB) {
            int c = s_cnt[tid], o = s_off[tid];
            for (int i = 0; i < c; i++)
                outl[o + i] = __ldcg(&g_seg[tid * 32 + i]);
        }
    }
}

// ======= pfin: halting scan + weighted reduce + fp16 split =======
__global__ void pfin(float* __restrict__ hfin, float* __restrict__ cfin,
                     float* __restrict__ ponder_out)
{
    int m = blockIdx.x;
    int j = threadIdx.x;   // 512 threads
    __shared__ float ps[NS];
    if (j == 0) {
        const float thresh = 1.0f - 0.01f;
        float halts[NS];
        float cum = 0.f; int nh = NS - 1; bool found = false;
#pragma unroll
        for (int n = 0; n < NS; n++) {
            halts[n] = g_halt[n * BD + m];   // entries past nh: never written -> 0, harmless
            cum += halts[n];
            if (!found && cum >= thresh) { nh = n; found = true; }
        }
        float s = 0.f;
#pragma unroll
        for (int n = 0; n < NS; n++) {
            float p = (n < nh) ? halts[n] : 0.f;
            if (n < nh) s += p;
            ps[n] = p;
        }
        float r = 1.f - s;
        ps[nh] = r;
        ponder_out[m] = (float)nh + 1.f + r;
    }
    __syncthreads();
    float ah = 0.f, ac = 0.f;
#pragma unroll
    for (int n = 0; n < NS; n++) {
        float p = ps[n];
        if (p != 0.f) {
            size_t o = ((size_t)n * BD + m) * HD + j;
            ah += p * g_hs[o];
            ac += p * g_cs[o];
        }
    }
    hfin[(size_t)m * HD + j] = ah;
    cfin[(size_t)m * HD + j] = ac;
    __half hh = __float2half(ah);
    g_hf_hi[(size_t)m * HD + j] = hh;
    g_hf_lo[(size_t)m * HD + j] = __float2half(ah - __half2float(hh));
}

// ======================= launcher =======================
extern "C" void kernel_launch(void* const* d_in, const int* in_sizes, int n_in,
                              void* d_out, int out_size)
{
    const float* x     = (const float*)d_in[0];
    const float* h0    = (const float*)d_in[1];
    const float* c0    = (const float*)d_in[2];
    const float* Wih   = (const float*)d_in[3];
    const float* bih   = (const float*)d_in[4];
    const float* Whh   = (const float*)d_in[5];
    const float* bhh   = (const float*)d_in[6];
    const float* Whalt = (const float*)d_in[7];
    const float* bhalt = (const float*)d_in[8];
    const float* Wout  = (const float*)d_in[9];
    const float* bout  = (const float*)d_in[10];
    (void)in_sizes; (void)n_in; (void)out_size;

    float* out   = (float*)d_out;
    float* out_y = out;
    float* out_h = out + (size_t)BD * HD;
    float* out_c = out + (size_t)BD * HD * 2;
    float* out_p = out + (size_t)BD * HD * 3;

    cudaFuncSetAttribute(mma_gemm<0>, cudaFuncAttributeMaxDynamicSharedMemorySize, DSMEM_BYTES);
    cudaFuncSetAttribute(mma_gemm<1>, cudaFuncAttributeMaxDynamicSharedMemorySize, DSMEM_BYTES);

    __half *Whh_hi, *Whh_lo, *Wih_hi, *Wih_lo, *Wout_hi, *Wout_lo;
    __half *x_hi, *x_lo, *h_hi, *h_lo, *hf_hi, *hf_lo;
    float *wflag, *biasp, *xb, *hs, *cs;
    int *listb;
    cudaGetSymbolAddress((void**)&Whh_hi, g_Whh_hi);
    cudaGetSymbolAddress((void**)&Whh_lo, g_Whh_lo);
    cudaGetSymbolAddress((void**)&Wih_hi, g_Wih_hi);
    cudaGetSymbolAddress((void**)&Wih_lo, g_Wih_lo);
    cudaGetSymbolAddress((void**)&Wout_hi, g_Wout_hi);
    cudaGetSymbolAddress((void**)&Wout_lo, g_Wout_lo);
    cudaGetSymbolAddress((void**)&x_hi, g_x_hi);
    cudaGetSymbolAddress((void**)&x_lo, g_x_lo);
    cudaGetSymbolAddress((void**)&h_hi, g_h_hi);
    cudaGetSymbolAddress((void**)&h_lo, g_h_lo);
    cudaGetSymbolAddress((void**)&hf_hi, g_hf_hi);
    cudaGetSymbolAddress((void**)&hf_lo, g_hf_lo);
    cudaGetSymbolAddress((void**)&wflag, g_wflag);
    cudaGetSymbolAddress((void**)&biasp, g_bias);
    cudaGetSymbolAddress((void**)&xb, g_xb);
    cudaGetSymbolAddress((void**)&hs, g_hs);
    cudaGetSymbolAddress((void**)&cs, g_cs);
    cudaGetSymbolAddress((void**)&listb, g_list);

    const size_t HBUF = (size_t)BD * HD;

    // 1) prep (also resets ACT state + identity list per launch)
    prep_weights<<<(G4 * HD + 255) / 256, 256>>>(Wih, Whh, bih, bhh);
    prep_data<<<(BD * HD + 255) / 256, 256>>>(x, h0, Wout);

    // 2) x-part: xb = x @ Wih_p^T + (b_ih + b_hh)
    dim3 gridG(G4 / 128, BD / 128);
    mma_gemm<0><<<gridG, 256, DSMEM_BYTES>>>(x_hi, x_lo, Wih_hi, Wih_lo, G4, biasp, xb,
                                             nullptr, nullptr, -1, nullptr, nullptr, nullptr,
                                             nullptr, nullptr, nullptr);

    // 3) recurrent steps over ACTIVE rows only; halt+compact builds next list.
    for (int n = 0; n < NS; n++) {
        const float* c_i = (n == 0) ? c0 : (cs + (size_t)(n - 1) * HBUF);
        mma_gemm<1><<<gridG, 256, DSMEM_BYTES>>>(
            h_hi + (size_t)(n & 1) * HBUF, h_lo + (size_t)(n & 1) * HBUF,
            Whh_hi, Whh_lo, G4, nullptr, nullptr,
            xb, wflag, n,
            c_i, hs + (size_t)n * HBUF, cs + (size_t)n * HBUF,
            h_hi + (size_t)((n + 1) & 1) * HBUF, h_lo + (size_t)((n + 1) & 1) * HBUF,
            listb + (size_t)(n & 1) * BD);
        halt_compact<<<NCB, 256>>>(n, Whalt, bhalt);
    }

    // 4) halting scan + h_fin / c_fin (+ fp16 split)
    pfin<<<BD, HD>>>(out_h, out_c, out_p);

    // 5) output = h_fin @ W_out^T + b_out
    dim3 gridO(HD / 128, BD / 128);
    mma_gemm<0><<<gridO, 256, DSMEM_BYTES>>>(hf_hi, hf_lo, Wout_hi, Wout_lo, HD, bout, out_y,
                                             nullptr, nullptr, -1, nullptr, nullptr, nullptr,
                                             nullptr, nullptr, nullptr);
}

// round 14
// speedup vs baseline: 1.2653x; 1.0893x over previous
#include <cuda_runtime.h>
#include <cuda_fp16.h>
#include <math.h>
#include <stdint.h>

#define BD 4096
#define HD 512
#define G4 2048    // 4*H
#define NS 16
#define NCB 128    // compaction blocks (32 list positions each)
#define TAIL0 3    // first step handled by the persistent tail
#define TAILG 128  // tail grid (<= SM count, all resident)

// ======================= device scratch (allocation-free) =======================
__device__ __half g_Whh_hi[G4*HD], g_Whh_lo[G4*HD];     // permuted n'=4j+g, K-major
__device__ __half g_Wih_hi[G4*HD], g_Wih_lo[G4*HD];
__device__ __half g_Wout_hi[HD*HD], g_Wout_lo[HD*HD];
__device__ __half g_x_hi[(size_t)BD*HD], g_x_lo[(size_t)BD*HD];
__device__ __half g_h_hi[2][(size_t)BD*HD], g_h_lo[2][(size_t)BD*HD];
__device__ __half g_hf_hi[(size_t)BD*HD], g_hf_lo[(size_t)BD*HD];
__device__ float g_wflag[G4], g_bias[G4];
__device__ float g_xb[(size_t)BD*G4];
__device__ float g_hs[(size_t)NS*BD*HD];
__device__ float g_cs[(size_t)NS*BD*HD];
// ---- ACT state: active-row compaction ----
__device__ float g_halt[NS*BD];     // halt prob per (step,row)
__device__ float g_cum[BD];         // running cumsum of halt
__device__ int   g_list[2][BD];     // active-row lists (ping-pong by step parity)
__device__ int   g_mact[NS+1];      // active-row counts per step
__device__ int   g_seg[BD];         // per-block compacted segments (NCB x 32)
__device__ int   g_bcnt[NCB];       // per-block active counts
__device__ int   g_arrive[NS];      // last-block arrival counters
__device__ int   g_bar[2*NS];       // tail grid-barrier counters

// ======================= helpers =======================
__device__ __forceinline__ float sigf(float x) {
    return __fdividef(1.f, 1.f + __expf(-x));
}
__device__ __forceinline__ float tanh_acc(float x) {
    float ax = fabsf(x);
    float e  = __expf(-2.f * ax);
    float t  = __fdividef(1.f - e, 1.f + e);
    return copysignf(t, x);
}
__device__ __forceinline__ uint32_t smem_u32(const void* p) {
    uint32_t a;
    asm("{ .reg .u64 t; cvta.to.shared.u64 t, %1; cvt.u32.u64 %0, t; }" : "=r"(a) : "l"(p));
    return a;
}
__device__ __forceinline__ void cpa16(uint32_t d, const void* s) {
    asm volatile("cp.async.cg.shared.global [%0], [%1], 16;" :: "r"(d), "l"(s));
}
__device__ __forceinline__ void cpa_commit() { asm volatile("cp.async.commit_group;"); }
template <int N> __device__ __forceinline__ void cpa_wait() {
    asm volatile("cp.async.wait_group %0;" :: "n"(N));
}
__device__ __forceinline__ void ldsm4(uint32_t* r, uint32_t a) {
    asm volatile("ldmatrix.sync.aligned.m8n8.x4.shared.b16 {%0,%1,%2,%3}, [%4];"
        : "=r"(r[0]), "=r"(r[1]), "=r"(r[2]), "=r"(r[3]) : "r"(a));
}
__device__ __forceinline__ void mma16816(float* c, const uint32_t* a, const uint32_t* b) {
    asm volatile("mma.sync.aligned.m16n8k16.row.col.f32.f16.f16.f32 "
        "{%0,%1,%2,%3}, {%4,%5,%6,%7}, {%8,%9}, {%0,%1,%2,%3};"
        : "+f"(c[0]), "+f"(c[1]), "+f"(c[2]), "+f"(c[3])
        : "r"(a[0]), "r"(a[1]), "r"(a[2]), "r"(a[3]), "r"(b[0]), "r"(b[1]));
}

// smem tile layout: 128 rows x 64B (4 x 16B chunks), XOR-swizzled
#define TILE_BYTES 8192
#define STAGE_BYTES 32768           // Ahi | Alo | Bhi | Blo
#define NSTAGE 3
#define DSMEM_BYTES (NSTAGE * STAGE_BYTES)   // 96KB; C-tile reuses it
#define CSTRIDE 132
// tail smem partition
#define TS_WS    0                       // [16][516] f32
#define TS_HS    (16*516*4)              // [16][512] f32
#define TS_GS    (TS_HS + 16*512*4)      // [16][16] f32
#define TS_MS    (TS_GS + 16*16*4)       // [16] int
#define TS_FLAG  (TS_MS + 16*4)          // [BD] char
#define TAIL_SMEM (TS_FLAG + BD)

// ======================= prep kernels =======================
__global__ void prep_weights(const float* __restrict__ Wih, const float* __restrict__ Whh,
                             const float* __restrict__ bih, const float* __restrict__ bhh) {
    int idx = blockIdx.x * blockDim.x + threadIdx.x;
    if (idx >= G4 * HD) return;
    int np = idx >> 9, k = idx & 511;
    int j = np >> 2, g = np & 3;
    int row = g * HD + j;
    float wh = Whh[row * HD + k];
    __half h1 = __float2half(wh);
    g_Whh_hi[idx] = h1;
    g_Whh_lo[idx] = __float2half(wh - __half2float(h1));
    float wi = Wih[row * (HD + 1) + 1 + k];
    __half i1 = __float2half(wi);
    g_Wih_hi[idx] = i1;
    g_Wih_lo[idx] = __float2half(wi - __half2float(i1));
    if (k == 0) {
        g_wflag[np] = Wih[row * (HD + 1)];
        g_bias [np] = bih[row] + bhh[row];
    }
}

__global__ void prep_data(const float* __restrict__ x, const float* __restrict__ h0,
                          const float* __restrict__ Wout) {
    size_t idx = (size_t)blockIdx.x * blockDim.x + threadIdx.x;
    if (idx < (size_t)BD * HD) {
        float v = x[idx];
        __half hv = __float2half(v);
        g_x_hi[idx] = hv;
        g_x_lo[idx] = __float2half(v - __half2float(hv));
        float h = h0[idx];
        __half hh = __float2half(h);
        g_h_hi[0][idx] = hh;
        g_h_lo[0][idx] = __float2half(h - __half2float(hh));
    }
    if (idx < (size_t)HD * HD) {
        float w = Wout[idx];
        __half wh = __float2half(w);
        g_Wout_hi[idx] = wh;
        g_Wout_lo[idx] = __float2half(w - __half2float(wh));
    }
    // ---- per-launch ACT state reset ----
    if (idx < BD) { g_cum[idx] = 0.f; g_list[0][idx] = (int)idx; }
    if (idx < NS) g_arrive[idx] = 0;
    if (idx < NS + 1) g_mact[idx] = (idx == 0) ? BD : 0;
    if (idx < 2 * NS) g_bar[idx] = 0;
}

// ======================= mma.sync GEMM + fused epilogue =======================
// MODE 0: Cout = acc + bias (dense, full M)
// MODE 1: LSTM gate epilogue over ACTIVE rows only (gathered via list)
template <int MODE>
__global__ void __launch_bounds__(256, 2)
mma_gemm(const __half* __restrict__ Ahi, const __half* __restrict__ Alo,
         const __half* __restrict__ Bhi, const __half* __restrict__ Blo,
         int Ntot, const float* __restrict__ bias, float* __restrict__ Cout,
         const float* __restrict__ xb, const float* __restrict__ wflag, int sidx,
         const float* __restrict__ c_in, float* __restrict__ h_out, float* __restrict__ c_out,
         __half* __restrict__ hhi_out, __half* __restrict__ hlo_out,
         const int* __restrict__ list)
{
    extern __shared__ char dsm[];
    __shared__ int ridx_s[128];

    const int tid  = threadIdx.x;
    const int wid  = tid >> 5;
    const int lane = tid & 31;
    const int m0 = blockIdx.y * 128;
    const int n0 = blockIdx.x * 128;
    const int wm = (wid & 3) * 32;
    const int wn = (wid >> 2) * 64;

    if (MODE == 1) {
        const int mact = g_mact[sidx];
        if (m0 >= mact) return;
        if (tid < 128) {
            int g = m0 + tid;
            ridx_s[tid] = list[g < mact ? g : mact - 1];
        }
        __syncthreads();
    }

    const uint32_t sbase = smem_u32(dsm);

    float acc[2][8][4];
#pragma unroll
    for (int a = 0; a < 2; a++)
#pragma unroll
        for (int b = 0; b < 8; b++)
#pragma unroll
            for (int q = 0; q < 4; q++) acc[a][b][q] = 0.f;

    auto load_stage = [&](int kc, int s) {
        uint32_t st = sbase + s * STAGE_BYTES;
#pragma unroll
        for (int i = 0; i < 2; i++) {
            int cid = tid + i * 256;
            int row = cid >> 2, c = cid & 3;
            uint32_t off = row * 64 + ((c ^ ((row >> 1) & 3)) << 4);
            int arow = (MODE == 1) ? ridx_s[row] : (m0 + row);
            size_t ga = (size_t)arow * 512 + kc * 32 + c * 8;
            size_t gb = (size_t)(n0 + row) * 512 + kc * 32 + c * 8;
            cpa16(st + off,                  Ahi + ga);
            cpa16(st + TILE_BYTES + off,     Alo + ga);
            cpa16(st + 2 * TILE_BYTES + off, Bhi + gb);
            cpa16(st + 3 * TILE_BYTES + off, Blo + gb);
        }
        cpa_commit();
    };

    auto compute = [&](int s) {
        uint32_t st = sbase + s * STAGE_BYTES;
#pragma unroll
        for (int k16 = 0; k16 < 2; k16++) {
            uint32_t ahi[2][4], alo[2][4];
#pragma unroll
            for (int mt = 0; mt < 2; mt++) {
                int row = wm + mt * 16 + (lane & 7) + ((lane >> 3) & 1) * 8;
                int ch  = k16 * 2 + (lane >> 4);
                uint32_t off = row * 64 + ((ch ^ ((row >> 1) & 3)) << 4);
                ldsm4(ahi[mt], st + off);
                ldsm4(alo[mt], st + TILE_BYTES + off);
            }
#pragma unroll
            for (int ng = 0; ng < 4; ng++) {
                uint32_t bh[4], bl[4];
                int row = wn + ng * 16 + (lane & 7) + ((lane >> 4) & 1) * 8;
                int ch  = k16 * 2 + ((lane >> 3) & 1);
                uint32_t off = row * 64 + ((ch ^ ((row >> 1) & 3)) << 4);
                ldsm4(bh, st + 2 * TILE_BYTES + off);
                ldsm4(bl, st + 3 * TILE_BYTES + off);
#pragma unroll
                for (int mt = 0; mt < 2; mt++)
#pragma unroll
                    for (int nf = 0; nf < 2; nf++)
                        mma16816(acc[mt][ng * 2 + nf], ahi[mt], &bh[nf * 2]);
#pragma unroll
                for (int mt = 0; mt < 2; mt++)
#pragma unroll
                    for (int nf = 0; nf < 2; nf++)
                        mma16816(acc[mt][ng * 2 + nf], ahi[mt], &bl[nf * 2]);
#pragma unroll
                for (int mt = 0; mt < 2; mt++)
#pragma unroll
                    for (int nf = 0; nf < 2; nf++)
                        mma16816(acc[mt][ng * 2 + nf], alo[mt], &bh[nf * 2]);
            }
        }
    };

    load_stage(0, 0);
    load_stage(1, 1);
    for (int kc = 0; kc < 16; kc++) {
        cpa_wait<1>();
        __syncthreads();
        if (kc + 2 < 16) load_stage(kc + 2, (kc + 2) % NSTAGE);
        compute(kc % NSTAGE);
    }
    __syncthreads();

    float* Cs = (float*)dsm;
#pragma unroll
    for (int mt = 0; mt < 2; mt++)
#pragma unroll
        for (int nf = 0; nf < 8; nf++) {
            int row = wm + mt * 16 + (lane >> 2);
            int col = wn + nf * 8 + (lane & 3) * 2;
            Cs[row * CSTRIDE + col]           = acc[mt][nf][0];
            Cs[row * CSTRIDE + col + 1]       = acc[mt][nf][1];
            Cs[(row + 8) * CSTRIDE + col]     = acc[mt][nf][2];
            Cs[(row + 8) * CSTRIDE + col + 1] = acc[mt][nf][3];
        }
    __syncthreads();

    const int ml = tid >> 1;
    const int colbase = (tid & 1) * 64;

    if (MODE == 0) {
        const int m = m0 + ml;
#pragma unroll
        for (int q = 0; q < 16; q++) {
            int ncol = colbase + q * 4;
            float4 v  = *(float4*)&Cs[ml * CSTRIDE + ncol];
            float4 bv = *(const float4*)&bias[n0 + ncol];
            v.x += bv.x; v.y += bv.y; v.z += bv.z; v.w += bv.w;
            *(float4*)&Cout[(size_t)m * Ntot + n0 + ncol] = v;
        }
    } else {
        const int m = ridx_s[ml];
        const int j0 = (n0 + colbase) >> 2;
        const int step0 = (sidx == 0);
        float cold[16];
#pragma unroll
        for (int q = 0; q < 16; q += 4) {
            float4 cv = *(const float4*)&c_in[(size_t)m * HD + j0 + q];
            cold[q] = cv.x; cold[q + 1] = cv.y; cold[q + 2] = cv.z; cold[q + 3] = cv.w;
        }
        float hbuf[16], cbuf[16];
#pragma unroll
        for (int q = 0; q < 16; q++) {
            int ncol = colbase + q * 4;
            float4 a  = *(float4*)&Cs[ml * CSTRIDE + ncol];
            float4 xv = *(const float4*)&xb[(size_t)m * G4 + n0 + ncol];
            float gi = a.x + xv.x, gf = a.y + xv.y, gg = a.z + xv.z, go = a.w + xv.w;
            if (step0) {
                float4 wf = *(const float4*)&wflag[n0 + ncol];
                gi += wf.x; gf += wf.y; gg += wf.z; go += wf.w;
            }
            float cn = sigf(gf) * cold[q] + sigf(gi) * tanh_acc(gg);
            float hn = sigf(go) * tanh_acc(cn);
            hbuf[q] = hn; cbuf[q] = cn;
        }
#pragma unroll
        for (int q = 0; q < 16; q += 4) {
            *(float4*)&h_out[(size_t)m * HD + j0 + q] = make_float4(hbuf[q], hbuf[q+1], hbuf[q+2], hbuf[q+3]);
            *(float4*)&c_out[(size_t)m * HD + j0 + q] = make_float4(cbuf[q], cbuf[q+1], cbuf[q+2], cbuf[q+3]);
        }
        __half hh[16], hl[16];
#pragma unroll
        for (int q = 0; q < 16; q++) {
            hh[q] = __float2half(hbuf[q]);
            hl[q] = __float2half(hbuf[q] - __half2float(hh[q]));
        }
        *(uint4*)&hhi_out[(size_t)m * HD + j0]     = *(uint4*)&hh[0];
        *(uint4*)&hhi_out[(size_t)m * HD + j0 + 8] = *(uint4*)&hh[8];
        *(uint4*)&hlo_out[(size_t)m * HD + j0]     = *(uint4*)&hl[0];
        *(uint4*)&hlo_out[(size_t)m * HD + j0 + 8] = *(uint4*)&hl[8];
    }
}

// ============ halt + compact (steps 0..TAIL0-1): parallel GEMV + parallel stitch ============
__global__ void halt_compact(int n, const float* __restrict__ Whalt,
                             const float* __restrict__ bhalt)
{
    __shared__ int s_flags[32];
    __shared__ int s_rows[32];
    __shared__ int s_cnt[NCB];
    __shared__ int s_off[NCB];
    __shared__ int s_last;

    const int tid = threadIdx.x;
    const int wid = tid >> 5;
    const int lane = tid & 31;
    const int b = blockIdx.x;

    const int mact = g_mact[n];
    if (mact == 0) {
        if (b == 0 && tid == 0) g_mact[n + 1] = 0;
        return;
    }
    const int* list = g_list[n & 1];
    const float thresh = 1.0f - 0.01f;
    const float4* w4 = (const float4*)Whalt;

#pragma unroll
    for (int r = 0; r < 4; r++) {
        int i = b * 32 + wid * 4 + r;
        int flag = 0, m = -1;
        if (i < mact) {
            m = list[i];
            const float4* h4 = (const float4*)(g_hs + ((size_t)n * BD + m) * HD);
            float sdot = 0.f;
#pragma unroll
            for (int it = 0; it < 4; it++) {
                float4 a = h4[lane + it * 32];
                float4 w = w4[lane + it * 32];
                sdot += a.x * w.x + a.y * w.y + a.z * w.z + a.w * w.w;
            }
#pragma unroll
            for (int off = 16; off; off >>= 1) sdot += __shfl_xor_sync(0xffffffffu, sdot, off);
            if (lane == 0) {
                float halt = sigf(sdot + bhalt[0]);
                float cum = g_cum[m] + halt;
                g_cum[m] = cum;
                g_halt[n * BD + m] = halt;
                flag = (cum < thresh) ? 1 : 0;
            }
        }
        if (lane == 0) { s_flags[wid * 4 + r] = flag; s_rows[wid * 4 + r] = m; }
    }
    __syncthreads();

    if (wid == 0) {
        int f = s_flags[lane];
        unsigned mask = __ballot_sync(0xffffffffu, f);
        int pre = __popc(mask & ((1u << lane) - 1u));
        if (f) g_seg[b * 32 + pre] = s_rows[lane];
        if (lane == 0) g_bcnt[b] = __popc(mask);
    }
    __syncthreads();

    if (tid == 0) {
        __threadfence();
        int old = atomicAdd(&g_arrive[n], 1);
        s_last = (old == (int)gridDim.x - 1) ? 1 : 0;
    }
    __syncthreads();

    if (s_last) {
        if (tid < NCB) s_cnt[tid] = __ldcg(&g_bcnt[tid]);
        __syncthreads();
        if (tid == 0) {
            int off = 0;
#pragma unroll 8
            for (int s2 = 0; s2 < NCB; s2++) { s_off[s2] = off; off += s_cnt[s2]; }
            g_mact[n + 1] = off;
        }
        __syncthreads();
        int* outl = g_list[(n + 1) & 1];
        if (tid < NCB) {
            int c = s_cnt[tid], o = s_off[tid];
            for (int i = 0; i < c; i++)
                outl[o + i] = __ldcg(&g_seg[tid * 32 + i]);
        }
    }
}

// ============ persistent tail: steps TAIL0..15 (fp32 SIMT, straggler path) ============
// Typical case (all rows halted by step TAIL0): immediate return, ~2us.
__device__ __forceinline__ void tail_barrier(int idx) {
    __threadfence();
    __syncthreads();
    if (threadIdx.x == 0) {
        atomicAdd(&g_bar[idx], 1);
        while (*(volatile int*)&g_bar[idx] < (int)gridDim.x) { }
    }
    __syncthreads();
}

__global__ void __launch_bounds__(256, 1)
act_tail(const float* __restrict__ Whalt, const float* __restrict__ bhalt)
{
    if (*(volatile int*)&g_mact[TAIL0] == 0) return;   // fast exit (typical)

    extern __shared__ char dsm[];
    float* Ws   = (float*)(dsm + TS_WS);    // [16][516]
    float* hs_s = (float*)(dsm + TS_HS);    // [16][512]
    float* gsum = (float*)(dsm + TS_GS);    // [16][16]
    int*   m_s  = (int*)  (dsm + TS_MS);    // [16]
    char*  flg  = (char*) (dsm + TS_FLAG);  // [BD]

    const int tid = threadIdx.x;
    const int wid = tid >> 5;
    const int lane = tid & 31;
    const int b = blockIdx.x;
    const size_t HBUF = (size_t)BD * HD;
    const int np0 = b * 16;                 // this CTA's 16 gate-columns

    // reconstruct W slice once (reused across steps)
    for (int idx = tid; idx < 16 * 512; idx += 256) {
        int col = idx >> 9, k = idx & 511;
        size_t o = (size_t)(np0 + col) * 512 + k;
        Ws[col * 516 + k] = __half2float(g_Whh_hi[o]) + __half2float(g_Whh_lo[o]);
    }
    __syncthreads();

    for (int n = TAIL0; n < NS; n++) {
        const int mact = *(volatile int*)&g_mact[n];
        if (mact == 0) break;               // uniform: all CTAs past same barriers
        const int* list = g_list[n & 1];
        const float* hprev = g_hs + (size_t)(n - 1) * HBUF;
        const float* cprev = g_cs + (size_t)(n - 1) * HBUF;
        float* hout = g_hs + (size_t)n * HBUF;
        float* cout = g_cs + (size_t)n * HBUF;

        for (int rc = 0; rc < mact; rc += 16) {
            // stage up to 16 h rows (scattered) into smem
            for (int rr = wid; rr < 16; rr += 8) {
                int i = rc + rr;
                if (i < mact) {
                    int m = __ldcg(&list[i]);
                    if (lane == 0) m_s[rr] = m;
                    const float4* src = (const float4*)(hprev + (size_t)m * HD);
                    float4* dst = (float4*)(hs_s + rr * 512);
                    for (int q = lane; q < 128; q += 32) dst[q] = src[q];
                }
            }
            __syncthreads();
            const int col = tid & 15, rg = tid >> 4;
            if (rc + rg < mact) {
                const float4* hv = (const float4*)(hs_s + rg * 512);
                const float4* wv = (const float4*)(Ws + col * 516);
                float d = 0.f;
                for (int q = 0; q < 128; q++) {
                    float4 a = hv[q], w = wv[q];
                    d += a.x * w.x + a.y * w.y + a.z * w.z + a.w * w.w;
                }
                gsum[rg * 16 + col] = d + g_xb[(size_t)m_s[rg] * G4 + np0 + col];
            }
            __syncthreads();
            if (tid < 64) {
                int rg2 = tid >> 2, jj = tid & 3;
                if (rc + rg2 < mact) {
                    int m = m_s[rg2];
                    float gi = gsum[rg2 * 16 + jj * 4 + 0];
                    float gf = gsum[rg2 * 16 + jj * 4 + 1];
                    float gg = gsum[rg2 * 16 + jj * 4 + 2];
                    float go = gsum[rg2 * 16 + jj * 4 + 3];
                    int j = (np0 >> 2) + jj;    // own units -> self-coherent c chain
                    float co = cprev[(size_t)m * HD + j];
                    float cn = sigf(gf) * co + sigf(gi) * tanh_acc(gg);
                    float hn = sigf(go) * tanh_acc(cn);
                    hout[(size_t)m * HD + j] = hn;
                    cout[(size_t)m * HD + j] = cn;
                }
            }
            __syncthreads();
        }

        tail_barrier(2 * n);

        if (b == 0) {   // deterministic halt + ascending compaction
            const float4* w4 = (const float4*)Whalt;
            for (int i = wid; i < mact; i += 8) {
                int m = __ldcg(&list[i]);
                const float4* h4 = (const float4*)(hout + (size_t)m * HD);
                float sdot = 0.f;
#pragma unroll
                for (int it = 0; it < 4; it++) {
                    float4 a = h4[lane + it * 32];
                    float4 w = w4[lane + it * 32];
                    sdot += a.x * w.x + a.y * w.y + a.z * w.z + a.w * w.w;
                }
#pragma unroll
                for (int off = 16; off; off >>= 1) sdot += __shfl_xor_sync(0xffffffffu, sdot, off);
                if (lane == 0) {
                    float halt = sigf(sdot + bhalt[0]);
                    float cum = g_cum[m] + halt;
                    g_cum[m] = cum;
                    g_halt[n * BD + m] = halt;
                    flg[i] = (cum < 1.0f - 0.01f) ? 1 : 0;
                }
            }
            __syncthreads();
            if (wid == 0) {
                int* outl = g_list[(n + 1) & 1];
                int pos = 0;
                for (int c2 = 0; c2 < mact; c2 += 32) {
                    int i2 = c2 + lane;
                    int f = (i2 < mact) ? flg[i2] : 0;
                    unsigned msk = __ballot_sync(0xffffffffu, f);
                    if (f) outl[pos + __popc(msk & ((1u << lane) - 1u))] = __ldcg(&list[i2]);
                    pos += __popc(msk);
                }
                if (lane == 0) g_mact[n + 1] = pos;
            }
        }
        tail_barrier(2 * n + 1);
    }
}

// ======= pfin: halting scan + weighted reduce + fp16 split =======
__global__ void pfin(float* __restrict__ hfin, float* __restrict__ cfin,
                     float* __restrict__ ponder_out)
{
    int m = blockIdx.x;
    int j = threadIdx.x;
    __shared__ float ps[NS];
    if (j == 0) {
        const float thresh = 1.0f - 0.01f;
        float halts[NS];
        float cum = 0.f; int nh = NS - 1; bool found = false;
#pragma unroll
        for (int n = 0; n < NS; n++) {
            halts[n] = g_halt[n * BD + m];
            cum += halts[n];
            if (!found && cum >= thresh) { nh = n; found = true; }
        }
        float s = 0.f;
#pragma unroll
        for (int n = 0; n < NS; n++) {
            float p = (n < nh) ? halts[n] : 0.f;
            if (n < nh) s += p;
            ps[n] = p;
        }
        float r = 1.f - s;
        ps[nh] = r;
        ponder_out[m] = (float)nh + 1.f + r;
    }
    __syncthreads();
    float ah = 0.f, ac = 0.f;
#pragma unroll
    for (int n = 0; n < NS; n++) {
        float p = ps[n];
        if (p != 0.f) {
            size_t o = ((size_t)n * BD + m) * HD + j;
            ah += p * g_hs[o];
            ac += p * g_cs[o];
        }
    }
    hfin[(size_t)m * HD + j] = ah;
    cfin[(size_t)m * HD + j] = ac;
    __half hh = __float2half(ah);
    g_hf_hi[(size_t)m * HD + j] = hh;
    g_hf_lo[(size_t)m * HD + j] = __float2half(ah - __half2float(hh));
}

// ======================= launcher =======================
extern "C" void kernel_launch(void* const* d_in, const int* in_sizes, int n_in,
                              void* d_out, int out_size)
{
    const float* x     = (const float*)d_in[0];
    const float* h0    = (const float*)d_in[1];
    const float* c0    = (const float*)d_in[2];
    const float* Wih   = (const float*)d_in[3];
    const float* bih   = (const float*)d_in[4];
    const float* Whh   = (const float*)d_in[5];
    const float* bhh   = (const float*)d_in[6];
    const float* Whalt = (const float*)d_in[7];
    const float* bhalt = (const float*)d_in[8];
    const float* Wout  = (const float*)d_in[9];
    const float* bout  = (const float*)d_in[10];
    (void)in_sizes; (void)n_in; (void)out_size;

    float* out   = (float*)d_out;
    float* out_y = out;
    float* out_h = out + (size_t)BD * HD;
    float* out_c = out + (size_t)BD * HD * 2;
    float* out_p = out + (size_t)BD * HD * 3;

    cudaFuncSetAttribute(mma_gemm<0>, cudaFuncAttributeMaxDynamicSharedMemorySize, DSMEM_BYTES);
    cudaFuncSetAttribute(mma_gemm<1>, cudaFuncAttributeMaxDynamicSharedMemorySize, DSMEM_BYTES);
    cudaFuncSetAttribute(act_tail, cudaFuncAttributeMaxDynamicSharedMemorySize, TAIL_SMEM);

    __half *Whh_hi, *Whh_lo, *Wih_hi, *Wih_lo, *Wout_hi, *Wout_lo;
    __half *x_hi, *x_lo, *h_hi, *h_lo, *hf_hi, *hf_lo;
    float *wflag, *biasp, *xb, *hs, *cs;
    int *listb;
    cudaGetSymbolAddress((void**)&Whh_hi, g_Whh_hi);
    cudaGetSymbolAddress((void**)&Whh_lo, g_Whh_lo);
    cudaGetSymbolAddress((void**)&Wih_hi, g_Wih_hi);
    cudaGetSymbolAddress((void**)&Wih_lo, g_Wih_lo);
    cudaGetSymbolAddress((void**)&Wout_hi, g_Wout_hi);
    cudaGetSymbolAddress((void**)&Wout_lo, g_Wout_lo);
    cudaGetSymbolAddress((void**)&x_hi, g_x_hi);
    cudaGetSymbolAddress((void**)&x_lo, g_x_lo);
    cudaGetSymbolAddress((void**)&h_hi, g_h_hi);
    cudaGetSymbolAddress((void**)&h_lo, g_h_lo);
    cudaGetSymbolAddress((void**)&hf_hi, g_hf_hi);
    cudaGetSymbolAddress((void**)&hf_lo, g_hf_lo);
    cudaGetSymbolAddress((void**)&wflag, g_wflag);
    cudaGetSymbolAddress((void**)&biasp, g_bias);
    cudaGetSymbolAddress((void**)&xb, g_xb);
    cudaGetSymbolAddress((void**)&hs, g_hs);
    cudaGetSymbolAddress((void**)&cs, g_cs);
    cudaGetSymbolAddress((void**)&listb, g_list);

    const size_t HBUF = (size_t)BD * HD;

    // 1) prep (resets ACT state, lists, barriers)
    prep_weights<<<(G4 * HD + 255) / 256, 256>>>(Wih, Whh, bih, bhh);
    prep_data<<<(BD * HD + 255) / 256, 256>>>(x, h0, Wout);

    // 2) x-part GEMM
    dim3 gridG(G4 / 128, BD / 128);
    mma_gemm<0><<<gridG, 256, DSMEM_BYTES>>>(x_hi, x_lo, Wih_hi, Wih_lo, G4, biasp, xb,
                                             nullptr, nullptr, -1, nullptr, nullptr, nullptr,
                                             nullptr, nullptr, nullptr);

    // 3) steps 0..TAIL0-1 as MMA launches with compaction
    for (int n = 0; n < TAIL0; n++) {
        const float* c_i = (n == 0) ? c0 : (cs + (size_t)(n - 1) * HBUF);
        mma_gemm<1><<<gridG, 256, DSMEM_BYTES>>>(
            h_hi + (size_t)(n & 1) * HBUF, h_lo + (size_t)(n & 1) * HBUF,
            Whh_hi, Whh_lo, G4, nullptr, nullptr,
            xb, wflag, n,
            c_i, hs + (size_t)n * HBUF, cs + (size_t)n * HBUF,
            h_hi + (size_t)((n + 1) & 1) * HBUF, h_lo + (size_t)((n + 1) & 1) * HBUF,
            listb + (size_t)(n & 1) * BD);
        halt_compact<<<NCB, 256>>>(n, Whalt, bhalt);
    }

    // 4) steps TAIL0..15 in one persistent straggler kernel (typically instant exit)
    act_tail<<<TAILG, 256, TAIL_SMEM>>>(Whalt, bhalt);

    // 5) halting scan + h_fin / c_fin (+ fp16 split)
    pfin<<<BD, HD>>>(out_h, out_c, out_p);

    // 6) output GEMM
    dim3 gridO(HD / 128, BD / 128);
    mma_gemm<0><<<gridO, 256, DSMEM_BYTES>>>(hf_hi, hf_lo, Wout_hi, Wout_lo, HD, bout, out_y,
                                             nullptr, nullptr, -1, nullptr, nullptr, nullptr,
                                             nullptr, nullptr, nullptr);
}

// round 15
// speedup vs baseline: 1.2710x; 1.0045x over previous
#include <cuda_runtime.h>
#include <cuda_fp16.h>
#include <math.h>
#include <stdint.h>

#define BD 4096
#define HD 512
#define G4 2048    // 4*H
#define NS 16
#define NCB 128    // compaction blocks (32 list positions each)
#define TAIL0 3    // first step handled by the persistent tail
#define TAILG 128  // tail grid (<= SM count, all resident)

// ======================= device scratch (allocation-free) =======================
__device__ __half g_Whh_hi[G4*HD], g_Whh_lo[G4*HD];     // permuted n'=4j+g, K-major
__device__ __half g_Wih_hi[G4*HD], g_Wih_lo[G4*HD];
__device__ __half g_Wout_hi[HD*HD], g_Wout_lo[HD*HD];
__device__ __half g_x_hi[(size_t)BD*HD], g_x_lo[(size_t)BD*HD];
__device__ __half g_h_hi[2][(size_t)BD*HD], g_h_lo[2][(size_t)BD*HD];
__device__ __half g_hf_hi[(size_t)BD*HD], g_hf_lo[(size_t)BD*HD];
__device__ float g_wflag[G4], g_bias[G4];
__device__ float g_xb[(size_t)BD*G4];
__device__ float g_hs[(size_t)NS*BD*HD];
__device__ float g_cs[(size_t)NS*BD*HD];
// ---- ACT state: active-row compaction ----
__device__ float g_halt[NS*BD];
__device__ float g_cum[BD];
__device__ int   g_list[2][BD];
__device__ int   g_mact[NS+1];
__device__ int   g_seg[BD];
__device__ int   g_bcnt[NCB];
__device__ int   g_arrive[NS];
__device__ int   g_bar[2*NS];

// ======================= helpers =======================
__device__ __forceinline__ float sigf(float x) {
    return __fdividef(1.f, 1.f + __expf(-x));
}
__device__ __forceinline__ float tanh_acc(float x) {
    float ax = fabsf(x);
    float e  = __expf(-2.f * ax);
    float t  = __fdividef(1.f - e, 1.f + e);
    return copysignf(t, x);
}
__device__ __forceinline__ uint32_t smem_u32(const void* p) {
    uint32_t a;
    asm("{ .reg .u64 t; cvta.to.shared.u64 t, %1; cvt.u32.u64 %0, t; }" : "=r"(a) : "l"(p));
    return a;
}
__device__ __forceinline__ void cpa16(uint32_t d, const void* s) {
    asm volatile("cp.async.cg.shared.global [%0], [%1], 16;" :: "r"(d), "l"(s));
}
__device__ __forceinline__ void cpa_commit() { asm volatile("cp.async.commit_group;"); }
template <int N> __device__ __forceinline__ void cpa_wait() {
    asm volatile("cp.async.wait_group %0;" :: "n"(N));
}
__device__ __forceinline__ void ldsm4(uint32_t* r, uint32_t a) {
    asm volatile("ldmatrix.sync.aligned.m8n8.x4.shared.b16 {%0,%1,%2,%3}, [%4];"
        : "=r"(r[0]), "=r"(r[1]), "=r"(r[2]), "=r"(r[3]) : "r"(a));
}
__device__ __forceinline__ void mma16816(float* c, const uint32_t* a, const uint32_t* b) {
    asm volatile("mma.sync.aligned.m16n8k16.row.col.f32.f16.f16.f32 "
        "{%0,%1,%2,%3}, {%4,%5,%6,%7}, {%8,%9}, {%0,%1,%2,%3};"
        : "+f"(c[0]), "+f"(c[1]), "+f"(c[2]), "+f"(c[3])
        : "r"(a[0]), "r"(a[1]), "r"(a[2]), "r"(a[3]), "r"(b[0]), "r"(b[1]));
}

// smem tile layout: rows x 64B (4 x 16B chunks), XOR-swizzled
#define TILE_BYTES 8192
#define STAGE_BYTES 32768
#define NSTAGE 3
#define DSMEM_BYTES (NSTAGE * STAGE_BYTES)   // 96KB
#define CSTRIDE 132
// n64-variant (M=64 tile) stage layout: Ahi 4K | Alo 4K | Bhi 8K | Blo 8K
#define S64_BYTES 24576
#define S64_ALO 4096
#define S64_BHI 8192
#define S64_BLO 16384
#define DSMEM64 (NSTAGE * S64_BYTES)         // 72KB
// tail smem partition
#define TS_WS    0
#define TS_HS    (16*516*4)
#define TS_GS    (TS_HS + 16*512*4)
#define TS_MS    (TS_GS + 16*16*4)
#define TS_FLAG  (TS_MS + 16*4)
#define TAIL_SMEM (TS_FLAG + BD)

// ======================= merged prep kernel =======================
__global__ void prep_all(const float* __restrict__ Wih, const float* __restrict__ Whh,
                         const float* __restrict__ bih, const float* __restrict__ bhh,
                         const float* __restrict__ x, const float* __restrict__ h0,
                         const float* __restrict__ Wout) {
    size_t idx = (size_t)blockIdx.x * blockDim.x + threadIdx.x;
    if (idx < (size_t)G4 * HD) {
        int np = (int)(idx >> 9), k = (int)(idx & 511);
        int j = np >> 2, g = np & 3;
        int row = g * HD + j;
        float wh = Whh[row * HD + k];
        __half h1 = __float2half(wh);
        g_Whh_hi[idx] = h1;
        g_Whh_lo[idx] = __float2half(wh - __half2float(h1));
        float wi = Wih[row * (HD + 1) + 1 + k];
        __half i1 = __float2half(wi);
        g_Wih_hi[idx] = i1;
        g_Wih_lo[idx] = __float2half(wi - __half2float(i1));
        if (k == 0) {
            g_wflag[np] = Wih[row * (HD + 1)];
            g_bias [np] = bih[row] + bhh[row];
        }
    }
    if (idx < (size_t)BD * HD) {
        float v = x[idx];
        __half hv = __float2half(v);
        g_x_hi[idx] = hv;
        g_x_lo[idx] = __float2half(v - __half2float(hv));
        float h = h0[idx];
        __half hh = __float2half(h);
        g_h_hi[0][idx] = hh;
        g_h_lo[0][idx] = __float2half(h - __half2float(hh));
    }
    if (idx < (size_t)HD * HD) {
        float w = Wout[idx];
        __half wh = __float2half(w);
        g_Wout_hi[idx] = wh;
        g_Wout_lo[idx] = __float2half(w - __half2float(wh));
    }
    if (idx < BD) { g_cum[idx] = 0.f; g_list[0][idx] = (int)idx; }
    if (idx < NS) g_arrive[idx] = 0;
    if (idx < NS + 1) g_mact[idx] = (idx == 0) ? BD : 0;
    if (idx < 2 * NS) g_bar[idx] = 0;
}

// ======================= mma.sync GEMM + fused epilogue (M=128 x N=128) =======================
template <int MODE>
__global__ void __launch_bounds__(256, 2)
mma_gemm(const __half* __restrict__ Ahi, const __half* __restrict__ Alo,
         const __half* __restrict__ Bhi, const __half* __restrict__ Blo,
         int Ntot, const float* __restrict__ bias, float* __restrict__ Cout,
         const float* __restrict__ xb, const float* __restrict__ wflag, int sidx,
         const float* __restrict__ c_in, float* __restrict__ h_out, float* __restrict__ c_out,
         __half* __restrict__ hhi_out, __half* __restrict__ hlo_out,
         const int* __restrict__ list)
{
    extern __shared__ char dsm[];
    __shared__ int ridx_s[128];

    const int tid  = threadIdx.x;
    const int wid  = tid >> 5;
    const int lane = tid & 31;
    const int m0 = blockIdx.y * 128;
    const int n0 = blockIdx.x * 128;
    const int wm = (wid & 3) * 32;
    const int wn = (wid >> 2) * 64;

    if (MODE == 1) {
        const int mact = g_mact[sidx];
        if (m0 >= mact) return;
        if (tid < 128) {
            int g = m0 + tid;
            ridx_s[tid] = list[g < mact ? g : mact - 1];
        }
        __syncthreads();
    }

    const uint32_t sbase = smem_u32(dsm);

    float acc[2][8][4];
#pragma unroll
    for (int a = 0; a < 2; a++)
#pragma unroll
        for (int b = 0; b < 8; b++)
#pragma unroll
            for (int q = 0; q < 4; q++) acc[a][b][q] = 0.f;

    auto load_stage = [&](int kc, int s) {
        uint32_t st = sbase + s * STAGE_BYTES;
#pragma unroll
        for (int i = 0; i < 2; i++) {
            int cid = tid + i * 256;
            int row = cid >> 2, c = cid & 3;
            uint32_t off = row * 64 + ((c ^ ((row >> 1) & 3)) << 4);
            int arow = (MODE == 1) ? ridx_s[row] : (m0 + row);
            size_t ga = (size_t)arow * 512 + kc * 32 + c * 8;
            size_t gb = (size_t)(n0 + row) * 512 + kc * 32 + c * 8;
            cpa16(st + off,                  Ahi + ga);
            cpa16(st + TILE_BYTES + off,     Alo + ga);
            cpa16(st + 2 * TILE_BYTES + off, Bhi + gb);
            cpa16(st + 3 * TILE_BYTES + off, Blo + gb);
        }
        cpa_commit();
    };

    auto compute = [&](int s) {
        uint32_t st = sbase + s * STAGE_BYTES;
#pragma unroll
        for (int k16 = 0; k16 < 2; k16++) {
            uint32_t ahi[2][4], alo[2][4];
#pragma unroll
            for (int mt = 0; mt < 2; mt++) {
                int row = wm + mt * 16 + (lane & 7) + ((lane >> 3) & 1) * 8;
                int ch  = k16 * 2 + (lane >> 4);
                uint32_t off = row * 64 + ((ch ^ ((row >> 1) & 3)) << 4);
                ldsm4(ahi[mt], st + off);
                ldsm4(alo[mt], st + TILE_BYTES + off);
            }
#pragma unroll
            for (int ng = 0; ng < 4; ng++) {
                uint32_t bh[4], bl[4];
                int row = wn + ng * 16 + (lane & 7) + ((lane >> 4) & 1) * 8;
                int ch  = k16 * 2 + ((lane >> 3) & 1);
                uint32_t off = row * 64 + ((ch ^ ((row >> 1) & 3)) << 4);
                ldsm4(bh, st + 2 * TILE_BYTES + off);
                ldsm4(bl, st + 3 * TILE_BYTES + off);
#pragma unroll
                for (int mt = 0; mt < 2; mt++)
#pragma unroll
                    for (int nf = 0; nf < 2; nf++)
                        mma16816(acc[mt][ng * 2 + nf], ahi[mt], &bh[nf * 2]);
#pragma unroll
                for (int mt = 0; mt < 2; mt++)
#pragma unroll
                    for (int nf = 0; nf < 2; nf++)
                        mma16816(acc[mt][ng * 2 + nf], ahi[mt], &bl[nf * 2]);
#pragma unroll
                for (int mt = 0; mt < 2; mt++)
#pragma unroll
                    for (int nf = 0; nf < 2; nf++)
                        mma16816(acc[mt][ng * 2 + nf], alo[mt], &bh[nf * 2]);
            }
        }
    };

    load_stage(0, 0);
    load_stage(1, 1);
    for (int kc = 0; kc < 16; kc++) {
        cpa_wait<1>();
        __syncthreads();
        if (kc + 2 < 16) load_stage(kc + 2, (kc + 2) % NSTAGE);
        compute(kc % NSTAGE);
    }
    __syncthreads();

    float* Cs = (float*)dsm;
#pragma unroll
    for (int mt = 0; mt < 2; mt++)
#pragma unroll
        for (int nf = 0; nf < 8; nf++) {
            int row = wm + mt * 16 + (lane >> 2);
            int col = wn + nf * 8 + (lane & 3) * 2;
            Cs[row * CSTRIDE + col]           = acc[mt][nf][0];
            Cs[row * CSTRIDE + col + 1]       = acc[mt][nf][1];
            Cs[(row + 8) * CSTRIDE + col]     = acc[mt][nf][2];
            Cs[(row + 8) * CSTRIDE + col + 1] = acc[mt][nf][3];
        }
    __syncthreads();

    const int ml = tid >> 1;
    const int colbase = (tid & 1) * 64;

    if (MODE == 0) {
        const int m = m0 + ml;
#pragma unroll
        for (int q = 0; q < 16; q++) {
            int ncol = colbase + q * 4;
            float4 v  = *(float4*)&Cs[ml * CSTRIDE + ncol];
            float4 bv = *(const float4*)&bias[n0 + ncol];
            v.x += bv.x; v.y += bv.y; v.z += bv.z; v.w += bv.w;
            *(float4*)&Cout[(size_t)m * Ntot + n0 + ncol] = v;
        }
    } else {
        const int m = ridx_s[ml];
        const int j0 = (n0 + colbase) >> 2;
        const int step0 = (sidx == 0);
        float cold[16];
#pragma unroll
        for (int q = 0; q < 16; q += 4) {
            float4 cv = *(const float4*)&c_in[(size_t)m * HD + j0 + q];
            cold[q] = cv.x; cold[q + 1] = cv.y; cold[q + 2] = cv.z; cold[q + 3] = cv.w;
        }
        float hbuf[16], cbuf[16];
#pragma unroll
        for (int q = 0; q < 16; q++) {
            int ncol = colbase + q * 4;
            float4 a  = *(float4*)&Cs[ml * CSTRIDE + ncol];
            float4 xv = *(const float4*)&xb[(size_t)m * G4 + n0 + ncol];
            float gi = a.x + xv.x, gf = a.y + xv.y, gg = a.z + xv.z, go = a.w + xv.w;
            if (step0) {
                float4 wf = *(const float4*)&wflag[n0 + ncol];
                gi += wf.x; gf += wf.y; gg += wf.z; go += wf.w;
            }
            float cn = sigf(gf) * cold[q] + sigf(gi) * tanh_acc(gg);
            float hn = sigf(go) * tanh_acc(cn);
            hbuf[q] = hn; cbuf[q] = cn;
        }
#pragma unroll
        for (int q = 0; q < 16; q += 4) {
            *(float4*)&h_out[(size_t)m * HD + j0 + q] = make_float4(hbuf[q], hbuf[q+1], hbuf[q+2], hbuf[q+3]);
            *(float4*)&c_out[(size_t)m * HD + j0 + q] = make_float4(cbuf[q], cbuf[q+1], cbuf[q+2], cbuf[q+3]);
        }
        __half hh[16], hl[16];
#pragma unroll
        for (int q = 0; q < 16; q++) {
            hh[q] = __float2half(hbuf[q]);
            hl[q] = __float2half(hbuf[q] - __half2float(hh[q]));
        }
        *(uint4*)&hhi_out[(size_t)m * HD + j0]     = *(uint4*)&hh[0];
        *(uint4*)&hhi_out[(size_t)m * HD + j0 + 8] = *(uint4*)&hh[8];
        *(uint4*)&hlo_out[(size_t)m * HD + j0]     = *(uint4*)&hl[0];
        *(uint4*)&hlo_out[(size_t)m * HD + j0 + 8] = *(uint4*)&hl[8];
    }
}

// ======================= M=64 x N=128 GEMM + bias (out-GEMM: 2x CTAs, half tile time) =======================
// Per-element accumulation order identical to mma_gemm<0> (chunk -> k16 -> term).
__global__ void __launch_bounds__(256, 2)
gemm_n64(const __half* __restrict__ Ahi, const __half* __restrict__ Alo,
         const __half* __restrict__ Bhi, const __half* __restrict__ Blo,
         int Ntot, const float* __restrict__ bias, float* __restrict__ Cout)
{
    extern __shared__ char dsm[];
    const int tid  = threadIdx.x;
    const int wid  = tid >> 5;
    const int lane = tid & 31;
    const int m0 = blockIdx.y * 64;
    const int n0 = blockIdx.x * 128;
    const int wm = (wid & 1) * 32;     // 2 warps over M (32 rows each)
    const int wn = (wid >> 1) * 32;    // 4 warps over N (32 cols each)
    const uint32_t sbase = smem_u32(dsm);

    float acc[2][4][4];
#pragma unroll
    for (int a = 0; a < 2; a++)
#pragma unroll
        for (int b = 0; b < 4; b++)
#pragma unroll
            for (int q = 0; q < 4; q++) acc[a][b][q] = 0.f;

    auto load_stage = [&](int kc, int s) {
        uint32_t st = sbase + s * S64_BYTES;
        {   // A: 64 rows x 4 chunks = 256 ld16
            int row = tid >> 2, c = tid & 3;
            uint32_t off = row * 64 + ((c ^ ((row >> 1) & 3)) << 4);
            size_t ga = (size_t)(m0 + row) * 512 + kc * 32 + c * 8;
            cpa16(st + off,           Ahi + ga);
            cpa16(st + S64_ALO + off, Alo + ga);
        }
#pragma unroll
        for (int i = 0; i < 2; i++) {   // B: 128 rows x 4 chunks = 512 ld16
            int cid = tid + i * 256;
            int row = cid >> 2, c = cid & 3;
            uint32_t off = row * 64 + ((c ^ ((row >> 1) & 3)) << 4);
            size_t gb = (size_t)(n0 + row) * 512 + kc * 32 + c * 8;
            cpa16(st + S64_BHI + off, Bhi + gb);
            cpa16(st + S64_BLO + off, Blo + gb);
        }
        cpa_commit();
    };

    auto compute = [&](int s) {
        uint32_t st = sbase + s * S64_BYTES;
#pragma unroll
        for (int k16 = 0; k16 < 2; k16++) {
            uint32_t ahi[2][4], alo[2][4];
#pragma unroll
            for (int mt = 0; mt < 2; mt++) {
                int row = wm + mt * 16 + (lane & 7) + ((lane >> 3) & 1) * 8;
                int ch  = k16 * 2 + (lane >> 4);
                uint32_t off = row * 64 + ((ch ^ ((row >> 1) & 3)) << 4);
                ldsm4(ahi[mt], st + off);
                ldsm4(alo[mt], st + S64_ALO + off);
            }
#pragma unroll
            for (int ng = 0; ng < 2; ng++) {
                uint32_t bh[4], bl[4];
                int row = wn + ng * 16 + (lane & 7) + ((lane >> 4) & 1) * 8;
                int ch  = k16 * 2 + ((lane >> 3) & 1);
                uint32_t off = row * 64 + ((ch ^ ((row >> 1) & 3)) << 4);
                ldsm4(bh, st + S64_BHI + off);
                ldsm4(bl, st + S64_BLO + off);
#pragma unroll
                for (int mt = 0; mt < 2; mt++)
#pragma unroll
                    for (int nf = 0; nf < 2; nf++)
                        mma16816(acc[mt][ng * 2 + nf], ahi[mt], &bh[nf * 2]);
#pragma unroll
                for (int mt = 0; mt < 2; mt++)
#pragma unroll
                    for (int nf = 0; nf < 2; nf++)
                        mma16816(acc[mt][ng * 2 + nf], ahi[mt], &bl[nf * 2]);
#pragma unroll
                for (int mt = 0; mt < 2; mt++)
#pragma unroll
                    for (int nf = 0; nf < 2; nf++)
                        mma16816(acc[mt][ng * 2 + nf], alo[mt], &bh[nf * 2]);
            }
        }
    };

    load_stage(0, 0);
    load_stage(1, 1);
    for (int kc = 0; kc < 16; kc++) {
        cpa_wait<1>();
        __syncthreads();
        if (kc + 2 < 16) load_stage(kc + 2, (kc + 2) % NSTAGE);
        compute(kc % NSTAGE);
    }
    __syncthreads();

    float* Cs = (float*)dsm;   // 64 x CSTRIDE
#pragma unroll
    for (int mt = 0; mt < 2; mt++)
#pragma unroll
        for (int nf = 0; nf < 4; nf++) {
            int row = wm + mt * 16 + (lane >> 2);
            int col = wn + nf * 8 + (lane & 3) * 2;
            Cs[row * CSTRIDE + col]           = acc[mt][nf][0];
            Cs[row * CSTRIDE + col + 1]       = acc[mt][nf][1];
            Cs[(row + 8) * CSTRIDE + col]     = acc[mt][nf][2];
            Cs[(row + 8) * CSTRIDE + col + 1] = acc[mt][nf][3];
        }
    __syncthreads();

    const int ml = tid >> 2;            // 0..63
    const int colbase = (tid & 3) * 32; // 4 col-quarters
    const int m = m0 + ml;
#pragma unroll
    for (int q = 0; q < 8; q++) {
        int ncol = colbase + q * 4;
        float4 v  = *(float4*)&Cs[ml * CSTRIDE + ncol];
        float4 bv = *(const float4*)&bias[n0 + ncol];
        v.x += bv.x; v.y += bv.y; v.z += bv.z; v.w += bv.w;
        *(float4*)&Cout[(size_t)m * Ntot + n0 + ncol] = v;
    }
}

// ============ halt + compact (steps 0..TAIL0-1) ============
__global__ void halt_compact(int n, const float* __restrict__ Whalt,
                             const float* __restrict__ bhalt)
{
    __shared__ int s_flags[32];
    __shared__ int s_rows[32];
    __shared__ int s_cnt[NCB];
    __shared__ int s_off[NCB];
    __shared__ int s_last;

    const int tid = threadIdx.x;
    const int wid = tid >> 5;
    const int lane = tid & 31;
    const int b = blockIdx.x;

    const int mact = g_mact[n];
    if (mact == 0) {
        if (b == 0 && tid == 0) g_mact[n + 1] = 0;
        return;
    }
    const int* list = g_list[n & 1];
    const float thresh = 1.0f - 0.01f;
    const float4* w4 = (const float4*)Whalt;

#pragma unroll
    for (int r = 0; r < 4; r++) {
        int i = b * 32 + wid * 4 + r;
        int flag = 0, m = -1;
        if (i < mact) {
            m = list[i];
            const float4* h4 = (const float4*)(g_hs + ((size_t)n * BD + m) * HD);
            float sdot = 0.f;
#pragma unroll
            for (int it = 0; it < 4; it++) {
                float4 a = h4[lane + it * 32];
                float4 w = w4[lane + it * 32];
                sdot += a.x * w.x + a.y * w.y + a.z * w.z + a.w * w.w;
            }
#pragma unroll
            for (int off = 16; off; off >>= 1) sdot += __shfl_xor_sync(0xffffffffu, sdot, off);
            if (lane == 0) {
                float halt = sigf(sdot + bhalt[0]);
                float cum = g_cum[m] + halt;
                g_cum[m] = cum;
                g_halt[n * BD + m] = halt;
                flag = (cum < thresh) ? 1 : 0;
            }
        }
        if (lane == 0) { s_flags[wid * 4 + r] = flag; s_rows[wid * 4 + r] = m; }
    }
    __syncthreads();

    if (wid == 0) {
        int f = s_flags[lane];
        unsigned mask = __ballot_sync(0xffffffffu, f);
        int pre = __popc(mask & ((1u << lane) - 1u));
        if (f) g_seg[b * 32 + pre] = s_rows[lane];
        if (lane == 0) g_bcnt[b] = __popc(mask);
    }
    __syncthreads();

    if (tid == 0) {
        __threadfence();
        int old = atomicAdd(&g_arrive[n], 1);
        s_last = (old == (int)gridDim.x - 1) ? 1 : 0;
    }
    __syncthreads();

    if (s_last) {
        if (tid < NCB) s_cnt[tid] = __ldcg(&g_bcnt[tid]);
        __syncthreads();
        if (tid == 0) {
            int off = 0;
#pragma unroll 8
            for (int s2 = 0; s2 < NCB; s2++) { s_off[s2] = off; off += s_cnt[s2]; }
            g_mact[n + 1] = off;
        }
        __syncthreads();
        int* outl = g_list[(n + 1) & 1];
        if (tid < NCB) {
            int c = s_cnt[tid], o = s_off[tid];
            for (int i = 0; i < c; i++)
                outl[o + i] = __ldcg(&g_seg[tid * 32 + i]);
        }
    }
}

// ============ persistent tail: steps TAIL0..15 (fp32 SIMT straggler path) ============
__device__ __forceinline__ void tail_barrier(int idx) {
    __threadfence();
    __syncthreads();
    if (threadIdx.x == 0) {
        atomicAdd(&g_bar[idx], 1);
        while (*(volatile int*)&g_bar[idx] < (int)gridDim.x) { }
    }
    __syncthreads();
}

__global__ void __launch_bounds__(256, 1)
act_tail(const float* __restrict__ Whalt, const float* __restrict__ bhalt)
{
    if (*(volatile int*)&g_mact[TAIL0] == 0) return;

    extern __shared__ char dsm[];
    float* Ws   = (float*)(dsm + TS_WS);
    float* hs_s = (float*)(dsm + TS_HS);
    float* gsum = (float*)(dsm + TS_GS);
    int*   m_s  = (int*)  (dsm + TS_MS);
    char*  flg  = (char*) (dsm + TS_FLAG);

    const int tid = threadIdx.x;
    const int wid = tid >> 5;
    const int lane = tid & 31;
    const int b = blockIdx.x;
    const size_t HBUF = (size_t)BD * HD;
    const int np0 = b * 16;

    for (int idx = tid; idx < 16 * 512; idx += 256) {
        int col = idx >> 9, k = idx & 511;
        size_t o = (size_t)(np0 + col) * 512 + k;
        Ws[col * 516 + k] = __half2float(g_Whh_hi[o]) + __half2float(g_Whh_lo[o]);
    }
    __syncthreads();

    for (int n = TAIL0; n < NS; n++) {
        const int mact = *(volatile int*)&g_mact[n];
        if (mact == 0) break;
        const int* list = g_list[n & 1];
        const float* hprev = g_hs + (size_t)(n - 1) * HBUF;
        const float* cprev = g_cs + (size_t)(n - 1) * HBUF;
        float* hout = g_hs + (size_t)n * HBUF;
        float* cout = g_cs + (size_t)n * HBUF;

        for (int rc = 0; rc < mact; rc += 16) {
            for (int rr = wid; rr < 16; rr += 8) {
                int i = rc + rr;
                if (i < mact) {
                    int m = __ldcg(&list[i]);
                    if (lane == 0) m_s[rr] = m;
                    const float4* src = (const float4*)(hprev + (size_t)m * HD);
                    float4* dst = (float4*)(hs_s + rr * 512);
                    for (int q = lane; q < 128; q += 32) dst[q] = src[q];
                }
            }
            __syncthreads();
            const int col = tid & 15, rg = tid >> 4;
            if (rc + rg < mact) {
                const float4* hv = (const float4*)(hs_s + rg * 512);
                const float4* wv = (const float4*)(Ws + col * 516);
                float d = 0.f;
                for (int q = 0; q < 128; q++) {
                    float4 a = hv[q], w = wv[q];
                    d += a.x * w.x + a.y * w.y + a.z * w.z + a.w * w.w;
                }
                gsum[rg * 16 + col] = d + g_xb[(size_t)m_s[rg] * G4 + np0 + col];
            }
            __syncthreads();
            if (tid < 64) {
                int rg2 = tid >> 2, jj = tid & 3;
                if (rc + rg2 < mact) {
                    int m = m_s[rg2];
                    float gi = gsum[rg2 * 16 + jj * 4 + 0];
                    float gf = gsum[rg2 * 16 + jj * 4 + 1];
                    float gg = gsum[rg2 * 16 + jj * 4 + 2];
                    float go = gsum[rg2 * 16 + jj * 4 + 3];
                    int j = (np0 >> 2) + jj;
                    float co = cprev[(size_t)m * HD + j];
                    float cn = sigf(gf) * co + sigf(gi) * tanh_acc(gg);
                    float hn = sigf(go) * tanh_acc(cn);
                    hout[(size_t)m * HD + j] = hn;
                    cout[(size_t)m * HD + j] = cn;
                }
            }
            __syncthreads();
        }

        tail_barrier(2 * n);

        if (b == 0) {
            const float4* w4 = (const float4*)Whalt;
            for (int i = wid; i < mact; i += 8) {
                int m = __ldcg(&list[i]);
                const float4* h4 = (const float4*)(hout + (size_t)m * HD);
                float sdot = 0.f;
#pragma unroll
                for (int it = 0; it < 4; it++) {
                    float4 a = h4[lane + it * 32];
                    float4 w = w4[lane + it * 32];
                    sdot += a.x * w.x + a.y * w.y + a.z * w.z + a.w * w.w;
                }
#pragma unroll
                for (int off = 16; off; off >>= 1) sdot += __shfl_xor_sync(0xffffffffu, sdot, off);
                if (lane == 0) {
                    float halt = sigf(sdot + bhalt[0]);
                    float cum = g_cum[m] + halt;
                    g_cum[m] = cum;
                    g_halt[n * BD + m] = halt;
                    flg[i] = (cum < 1.0f - 0.01f) ? 1 : 0;
                }
            }
            __syncthreads();
            if (wid == 0) {
                int* outl = g_list[(n + 1) & 1];
                int pos = 0;
                for (int c2 = 0; c2 < mact; c2 += 32) {
                    int i2 = c2 + lane;
                    int f = (i2 < mact) ? flg[i2] : 0;
                    unsigned msk = __ballot_sync(0xffffffffu, f);
                    if (f) outl[pos + __popc(msk & ((1u << lane) - 1u))] = __ldcg(&list[i2]);
                    pos += __popc(msk);
                }
                if (lane == 0) g_mact[n + 1] = pos;
            }
        }
        tail_barrier(2 * n + 1);
    }
}

// ======= pfin: halting scan + weighted reduce + fp16 split =======
__global__ void pfin(float* __restrict__ hfin, float* __restrict__ cfin,
                     float* __restrict__ ponder_out)
{
    int m = blockIdx.x;
    int j = threadIdx.x;
    __shared__ float ps[NS];
    if (j == 0) {
        const float thresh = 1.0f - 0.01f;
        float halts[NS];
        float cum = 0.f; int nh = NS - 1; bool found = false;
#pragma unroll
        for (int n = 0; n < NS; n++) {
            halts[n] = g_halt[n * BD + m];
            cum += halts[n];
            if (!found && cum >= thresh) { nh = n; found = true; }
        }
        float s = 0.f;
#pragma unroll
        for (int n = 0; n < NS; n++) {
            float p = (n < nh) ? halts[n] : 0.f;
            if (n < nh) s += p;
            ps[n] = p;
        }
        float r = 1.f - s;
        ps[nh] = r;
        ponder_out[m] = (float)nh + 1.f + r;
    }
    __syncthreads();
    float ah = 0.f, ac = 0.f;
#pragma unroll
    for (int n = 0; n < NS; n++) {
        float p = ps[n];
        if (p != 0.f) {
            size_t o = ((size_t)n * BD + m) * HD + j;
            ah += p * g_hs[o];
            ac += p * g_cs[o];
        }
    }
    hfin[(size_t)m * HD + j] = ah;
    cfin[(size_t)m * HD + j] = ac;
    __half hh = __float2half(ah);
    g_hf_hi[(size_t)m * HD + j] = hh;
    g_hf_lo[(size_t)m * HD + j] = __float2half(ah - __half2float(hh));
}

// ======================= launcher =======================
extern "C" void kernel_launch(void* const* d_in, const int* in_sizes, int n_in,
                              void* d_out, int out_size)
{
    const float* x     = (const float*)d_in[0];
    const float* h0    = (const float*)d_in[1];
    const float* c0    = (const float*)d_in[2];
    const float* Wih   = (const float*)d_in[3];
    const float* bih   = (const float*)d_in[4];
    const float* Whh   = (const float*)d_in[5];
    const float* bhh   = (const float*)d_in[6];
    const float* Whalt = (const float*)d_in[7];
    const float* bhalt = (const float*)d_in[8];
    const float* Wout  = (const float*)d_in[9];
    const float* bout  = (const float*)d_in[10];
    (void)in_sizes; (void)n_in; (void)out_size;

    float* out   = (float*)d_out;
    float* out_y = out;
    float* out_h = out + (size_t)BD * HD;
    float* out_c = out + (size_t)BD * HD * 2;
    float* out_p = out + (size_t)BD * HD * 3;

    cudaFuncSetAttribute(mma_gemm<0>, cudaFuncAttributeMaxDynamicSharedMemorySize, DSMEM_BYTES);
    cudaFuncSetAttribute(mma_gemm<1>, cudaFuncAttributeMaxDynamicSharedMemorySize, DSMEM_BYTES);
    cudaFuncSetAttribute(gemm_n64, cudaFuncAttributeMaxDynamicSharedMemorySize, DSMEM64);
    cudaFuncSetAttribute(act_tail, cudaFuncAttributeMaxDynamicSharedMemorySize, TAIL_SMEM);

    __half *Whh_hi, *Whh_lo, *Wih_hi, *Wih_lo, *Wout_hi, *Wout_lo;
    __half *x_hi, *x_lo, *h_hi, *h_lo, *hf_hi, *hf_lo;
    float *wflag, *biasp, *xb, *hs, *cs;
    int *listb;
    cudaGetSymbolAddress((void**)&Whh_hi, g_Whh_hi);
    cudaGetSymbolAddress((void**)&Whh_lo, g_Whh_lo);
    cudaGetSymbolAddress((void**)&Wih_hi, g_Wih_hi);
    cudaGetSymbolAddress((void**)&Wih_lo, g_Wih_lo);
    cudaGetSymbolAddress((void**)&Wout_hi, g_Wout_hi);
    cudaGetSymbolAddress((void**)&Wout_lo, g_Wout_lo);
    cudaGetSymbolAddress((void**)&x_hi, g_x_hi);
    cudaGetSymbolAddress((void**)&x_lo, g_x_lo);
    cudaGetSymbolAddress((void**)&h_hi, g_h_hi);
    cudaGetSymbolAddress((void**)&h_lo, g_h_lo);
    cudaGetSymbolAddress((void**)&hf_hi, g_hf_hi);
    cudaGetSymbolAddress((void**)&hf_lo, g_hf_lo);
    cudaGetSymbolAddress((void**)&wflag, g_wflag);
    cudaGetSymbolAddress((void**)&biasp, g_bias);
    cudaGetSymbolAddress((void**)&xb, g_xb);
    cudaGetSymbolAddress((void**)&hs, g_hs);
    cudaGetSymbolAddress((void**)&cs, g_cs);
    cudaGetSymbolAddress((void**)&listb, g_list);

    const size_t HBUF = (size_t)BD * HD;

    // 1) merged prep (weights + data + ACT state)
    prep_all<<<(BD * HD + 255) / 256, 256>>>(Wih, Whh, bih, bhh, x, h0, Wout);

    // 2) x-part GEMM
    dim3 gridG(G4 / 128, BD / 128);
    mma_gemm<0><<<gridG, 256, DSMEM_BYTES>>>(x_hi, x_lo, Wih_hi, Wih_lo, G4, biasp, xb,
                                             nullptr, nullptr, -1, nullptr, nullptr, nullptr,
                                             nullptr, nullptr, nullptr);

    // 3) steps 0..TAIL0-1 as MMA launches with compaction
    for (int n = 0; n < TAIL0; n++) {
        const float* c_i = (n == 0) ? c0 : (cs + (size_t)(n - 1) * HBUF);
        mma_gemm<1><<<gridG, 256, DSMEM_BYTES>>>(
            h_hi + (size_t)(n & 1) * HBUF, h_lo + (size_t)(n & 1) * HBUF,
            Whh_hi, Whh_lo, G4, nullptr, nullptr,
            xb, wflag, n,
            c_i, hs + (size_t)n * HBUF, cs + (size_t)n * HBUF,
            h_hi + (size_t)((n + 1) & 1) * HBUF, h_lo + (size_t)((n + 1) & 1) * HBUF,
            listb + (size_t)(n & 1) * BD);
        halt_compact<<<NCB, 256>>>(n, Whalt, bhalt);
    }

    // 4) persistent straggler tail (typically instant exit)
    act_tail<<<TAILG, 256, TAIL_SMEM>>>(Whalt, bhalt);

    // 5) halting scan + h_fin / c_fin (+ fp16 split)
    pfin<<<BD, HD>>>(out_h, out_c, out_p);

    // 6) output GEMM: M=64 tiles -> 256 CTAs, ~half the single-wave latency
    dim3 gridO(HD / 128, BD / 64);
    gemm_n64<<<gridO, 256, DSMEM64>>>(hf_hi, hf_lo, Wout_hi, Wout_lo, HD, bout, out_y);
}

// round 16
// speedup vs baseline: 1.3124x; 1.0326x over previous
#include <cuda_runtime.h>
#include <cuda_fp16.h>
#include <math.h>
#include <stdint.h>

#define BD 4096
#define HD 512
#define G4 2048    // 4*H
#define NS 16
#define NB 16      // n-blocks per step GEMM (G4/128)
#define NCB 128    // compaction blocks (32 list positions each)
#define TAIL0 3    // first step handled by the persistent tail
#define TAILG 128  // tail grid (<= SM count, all resident)

// ======================= device scratch (allocation-free) =======================
__device__ __half g_Whh_hi[G4*HD], g_Whh_lo[G4*HD];     // permuted n'=4j+g, K-major
__device__ __half g_Wih_hi[G4*HD], g_Wih_lo[G4*HD];
__device__ __half g_Wout_hi[HD*HD], g_Wout_lo[HD*HD];
__device__ __half g_x_hi[(size_t)BD*HD], g_x_lo[(size_t)BD*HD];
__device__ __half g_h_hi[2][(size_t)BD*HD], g_h_lo[2][(size_t)BD*HD];
__device__ __half g_hf_hi[(size_t)BD*HD], g_hf_lo[(size_t)BD*HD];
__device__ float g_wflag[G4], g_bias[G4];
__device__ float g_xb[(size_t)BD*G4];
__device__ float g_hs[(size_t)NS*BD*HD];
__device__ float g_cs[(size_t)NS*BD*HD];
// ---- ACT state: active-row compaction ----
__device__ float g_halt[NS*BD];
__device__ float g_cum[BD];
__device__ int   g_list[2][BD];
__device__ int   g_mact[NS+1];
__device__ int   g_seg[BD];
__device__ int   g_bcnt[NCB];
__device__ int   g_arrive[NS];
__device__ int   g_bar[2*NS];
__device__ float g_part[(size_t)BD*NB];   // per-(row, nblock) halt-dot partials

// ======================= helpers =======================
__device__ __forceinline__ float sigf(float x) {
    return __fdividef(1.f, 1.f + __expf(-x));
}
__device__ __forceinline__ float tanh_acc(float x) {
    float ax = fabsf(x);
    float e  = __expf(-2.f * ax);
    float t  = __fdividef(1.f - e, 1.f + e);
    return copysignf(t, x);
}
__device__ __forceinline__ uint32_t smem_u32(const void* p) {
    uint32_t a;
    asm("{ .reg .u64 t; cvta.to.shared.u64 t, %1; cvt.u32.u64 %0, t; }" : "=r"(a) : "l"(p));
    return a;
}
__device__ __forceinline__ void cpa16(uint32_t d, const void* s) {
    asm volatile("cp.async.cg.shared.global [%0], [%1], 16;" :: "r"(d), "l"(s));
}
__device__ __forceinline__ void cpa_commit() { asm volatile("cp.async.commit_group;"); }
template <int N> __device__ __forceinline__ void cpa_wait() {
    asm volatile("cp.async.wait_group %0;" :: "n"(N));
}
__device__ __forceinline__ void ldsm4(uint32_t* r, uint32_t a) {
    asm volatile("ldmatrix.sync.aligned.m8n8.x4.shared.b16 {%0,%1,%2,%3}, [%4];"
        : "=r"(r[0]), "=r"(r[1]), "=r"(r[2]), "=r"(r[3]) : "r"(a));
}
__device__ __forceinline__ void mma16816(float* c, const uint32_t* a, const uint32_t* b) {
    asm volatile("mma.sync.aligned.m16n8k16.row.col.f32.f16.f16.f32 "
        "{%0,%1,%2,%3}, {%4,%5,%6,%7}, {%8,%9}, {%0,%1,%2,%3};"
        : "+f"(c[0]), "+f"(c[1]), "+f"(c[2]), "+f"(c[3])
        : "r"(a[0]), "r"(a[1]), "r"(a[2]), "r"(a[3]), "r"(b[0]), "r"(b[1]));
}

// smem tile layout: rows x 64B (4 x 16B chunks), XOR-swizzled
#define TILE_BYTES 8192
#define STAGE_BYTES 32768
#define NSTAGE 3
#define DSMEM_BYTES (NSTAGE * STAGE_BYTES)   // 96KB
#define CSTRIDE 132
// n64-variant stage layout
#define S64_BYTES 24576
#define S64_ALO 4096
#define S64_BHI 8192
#define S64_BLO 16384
#define DSMEM64 (NSTAGE * S64_BYTES)
// tail smem partition
#define TS_WS    0
#define TS_HS    (16*516*4)
#define TS_GS    (TS_HS + 16*512*4)
#define TS_MS    (TS_GS + 16*16*4)
#define TS_FLAG  (TS_MS + 16*4)
#define TAIL_SMEM (TS_FLAG + BD)

// ======================= merged prep kernel =======================
__global__ void prep_all(const float* __restrict__ Wih, const float* __restrict__ Whh,
                         const float* __restrict__ bih, const float* __restrict__ bhh,
                         const float* __restrict__ x, const float* __restrict__ h0,
                         const float* __restrict__ Wout) {
    size_t idx = (size_t)blockIdx.x * blockDim.x + threadIdx.x;
    if (idx < (size_t)G4 * HD) {
        int np = (int)(idx >> 9), k = (int)(idx & 511);
        int j = np >> 2, g = np & 3;
        int row = g * HD + j;
        float wh = Whh[row * HD + k];
        __half h1 = __float2half(wh);
        g_Whh_hi[idx] = h1;
        g_Whh_lo[idx] = __float2half(wh - __half2float(h1));
        float wi = Wih[row * (HD + 1) + 1 + k];
        __half i1 = __float2half(wi);
        g_Wih_hi[idx] = i1;
        g_Wih_lo[idx] = __float2half(wi - __half2float(i1));
        if (k == 0) {
            g_wflag[np] = Wih[row * (HD + 1)];
            g_bias [np] = bih[row] + bhh[row];
        }
    }
    if (idx < (size_t)BD * HD) {
        float v = x[idx];
        __half hv = __float2half(v);
        g_x_hi[idx] = hv;
        g_x_lo[idx] = __float2half(v - __half2float(hv));
        float h = h0[idx];
        __half hh = __float2half(h);
        g_h_hi[0][idx] = hh;
        g_h_lo[0][idx] = __float2half(h - __half2float(hh));
    }
    if (idx < (size_t)HD * HD) {
        float w = Wout[idx];
        __half wh = __float2half(w);
        g_Wout_hi[idx] = wh;
        g_Wout_lo[idx] = __float2half(w - __half2float(wh));
    }
    if (idx < BD) { g_cum[idx] = 0.f; g_list[0][idx] = (int)idx; }
    if (idx < NS) g_arrive[idx] = 0;
    if (idx < NS + 1) g_mact[idx] = (idx == 0) ? BD : 0;
    if (idx < 2 * NS) g_bar[idx] = 0;
}

// ======================= mma.sync GEMM + fused epilogue (M=128 x N=128) =======================
// MODE 0: Cout = acc + bias (dense)
// MODE 1: LSTM gate epilogue over ACTIVE rows; also writes per-nblock halt partials
template <int MODE>
__global__ void __launch_bounds__(256, 2)
mma_gemm(const __half* __restrict__ Ahi, const __half* __restrict__ Alo,
         const __half* __restrict__ Bhi, const __half* __restrict__ Blo,
         int Ntot, const float* __restrict__ bias, float* __restrict__ Cout,
         const float* __restrict__ xb, const float* __restrict__ wflag, int sidx,
         const float* __restrict__ c_in, float* __restrict__ h_out, float* __restrict__ c_out,
         __half* __restrict__ hhi_out, __half* __restrict__ hlo_out,
         const int* __restrict__ list, const float* __restrict__ Whalt)
{
    extern __shared__ char dsm[];
    __shared__ int ridx_s[128];

    const int tid  = threadIdx.x;
    const int wid  = tid >> 5;
    const int lane = tid & 31;
    const int m0 = blockIdx.y * 128;
    const int n0 = blockIdx.x * 128;
    const int wm = (wid & 3) * 32;
    const int wn = (wid >> 2) * 64;

    if (MODE == 1) {
        const int mact = g_mact[sidx];
        if (m0 >= mact) return;
        if (tid < 128) {
            int g = m0 + tid;
            ridx_s[tid] = list[g < mact ? g : mact - 1];
        }
        __syncthreads();
    }

    const uint32_t sbase = smem_u32(dsm);

    float acc[2][8][4];
#pragma unroll
    for (int a = 0; a < 2; a++)
#pragma unroll
        for (int b = 0; b < 8; b++)
#pragma unroll
            for (int q = 0; q < 4; q++) acc[a][b][q] = 0.f;

    auto load_stage = [&](int kc, int s) {
        uint32_t st = sbase + s * STAGE_BYTES;
#pragma unroll
        for (int i = 0; i < 2; i++) {
            int cid = tid + i * 256;
            int row = cid >> 2, c = cid & 3;
            uint32_t off = row * 64 + ((c ^ ((row >> 1) & 3)) << 4);
            int arow = (MODE == 1) ? ridx_s[row] : (m0 + row);
            size_t ga = (size_t)arow * 512 + kc * 32 + c * 8;
            size_t gb = (size_t)(n0 + row) * 512 + kc * 32 + c * 8;
            cpa16(st + off,                  Ahi + ga);
            cpa16(st + TILE_BYTES + off,     Alo + ga);
            cpa16(st + 2 * TILE_BYTES + off, Bhi + gb);
            cpa16(st + 3 * TILE_BYTES + off, Blo + gb);
        }
        cpa_commit();
    };

    auto compute = [&](int s) {
        uint32_t st = sbase + s * STAGE_BYTES;
#pragma unroll
        for (int k16 = 0; k16 < 2; k16++) {
            uint32_t ahi[2][4], alo[2][4];
#pragma unroll
            for (int mt = 0; mt < 2; mt++) {
                int row = wm + mt * 16 + (lane & 7) + ((lane >> 3) & 1) * 8;
                int ch  = k16 * 2 + (lane >> 4);
                uint32_t off = row * 64 + ((ch ^ ((row >> 1) & 3)) << 4);
                ldsm4(ahi[mt], st + off);
                ldsm4(alo[mt], st + TILE_BYTES + off);
            }
#pragma unroll
            for (int ng = 0; ng < 4; ng++) {
                uint32_t bh[4], bl[4];
                int row = wn + ng * 16 + (lane & 7) + ((lane >> 4) & 1) * 8;
                int ch  = k16 * 2 + ((lane >> 3) & 1);
                uint32_t off = row * 64 + ((ch ^ ((row >> 1) & 3)) << 4);
                ldsm4(bh, st + 2 * TILE_BYTES + off);
                ldsm4(bl, st + 3 * TILE_BYTES + off);
#pragma unroll
                for (int mt = 0; mt < 2; mt++)
#pragma unroll
                    for (int nf = 0; nf < 2; nf++)
                        mma16816(acc[mt][ng * 2 + nf], ahi[mt], &bh[nf * 2]);
#pragma unroll
                for (int mt = 0; mt < 2; mt++)
#pragma unroll
                    for (int nf = 0; nf < 2; nf++)
                        mma16816(acc[mt][ng * 2 + nf], ahi[mt], &bl[nf * 2]);
#pragma unroll
                for (int mt = 0; mt < 2; mt++)
#pragma unroll
                    for (int nf = 0; nf < 2; nf++)
                        mma16816(acc[mt][ng * 2 + nf], alo[mt], &bh[nf * 2]);
            }
        }
    };

    load_stage(0, 0);
    load_stage(1, 1);
    for (int kc = 0; kc < 16; kc++) {
        cpa_wait<1>();
        __syncthreads();
        if (kc + 2 < 16) load_stage(kc + 2, (kc + 2) % NSTAGE);
        compute(kc % NSTAGE);
    }
    __syncthreads();

    float* Cs = (float*)dsm;
#pragma unroll
    for (int mt = 0; mt < 2; mt++)
#pragma unroll
        for (int nf = 0; nf < 8; nf++) {
            int row = wm + mt * 16 + (lane >> 2);
            int col = wn + nf * 8 + (lane & 3) * 2;
            Cs[row * CSTRIDE + col]           = acc[mt][nf][0];
            Cs[row * CSTRIDE + col + 1]       = acc[mt][nf][1];
            Cs[(row + 8) * CSTRIDE + col]     = acc[mt][nf][2];
            Cs[(row + 8) * CSTRIDE + col + 1] = acc[mt][nf][3];
        }
    __syncthreads();

    const int ml = tid >> 1;
    const int colbase = (tid & 1) * 64;

    if (MODE == 0) {
        const int m = m0 + ml;
#pragma unroll
        for (int q = 0; q < 16; q++) {
            int ncol = colbase + q * 4;
            float4 v  = *(float4*)&Cs[ml * CSTRIDE + ncol];
            float4 bv = *(const float4*)&bias[n0 + ncol];
            v.x += bv.x; v.y += bv.y; v.z += bv.z; v.w += bv.w;
            *(float4*)&Cout[(size_t)m * Ntot + n0 + ncol] = v;
        }
    } else {
        const int m = ridx_s[ml];
        const int j0 = (n0 + colbase) >> 2;
        const int step0 = (sidx == 0);
        float cold[16];
#pragma unroll
        for (int q = 0; q < 16; q += 4) {
            float4 cv = *(const float4*)&c_in[(size_t)m * HD + j0 + q];
            cold[q] = cv.x; cold[q + 1] = cv.y; cold[q + 2] = cv.z; cold[q + 3] = cv.w;
        }
        float hbuf[16], cbuf[16];
#pragma unroll
        for (int q = 0; q < 16; q++) {
            int ncol = colbase + q * 4;
            float4 a  = *(float4*)&Cs[ml * CSTRIDE + ncol];
            float4 xv = *(const float4*)&xb[(size_t)m * G4 + n0 + ncol];
            float gi = a.x + xv.x, gf = a.y + xv.y, gg = a.z + xv.z, go = a.w + xv.w;
            if (step0) {
                float4 wf = *(const float4*)&wflag[n0 + ncol];
                gi += wf.x; gf += wf.y; gg += wf.z; go += wf.w;
            }
            float cn = sigf(gf) * cold[q] + sigf(gi) * tanh_acc(gg);
            float hn = sigf(go) * tanh_acc(cn);
            hbuf[q] = hn; cbuf[q] = cn;
        }
#pragma unroll
        for (int q = 0; q < 16; q += 4) {
            *(float4*)&h_out[(size_t)m * HD + j0 + q] = make_float4(hbuf[q], hbuf[q+1], hbuf[q+2], hbuf[q+3]);
            *(float4*)&c_out[(size_t)m * HD + j0 + q] = make_float4(cbuf[q], cbuf[q+1], cbuf[q+2], cbuf[q+3]);
        }
        __half hh[16], hl[16];
#pragma unroll
        for (int q = 0; q < 16; q++) {
            hh[q] = __float2half(hbuf[q]);
            hl[q] = __float2half(hbuf[q] - __half2float(hh[q]));
        }
        *(uint4*)&hhi_out[(size_t)m * HD + j0]     = *(uint4*)&hh[0];
        *(uint4*)&hhi_out[(size_t)m * HD + j0 + 8] = *(uint4*)&hh[8];
        *(uint4*)&hlo_out[(size_t)m * HD + j0]     = *(uint4*)&hl[0];
        *(uint4*)&hlo_out[(size_t)m * HD + j0 + 8] = *(uint4*)&hl[8];

        // ---- halt partial: 16 FMAs from registers + 1 shuffle + 1 store ----
        float hp = 0.f;
#pragma unroll
        for (int q = 0; q < 16; q++) hp += hbuf[q] * Whalt[j0 + q];
        hp += __shfl_xor_sync(0xffffffffu, hp, 1);   // pair covers this nblock's 32 units
        if ((tid & 1) == 0) g_part[(size_t)m * NB + blockIdx.x] = hp;
    }
}

// ======================= M=64 x N=128 GEMM + bias (out-GEMM) =======================
__global__ void __launch_bounds__(256, 2)
gemm_n64(const __half* __restrict__ Ahi, const __half* __restrict__ Alo,
         const __half* __restrict__ Bhi, const __half* __restrict__ Blo,
         int Ntot, const float* __restrict__ bias, float* __restrict__ Cout)
{
    extern __shared__ char dsm[];
    const int tid  = threadIdx.x;
    const int wid  = tid >> 5;
    const int lane = tid & 31;
    const int m0 = blockIdx.y * 64;
    const int n0 = blockIdx.x * 128;
    const int wm = (wid & 1) * 32;
    const int wn = (wid >> 1) * 32;
    const uint32_t sbase = smem_u32(dsm);

    float acc[2][4][4];
#pragma unroll
    for (int a = 0; a < 2; a++)
#pragma unroll
        for (int b = 0; b < 4; b++)
#pragma unroll
            for (int q = 0; q < 4; q++) acc[a][b][q] = 0.f;

    auto load_stage = [&](int kc, int s) {
        uint32_t st = sbase + s * S64_BYTES;
        {
            int row = tid >> 2, c = tid & 3;
            uint32_t off = row * 64 + ((c ^ ((row >> 1) & 3)) << 4);
            size_t ga = (size_t)(m0 + row) * 512 + kc * 32 + c * 8;
            cpa16(st + off,           Ahi + ga);
            cpa16(st + S64_ALO + off, Alo + ga);
        }
#pragma unroll
        for (int i = 0; i < 2; i++) {
            int cid = tid + i * 256;
            int row = cid >> 2, c = cid & 3;
            uint32_t off = row * 64 + ((c ^ ((row >> 1) & 3)) << 4);
            size_t gb = (size_t)(n0 + row) * 512 + kc * 32 + c * 8;
            cpa16(st + S64_BHI + off, Bhi + gb);
            cpa16(st + S64_BLO + off, Blo + gb);
        }
        cpa_commit();
    };

    auto compute = [&](int s) {
        uint32_t st = sbase + s * S64_BYTES;
#pragma unroll
        for (int k16 = 0; k16 < 2; k16++) {
            uint32_t ahi[2][4], alo[2][4];
#pragma unroll
            for (int mt = 0; mt < 2; mt++) {
                int row = wm + mt * 16 + (lane & 7) + ((lane >> 3) & 1) * 8;
                int ch  = k16 * 2 + (lane >> 4);
                uint32_t off = row * 64 + ((ch ^ ((row >> 1) & 3)) << 4);
                ldsm4(ahi[mt], st + off);
                ldsm4(alo[mt], st + S64_ALO + off);
            }
#pragma unroll
            for (int ng = 0; ng < 2; ng++) {
                uint32_t bh[4], bl[4];
                int row = wn + ng * 16 + (lane & 7) + ((lane >> 4) & 1) * 8;
                int ch  = k16 * 2 + ((lane >> 3) & 1);
                uint32_t off = row * 64 + ((ch ^ ((row >> 1) & 3)) << 4);
                ldsm4(bh, st + S64_BHI + off);
                ldsm4(bl, st + S64_BLO + off);
#pragma unroll
                for (int mt = 0; mt < 2; mt++)
#pragma unroll
                    for (int nf = 0; nf < 2; nf++)
                        mma16816(acc[mt][ng * 2 + nf], ahi[mt], &bh[nf * 2]);
#pragma unroll
                for (int mt = 0; mt < 2; mt++)
#pragma unroll
                    for (int nf = 0; nf < 2; nf++)
                        mma16816(acc[mt][ng * 2 + nf], ahi[mt], &bl[nf * 2]);
#pragma unroll
                for (int mt = 0; mt < 2; mt++)
#pragma unroll
                    for (int nf = 0; nf < 2; nf++)
                        mma16816(acc[mt][ng * 2 + nf], alo[mt], &bh[nf * 2]);
            }
        }
    };

    load_stage(0, 0);
    load_stage(1, 1);
    for (int kc = 0; kc < 16; kc++) {
        cpa_wait<1>();
        __syncthreads();
        if (kc + 2 < 16) load_stage(kc + 2, (kc + 2) % NSTAGE);
        compute(kc % NSTAGE);
    }
    __syncthreads();

    float* Cs = (float*)dsm;
#pragma unroll
    for (int mt = 0; mt < 2; mt++)
#pragma unroll
        for (int nf = 0; nf < 4; nf++) {
            int row = wm + mt * 16 + (lane >> 2);
            int col = wn + nf * 8 + (lane & 3) * 2;
            Cs[row * CSTRIDE + col]           = acc[mt][nf][0];
            Cs[row * CSTRIDE + col + 1]       = acc[mt][nf][1];
            Cs[(row + 8) * CSTRIDE + col]     = acc[mt][nf][2];
            Cs[(row + 8) * CSTRIDE + col + 1] = acc[mt][nf][3];
        }
    __syncthreads();

    const int ml = tid >> 2;
    const int colbase = (tid & 3) * 32;
    const int m = m0 + ml;
#pragma unroll
    for (int q = 0; q < 8; q++) {
        int ncol = colbase + q * 4;
        float4 v  = *(float4*)&Cs[ml * CSTRIDE + ncol];
        float4 bv = *(const float4*)&bias[n0 + ncol];
        v.x += bv.x; v.y += bv.y; v.z += bv.z; v.w += bv.w;
        *(float4*)&Cout[(size_t)m * Ntot + n0 + ncol] = v;
    }
}

// ============ halt + compact: reads precomputed partials (256KB, not 8MB) ============
__global__ void halt_compact(int n, const float* __restrict__ bhalt)
{
    __shared__ int s_cnt[NCB];
    __shared__ int s_off[NCB];
    __shared__ int s_last;

    const int tid = threadIdx.x;   // 128 threads
    const int b = blockIdx.x;

    const int mact = g_mact[n];
    if (mact == 0) {
        if (b == 0 && tid == 0) g_mact[n + 1] = 0;
        return;
    }
    const int* list = g_list[n & 1];
    const float thresh = 1.0f - 0.01f;

    // warp 0: one thread per list position (32 per block)
    if (tid < 32) {
        int i = b * 32 + tid;
        int flag = 0, m = -1;
        if (i < mact) {
            m = list[i];
            const float4* pp = (const float4*)&g_part[(size_t)m * NB];
            float4 p0 = pp[0], p1 = pp[1], p2 = pp[2], p3 = pp[3];
            float d = ((p0.x + p0.y) + (p0.z + p0.w)) + ((p1.x + p1.y) + (p1.z + p1.w))
                    + ((p2.x + p2.y) + (p2.z + p2.w)) + ((p3.x + p3.y) + (p3.z + p3.w));
            float halt = sigf(d + bhalt[0]);
            float cum = g_cum[m] + halt;
            g_cum[m] = cum;
            g_halt[n * BD + m] = halt;
            flag = (cum < thresh) ? 1 : 0;
        }
        unsigned mask = __ballot_sync(0xffffffffu, flag);
        int pre = __popc(mask & ((1u << tid) - 1u));
        if (flag) g_seg[b * 32 + pre] = m;
        if (tid == 0) g_bcnt[b] = __popc(mask);
    }
    __syncthreads();

    if (tid == 0) {
        __threadfence();
        int old = atomicAdd(&g_arrive[n], 1);
        s_last = (old == (int)gridDim.x - 1) ? 1 : 0;
    }
    __syncthreads();

    if (s_last) {
        if (tid < NCB) s_cnt[tid] = __ldcg(&g_bcnt[tid]);
        __syncthreads();
        if (tid == 0) {
            int off = 0;
#pragma unroll 8
            for (int s2 = 0; s2 < NCB; s2++) { s_off[s2] = off; off += s_cnt[s2]; }
            g_mact[n + 1] = off;
        }
        __syncthreads();
        int* outl = g_list[(n + 1) & 1];
        if (tid < NCB) {
            int c = s_cnt[tid], o = s_off[tid];
            for (int i = 0; i < c; i++)
                outl[o + i] = __ldcg(&g_seg[tid * 32 + i]);
        }
    }
}

// ============ persistent tail: steps TAIL0..15 (fp32 SIMT straggler path) ============
__device__ __forceinline__ void tail_barrier(int idx) {
    __threadfence();
    __syncthreads();
    if (threadIdx.x == 0) {
        atomicAdd(&g_bar[idx], 1);
        while (*(volatile int*)&g_bar[idx] < (int)gridDim.x) { }
    }
    __syncthreads();
}

__global__ void __launch_bounds__(256, 1)
act_tail(const float* __restrict__ Whalt, const float* __restrict__ bhalt)
{
    if (*(volatile int*)&g_mact[TAIL0] == 0) return;

    extern __shared__ char dsm[];
    float* Ws   = (float*)(dsm + TS_WS);
    float* hs_s = (float*)(dsm + TS_HS);
    float* gsum = (float*)(dsm + TS_GS);
    int*   m_s  = (int*)  (dsm + TS_MS);
    char*  flg  = (char*) (dsm + TS_FLAG);

    const int tid = threadIdx.x;
    const int wid = tid >> 5;
    const int lane = tid & 31;
    const int b = blockIdx.x;
    const size_t HBUF = (size_t)BD * HD;
    const int np0 = b * 16;

    for (int idx = tid; idx < 16 * 512; idx += 256) {
        int col = idx >> 9, k = idx & 511;
        size_t o = (size_t)(np0 + col) * 512 + k;
        Ws[col * 516 + k] = __half2float(g_Whh_hi[o]) + __half2float(g_Whh_lo[o]);
    }
    __syncthreads();

    for (int n = TAIL0; n < NS; n++) {
        const int mact = *(volatile int*)&g_mact[n];
        if (mact == 0) break;
        const int* list = g_list[n & 1];
        const float* hprev = g_hs + (size_t)(n - 1) * HBUF;
        const float* cprev = g_cs + (size_t)(n - 1) * HBUF;
        float* hout = g_hs + (size_t)n * HBUF;
        float* cout = g_cs + (size_t)n * HBUF;

        for (int rc = 0; rc < mact; rc += 16) {
            for (int rr = wid; rr < 16; rr += 8) {
                int i = rc + rr;
                if (i < mact) {
                    int m = __ldcg(&list[i]);
                    if (lane == 0) m_s[rr] = m;
                    const float4* src = (const float4*)(hprev + (size_t)m * HD);
                    float4* dst = (float4*)(hs_s + rr * 512);
                    for (int q = lane; q < 128; q += 32) dst[q] = src[q];
                }
            }
            __syncthreads();
            const int col = tid & 15, rg = tid >> 4;
            if (rc + rg < mact) {
                const float4* hv = (const float4*)(hs_s + rg * 512);
                const float4* wv = (const float4*)(Ws + col * 516);
                float d = 0.f;
                for (int q = 0; q < 128; q++) {
                    float4 a = hv[q], w = wv[q];
                    d += a.x * w.x + a.y * w.y + a.z * w.z + a.w * w.w;
                }
                gsum[rg * 16 + col] = d + g_xb[(size_t)m_s[rg] * G4 + np0 + col];
            }
            __syncthreads();
            if (tid < 64) {
                int rg2 = tid >> 2, jj = tid & 3;
                if (rc + rg2 < mact) {
                    int m = m_s[rg2];
                    float gi = gsum[rg2 * 16 + jj * 4 + 0];
                    float gf = gsum[rg2 * 16 + jj * 4 + 1];
                    float gg = gsum[rg2 * 16 + jj * 4 + 2];
                    float go = gsum[rg2 * 16 + jj * 4 + 3];
                    int j = (np0 >> 2) + jj;
                    float co = cprev[(size_t)m * HD + j];
                    float cn = sigf(gf) * co + sigf(gi) * tanh_acc(gg);
                    float hn = sigf(go) * tanh_acc(cn);
                    hout[(size_t)m * HD + j] = hn;
                    cout[(size_t)m * HD + j] = cn;
                }
            }
            __syncthreads();
        }

        tail_barrier(2 * n);

        if (b == 0) {
            const float4* w4 = (const float4*)Whalt;
            for (int i = wid; i < mact; i += 8) {
                int m = __ldcg(&list[i]);
                const float4* h4 = (const float4*)(hout + (size_t)m * HD);
                float sdot = 0.f;
#pragma unroll
                for (int it = 0; it < 4; it++) {
                    float4 a = h4[lane + it * 32];
                    float4 w = w4[lane + it * 32];
                    sdot += a.x * w.x + a.y * w.y + a.z * w.z + a.w * w.w;
                }
#pragma unroll
                for (int off = 16; off; off >>= 1) sdot += __shfl_xor_sync(0xffffffffu, sdot, off);
                if (lane == 0) {
                    float halt = sigf(sdot + bhalt[0]);
                    float cum = g_cum[m] + halt;
                    g_cum[m] = cum;
                    g_halt[n * BD + m] = halt;
                    flg[i] = (cum < 1.0f - 0.01f) ? 1 : 0;
                }
            }
            __syncthreads();
            if (wid == 0) {
                int* outl = g_list[(n + 1) & 1];
                int pos = 0;
                for (int c2 = 0; c2 < mact; c2 += 32) {
                    int i2 = c2 + lane;
                    int f = (i2 < mact) ? flg[i2] : 0;
                    unsigned msk = __ballot_sync(0xffffffffu, f);
                    if (f) outl[pos + __popc(msk & ((1u << lane) - 1u))] = __ldcg(&list[i2]);
                    pos += __popc(msk);
                }
                if (lane == 0) g_mact[n + 1] = pos;
            }
        }
        tail_barrier(2 * n + 1);
    }
}

// ======= pfin: halting scan + weighted reduce + fp16 split =======
__global__ void pfin(float* __restrict__ hfin, float* __restrict__ cfin,
                     float* __restrict__ ponder_out)
{
    int m = blockIdx.x;
    int j = threadIdx.x;
    __shared__ float ps[NS];
    if (j == 0) {
        const float thresh = 1.0f - 0.01f;
        float halts[NS];
        float cum = 0.f; int nh = NS - 1; bool found = false;
#pragma unroll
        for (int n = 0; n < NS; n++) {
            halts[n] = g_halt[n * BD + m];
            cum += halts[n];
            if (!found && cum >= thresh) { nh = n; found = true; }
        }
        float s = 0.f;
#pragma unroll
        for (int n = 0; n < NS; n++) {
            float p = (n < nh) ? halts[n] : 0.f;
            if (n < nh) s += p;
            ps[n] = p;
        }
        float r = 1.f - s;
        ps[nh] = r;
        ponder_out[m] = (float)nh + 1.f + r;
    }
    __syncthreads();
    float ah = 0.f, ac = 0.f;
#pragma unroll
    for (int n = 0; n < NS; n++) {
        float p = ps[n];
        if (p != 0.f) {
            size_t o = ((size_t)n * BD + m) * HD + j;
            ah += p * g_hs[o];
            ac += p * g_cs[o];
        }
    }
    hfin[(size_t)m * HD + j] = ah;
    cfin[(size_t)m * HD + j] = ac;
    __half hh = __float2half(ah);
    g_hf_hi[(size_t)m * HD + j] = hh;
    g_hf_lo[(size_t)m * HD + j] = __float2half(ah - __half2float(hh));
}

// ======================= launcher =======================
extern "C" void kernel_launch(void* const* d_in, const int* in_sizes, int n_in,
                              void* d_out, int out_size)
{
    const float* x     = (const float*)d_in[0];
    const float* h0    = (const float*)d_in[1];
    const float* c0    = (const float*)d_in[2];
    const float* Wih   = (const float*)d_in[3];
    const float* bih   = (const float*)d_in[4];
    const float* Whh   = (const float*)d_in[5];
    const float* bhh   = (const float*)d_in[6];
    const float* Whalt = (const float*)d_in[7];
    const float* bhalt = (const float*)d_in[8];
    const float* Wout  = (const float*)d_in[9];
    const float* bout  = (const float*)d_in[10];
    (void)in_sizes; (void)n_in; (void)out_size;

    float* out   = (float*)d_out;
    float* out_y = out;
    float* out_h = out + (size_t)BD * HD;
    float* out_c = out + (size_t)BD * HD * 2;
    float* out_p = out + (size_t)BD * HD * 3;

    cudaFuncSetAttribute(mma_gemm<0>, cudaFuncAttributeMaxDynamicSharedMemorySize, DSMEM_BYTES);
    cudaFuncSetAttribute(mma_gemm<1>, cudaFuncAttributeMaxDynamicSharedMemorySize, DSMEM_BYTES);
    cudaFuncSetAttribute(gemm_n64, cudaFuncAttributeMaxDynamicSharedMemorySize, DSMEM64);
    cudaFuncSetAttribute(act_tail, cudaFuncAttributeMaxDynamicSharedMemorySize, TAIL_SMEM);

    __half *Whh_hi, *Whh_lo, *Wih_hi, *Wih_lo, *Wout_hi, *Wout_lo;
    __half *x_hi, *x_lo, *h_hi, *h_lo, *hf_hi, *hf_lo;
    float *wflag, *biasp, *xb, *hs, *cs;
    int *listb;
    cudaGetSymbolAddress((void**)&Whh_hi, g_Whh_hi);
    cudaGetSymbolAddress((void**)&Whh_lo, g_Whh_lo);
    cudaGetSymbolAddress((void**)&Wih_hi, g_Wih_hi);
    cudaGetSymbolAddress((void**)&Wih_lo, g_Wih_lo);
    cudaGetSymbolAddress((void**)&Wout_hi, g_Wout_hi);
    cudaGetSymbolAddress((void**)&Wout_lo, g_Wout_lo);
    cudaGetSymbolAddress((void**)&x_hi, g_x_hi);
    cudaGetSymbolAddress((void**)&x_lo, g_x_lo);
    cudaGetSymbolAddress((void**)&h_hi, g_h_hi);
    cudaGetSymbolAddress((void**)&h_lo, g_h_lo);
    cudaGetSymbolAddress((void**)&hf_hi, g_hf_hi);
    cudaGetSymbolAddress((void**)&hf_lo, g_hf_lo);
    cudaGetSymbolAddress((void**)&wflag, g_wflag);
    cudaGetSymbolAddress((void**)&biasp, g_bias);
    cudaGetSymbolAddress((void**)&xb, g_xb);
    cudaGetSymbolAddress((void**)&hs, g_hs);
    cudaGetSymbolAddress((void**)&cs, g_cs);
    cudaGetSymbolAddress((void**)&listb, g_list);

    const size_t HBUF = (size_t)BD * HD;

    // 1) merged prep
    prep_all<<<(BD * HD + 255) / 256, 256>>>(Wih, Whh, bih, bhh, x, h0, Wout);

    // 2) x-part GEMM
    dim3 gridG(G4 / 128, BD / 128);
    mma_gemm<0><<<gridG, 256, DSMEM_BYTES>>>(x_hi, x_lo, Wih_hi, Wih_lo, G4, biasp, xb,
                                             nullptr, nullptr, -1, nullptr, nullptr, nullptr,
                                             nullptr, nullptr, nullptr, nullptr);

    // 3) steps 0..TAIL0-1: GEMM (writes halt partials from registers) + cheap compact
    for (int n = 0; n < TAIL0; n++) {
        const float* c_i = (n == 0) ? c0 : (cs + (size_t)(n - 1) * HBUF);
        mma_gemm<1><<<gridG, 256, DSMEM_BYTES>>>(
            h_hi + (size_t)(n & 1) * HBUF, h_lo + (size_t)(n & 1) * HBUF,
            Whh_hi, Whh_lo, G4, nullptr, nullptr,
            xb, wflag, n,
            c_i, hs + (size_t)n * HBUF, cs + (size_t)n * HBUF,
            h_hi + (size_t)((n + 1) & 1) * HBUF, h_lo + (size_t)((n + 1) & 1) * HBUF,
            listb + (size_t)(n & 1) * BD, Whalt);
        halt_compact<<<NCB, 128>>>(n, bhalt);
    }

    // 4) persistent straggler tail (typically instant exit)
    act_tail<<<TAILG, 256, TAIL_SMEM>>>(Whalt, bhalt);

    // 5) halting scan + h_fin / c_fin (+ fp16 split)
    pfin<<<BD, HD>>>(out_h, out_c, out_p);

    // 6) output GEMM
    dim3 gridO(HD / 128, BD / 64);
    gemm_n64<<<gridO, 256, DSMEM64>>>(hf_hi, hf_lo, Wout_hi, Wout_lo, HD, bout, out_y);
}

// round 17
// speedup vs baseline: 1.3518x; 1.0300x over previous
#include <cuda_runtime.h>
#include <cuda_fp16.h>
#include <math.h>
#include <stdint.h>

#define BD 4096
#define HD 512
#define G4 2048    // 4*H
#define NS 16
#define NB 16      // n-blocks per step GEMM (G4/128)
#define NCB 128    // compaction blocks (32 list positions each)
#define TAIL0 3    // first step handled by the persistent tail
#define TAILG 128  // tail grid (<= SM count, all resident)

// ======================= device scratch (allocation-free) =======================
__device__ __half g_Whh_hi[G4*HD], g_Whh_lo[G4*HD];     // permuted n'=4j+g, K-major
__device__ __half g_Wih_hi[G4*HD], g_Wih_lo[G4*HD];
__device__ __half g_Wout_hi[HD*HD], g_Wout_lo[HD*HD];
__device__ __half g_x_hi[(size_t)BD*HD], g_x_lo[(size_t)BD*HD];
__device__ __half g_h_hi[2][(size_t)BD*HD], g_h_lo[2][(size_t)BD*HD];
__device__ __half g_hf_hi[(size_t)BD*HD], g_hf_lo[(size_t)BD*HD];
__device__ float g_wflag[G4], g_bias[G4];
__device__ float g_xb[(size_t)BD*G4];
__device__ float g_hs[(size_t)NS*BD*HD];
__device__ float g_cs[(size_t)NS*BD*HD];
// ---- ACT state: active-row compaction ----
__device__ float g_halt[NS*BD];
__device__ float g_cum[BD];
__device__ int   g_list[2][BD];
__device__ int   g_mact[NS+1];
__device__ int   g_seg[BD];
__device__ int   g_bcnt[NCB];
__device__ int   g_arrive[NS];
__device__ int   g_bar[2*NS];
__device__ float g_part[(size_t)BD*NB];   // per-(row, nblock) halt-dot partials

// ======================= helpers =======================
__device__ __forceinline__ float sigf(float x) {
    return __fdividef(1.f, 1.f + __expf(-x));
}
__device__ __forceinline__ float tanh_acc(float x) {
    float ax = fabsf(x);
    float e  = __expf(-2.f * ax);
    float t  = __fdividef(1.f - e, 1.f + e);
    return copysignf(t, x);
}
__device__ __forceinline__ uint32_t smem_u32(const void* p) {
    uint32_t a;
    asm("{ .reg .u64 t; cvta.to.shared.u64 t, %1; cvt.u32.u64 %0, t; }" : "=r"(a) : "l"(p));
    return a;
}
__device__ __forceinline__ void cpa16(uint32_t d, const void* s) {
    asm volatile("cp.async.cg.shared.global [%0], [%1], 16;" :: "r"(d), "l"(s));
}
__device__ __forceinline__ void cpa_commit() { asm volatile("cp.async.commit_group;"); }
template <int N> __device__ __forceinline__ void cpa_wait() {
    asm volatile("cp.async.wait_group %0;" :: "n"(N));
}
__device__ __forceinline__ void ldsm4(uint32_t* r, uint32_t a) {
    asm volatile("ldmatrix.sync.aligned.m8n8.x4.shared.b16 {%0,%1,%2,%3}, [%4];"
        : "=r"(r[0]), "=r"(r[1]), "=r"(r[2]), "=r"(r[3]) : "r"(a));
}
__device__ __forceinline__ void mma16816(float* c, const uint32_t* a, const uint32_t* b) {
    asm volatile("mma.sync.aligned.m16n8k16.row.col.f32.f16.f16.f32 "
        "{%0,%1,%2,%3}, {%4,%5,%6,%7}, {%8,%9}, {%0,%1,%2,%3};"
        : "+f"(c[0]), "+f"(c[1]), "+f"(c[2]), "+f"(c[3])
        : "r"(a[0]), "r"(a[1]), "r"(a[2]), "r"(a[3]), "r"(b[0]), "r"(b[1]));
}

// smem tile layout: rows x 64B (4 x 16B chunks), XOR-swizzled
#define TILE_BYTES 8192
#define STAGE_BYTES 32768
#define NSTAGE 3
#define DSMEM_BYTES (NSTAGE * STAGE_BYTES)   // 96KB
#define CSTRIDE 132
// n64-variant stage layout
#define S64_BYTES 24576
#define S64_ALO 4096
#define S64_BHI 8192
#define S64_BLO 16384
#define DSMEM64 (NSTAGE * S64_BYTES)
// tail smem partition
#define TS_WS    0
#define TS_HS    (16*516*4)
#define TS_GS    (TS_HS + 16*512*4)
#define TS_MS    (TS_GS + 16*16*4)
#define TS_FLAG  (TS_MS + 16*4)
#define TAIL_SMEM (TS_FLAG + BD)

// ======================= merged prep kernel =======================
__global__ void prep_all(const float* __restrict__ Wih, const float* __restrict__ Whh,
                         const float* __restrict__ bih, const float* __restrict__ bhh,
                         const float* __restrict__ x, const float* __restrict__ h0,
                         const float* __restrict__ Wout) {
    size_t idx = (size_t)blockIdx.x * blockDim.x + threadIdx.x;
    if (idx < (size_t)G4 * HD) {
        int np = (int)(idx >> 9), k = (int)(idx & 511);
        int j = np >> 2, g = np & 3;
        int row = g * HD + j;
        float wh = Whh[row * HD + k];
        __half h1 = __float2half(wh);
        g_Whh_hi[idx] = h1;
        g_Whh_lo[idx] = __float2half(wh - __half2float(h1));
        float wi = Wih[row * (HD + 1) + 1 + k];
        __half i1 = __float2half(wi);
        g_Wih_hi[idx] = i1;
        g_Wih_lo[idx] = __float2half(wi - __half2float(i1));
        if (k == 0) {
            g_wflag[np] = Wih[row * (HD + 1)];
            g_bias [np] = bih[row] + bhh[row];
        }
    }
    if (idx < (size_t)BD * HD) {
        float v = x[idx];
        __half hv = __float2half(v);
        g_x_hi[idx] = hv;
        g_x_lo[idx] = __float2half(v - __half2float(hv));
        float h = h0[idx];
        __half hh = __float2half(h);
        g_h_hi[0][idx] = hh;
        g_h_lo[0][idx] = __float2half(h - __half2float(hh));
    }
    if (idx < (size_t)HD * HD) {
        float w = Wout[idx];
        __half wh = __float2half(w);
        g_Wout_hi[idx] = wh;
        g_Wout_lo[idx] = __float2half(w - __half2float(wh));
    }
    if (idx < BD) { g_cum[idx] = 0.f; g_list[0][idx] = (int)idx; }
    if (idx < NS) g_arrive[idx] = 0;
    if (idx < NS + 1) g_mact[idx] = (idx == 0) ? BD : 0;
    if (idx < 2 * NS) g_bar[idx] = 0;
}

// ======================= mma.sync GEMM + fused epilogue (M=128 x N=128) =======================
// MODE 0: Cout = acc + bias (dense)
// MODE 1: LSTM gate epilogue over ACTIVE rows; also writes per-nblock halt partials
template <int MODE>
__global__ void __launch_bounds__(256, 2)
mma_gemm(const __half* __restrict__ Ahi, const __half* __restrict__ Alo,
         const __half* __restrict__ Bhi, const __half* __restrict__ Blo,
         int Ntot, const float* __restrict__ bias, float* __restrict__ Cout,
         const float* __restrict__ xb, const float* __restrict__ wflag, int sidx,
         const float* __restrict__ c_in, float* __restrict__ h_out, float* __restrict__ c_out,
         __half* __restrict__ hhi_out, __half* __restrict__ hlo_out,
         const int* __restrict__ list, const float* __restrict__ Whalt)
{
    extern __shared__ char dsm[];
    __shared__ int ridx_s[128];

    const int tid  = threadIdx.x;
    const int wid  = tid >> 5;
    const int lane = tid & 31;
    const int m0 = blockIdx.y * 128;
    const int n0 = blockIdx.x * 128;
    const int wm = (wid & 3) * 32;
    const int wn = (wid >> 2) * 64;

    if (MODE == 1) {
        const int mact = g_mact[sidx];
        if (m0 >= mact) return;
        if (tid < 128) {
            int g = m0 + tid;
            ridx_s[tid] = list[g < mact ? g : mact - 1];
        }
        __syncthreads();
    }

    const uint32_t sbase = smem_u32(dsm);

    float acc[2][8][4];
#pragma unroll
    for (int a = 0; a < 2; a++)
#pragma unroll
        for (int b = 0; b < 8; b++)
#pragma unroll
            for (int q = 0; q < 4; q++) acc[a][b][q] = 0.f;

    auto load_stage = [&](int kc, int s) {
        uint32_t st = sbase + s * STAGE_BYTES;
#pragma unroll
        for (int i = 0; i < 2; i++) {
            int cid = tid + i * 256;
            int row = cid >> 2, c = cid & 3;
            uint32_t off = row * 64 + ((c ^ ((row >> 1) & 3)) << 4);
            int arow = (MODE == 1) ? ridx_s[row] : (m0 + row);
            size_t ga = (size_t)arow * 512 + kc * 32 + c * 8;
            size_t gb = (size_t)(n0 + row) * 512 + kc * 32 + c * 8;
            cpa16(st + off,                  Ahi + ga);
            cpa16(st + TILE_BYTES + off,     Alo + ga);
            cpa16(st + 2 * TILE_BYTES + off, Bhi + gb);
            cpa16(st + 3 * TILE_BYTES + off, Blo + gb);
        }
        cpa_commit();
    };

    auto compute = [&](int s) {
        uint32_t st = sbase + s * STAGE_BYTES;
#pragma unroll
        for (int k16 = 0; k16 < 2; k16++) {
            uint32_t ahi[2][4], alo[2][4];
#pragma unroll
            for (int mt = 0; mt < 2; mt++) {
                int row = wm + mt * 16 + (lane & 7) + ((lane >> 3) & 1) * 8;
                int ch  = k16 * 2 + (lane >> 4);
                uint32_t off = row * 64 + ((ch ^ ((row >> 1) & 3)) << 4);
                ldsm4(ahi[mt], st + off);
                ldsm4(alo[mt], st + TILE_BYTES + off);
            }
#pragma unroll
            for (int ng = 0; ng < 4; ng++) {
                uint32_t bh[4], bl[4];
                int row = wn + ng * 16 + (lane & 7) + ((lane >> 4) & 1) * 8;
                int ch  = k16 * 2 + ((lane >> 3) & 1);
                uint32_t off = row * 64 + ((ch ^ ((row >> 1) & 3)) << 4);
                ldsm4(bh, st + 2 * TILE_BYTES + off);
                ldsm4(bl, st + 3 * TILE_BYTES + off);
#pragma unroll
                for (int mt = 0; mt < 2; mt++)
#pragma unroll
                    for (int nf = 0; nf < 2; nf++)
                        mma16816(acc[mt][ng * 2 + nf], ahi[mt], &bh[nf * 2]);
#pragma unroll
                for (int mt = 0; mt < 2; mt++)
#pragma unroll
                    for (int nf = 0; nf < 2; nf++)
                        mma16816(acc[mt][ng * 2 + nf], ahi[mt], &bl[nf * 2]);
#pragma unroll
                for (int mt = 0; mt < 2; mt++)
#pragma unroll
                    for (int nf = 0; nf < 2; nf++)
                        mma16816(acc[mt][ng * 2 + nf], alo[mt], &bh[nf * 2]);
            }
        }
    };

    load_stage(0, 0);
    load_stage(1, 1);
    for (int kc = 0; kc < 16; kc++) {
        cpa_wait<1>();
        __syncthreads();
        if (kc + 2 < 16) load_stage(kc + 2, (kc + 2) % NSTAGE);
        compute(kc % NSTAGE);
    }
    __syncthreads();

    float* Cs = (float*)dsm;
#pragma unroll
    for (int mt = 0; mt < 2; mt++)
#pragma unroll
        for (int nf = 0; nf < 8; nf++) {
            int row = wm + mt * 16 + (lane >> 2);
            int col = wn + nf * 8 + (lane & 3) * 2;
            Cs[row * CSTRIDE + col]           = acc[mt][nf][0];
            Cs[row * CSTRIDE + col + 1]       = acc[mt][nf][1];
            Cs[(row + 8) * CSTRIDE + col]     = acc[mt][nf][2];
            Cs[(row + 8) * CSTRIDE + col + 1] = acc[mt][nf][3];
        }
    __syncthreads();

    const int ml = tid >> 1;
    const int colbase = (tid & 1) * 64;

    if (MODE == 0) {
        const int m = m0 + ml;
#pragma unroll
        for (int q = 0; q < 16; q++) {
            int ncol = colbase + q * 4;
            float4 v  = *(float4*)&Cs[ml * CSTRIDE + ncol];
            float4 bv = *(const float4*)&bias[n0 + ncol];
            v.x += bv.x; v.y += bv.y; v.z += bv.z; v.w += bv.w;
            *(float4*)&Cout[(size_t)m * Ntot + n0 + ncol] = v;
        }
    } else {
        const int m = ridx_s[ml];
        const int j0 = (n0 + colbase) >> 2;
        const int step0 = (sidx == 0);
        float cold[16];
#pragma unroll
        for (int q = 0; q < 16; q += 4) {
            float4 cv = *(const float4*)&c_in[(size_t)m * HD + j0 + q];
            cold[q] = cv.x; cold[q + 1] = cv.y; cold[q + 2] = cv.z; cold[q + 3] = cv.w;
        }
        float hbuf[16], cbuf[16];
#pragma unroll
        for (int q = 0; q < 16; q++) {
            int ncol = colbase + q * 4;
            float4 a  = *(float4*)&Cs[ml * CSTRIDE + ncol];
            float4 xv = *(const float4*)&xb[(size_t)m * G4 + n0 + ncol];
            float gi = a.x + xv.x, gf = a.y + xv.y, gg = a.z + xv.z, go = a.w + xv.w;
            if (step0) {
                float4 wf = *(const float4*)&wflag[n0 + ncol];
                gi += wf.x; gf += wf.y; gg += wf.z; go += wf.w;
            }
            float cn = sigf(gf) * cold[q] + sigf(gi) * tanh_acc(gg);
            float hn = sigf(go) * tanh_acc(cn);
            hbuf[q] = hn; cbuf[q] = cn;
        }
#pragma unroll
        for (int q = 0; q < 16; q += 4) {
            *(float4*)&h_out[(size_t)m * HD + j0 + q] = make_float4(hbuf[q], hbuf[q+1], hbuf[q+2], hbuf[q+3]);
            *(float4*)&c_out[(size_t)m * HD + j0 + q] = make_float4(cbuf[q], cbuf[q+1], cbuf[q+2], cbuf[q+3]);
        }
        __half hh[16], hl[16];
#pragma unroll
        for (int q = 0; q < 16; q++) {
            hh[q] = __float2half(hbuf[q]);
            hl[q] = __float2half(hbuf[q] - __half2float(hh[q]));
        }
        *(uint4*)&hhi_out[(size_t)m * HD + j0]     = *(uint4*)&hh[0];
        *(uint4*)&hhi_out[(size_t)m * HD + j0 + 8] = *(uint4*)&hh[8];
        *(uint4*)&hlo_out[(size_t)m * HD + j0]     = *(uint4*)&hl[0];
        *(uint4*)&hlo_out[(size_t)m * HD + j0 + 8] = *(uint4*)&hl[8];

        // ---- halt partial: 16 FMAs from registers + 1 shuffle + 1 store ----
        float hp = 0.f;
#pragma unroll
        for (int q = 0; q < 16; q++) hp += hbuf[q] * Whalt[j0 + q];
        hp += __shfl_xor_sync(0xffffffffu, hp, 1);
        if ((tid & 1) == 0) g_part[(size_t)m * NB + blockIdx.x] = hp;
    }
}

// ======================= M=64 x N=128 GEMM + bias (out-GEMM) =======================
__global__ void __launch_bounds__(256, 2)
gemm_n64(const __half* __restrict__ Ahi, const __half* __restrict__ Alo,
         const __half* __restrict__ Bhi, const __half* __restrict__ Blo,
         int Ntot, const float* __restrict__ bias, float* __restrict__ Cout)
{
    extern __shared__ char dsm[];
    const int tid  = threadIdx.x;
    const int wid  = tid >> 5;
    const int lane = tid & 31;
    const int m0 = blockIdx.y * 64;
    const int n0 = blockIdx.x * 128;
    const int wm = (wid & 1) * 32;
    const int wn = (wid >> 1) * 32;
    const uint32_t sbase = smem_u32(dsm);

    float acc[2][4][4];
#pragma unroll
    for (int a = 0; a < 2; a++)
#pragma unroll
        for (int b = 0; b < 4; b++)
#pragma unroll
            for (int q = 0; q < 4; q++) acc[a][b][q] = 0.f;

    auto load_stage = [&](int kc, int s) {
        uint32_t st = sbase + s * S64_BYTES;
        {
            int row = tid >> 2, c = tid & 3;
            uint32_t off = row * 64 + ((c ^ ((row >> 1) & 3)) << 4);
            size_t ga = (size_t)(m0 + row) * 512 + kc * 32 + c * 8;
            cpa16(st + off,           Ahi + ga);
            cpa16(st + S64_ALO + off, Alo + ga);
        }
#pragma unroll
        for (int i = 0; i < 2; i++) {
            int cid = tid + i * 256;
            int row = cid >> 2, c = cid & 3;
            uint32_t off = row * 64 + ((c ^ ((row >> 1) & 3)) << 4);
            size_t gb = (size_t)(n0 + row) * 512 + kc * 32 + c * 8;
            cpa16(st + S64_BHI + off, Bhi + gb);
            cpa16(st + S64_BLO + off, Blo + gb);
        }
        cpa_commit();
    };

    auto compute = [&](int s) {
        uint32_t st = sbase + s * S64_BYTES;
#pragma unroll
        for (int k16 = 0; k16 < 2; k16++) {
            uint32_t ahi[2][4], alo[2][4];
#pragma unroll
            for (int mt = 0; mt < 2; mt++) {
                int row = wm + mt * 16 + (lane & 7) + ((lane >> 3) & 1) * 8;
                int ch  = k16 * 2 + (lane >> 4);
                uint32_t off = row * 64 + ((ch ^ ((row >> 1) & 3)) << 4);
                ldsm4(ahi[mt], st + off);
                ldsm4(alo[mt], st + S64_ALO + off);
            }
#pragma unroll
            for (int ng = 0; ng < 2; ng++) {
                uint32_t bh[4], bl[4];
                int row = wn + ng * 16 + (lane & 7) + ((lane >> 4) & 1) * 8;
                int ch  = k16 * 2 + ((lane >> 3) & 1);
                uint32_t off = row * 64 + ((ch ^ ((row >> 1) & 3)) << 4);
                ldsm4(bh, st + S64_BHI + off);
                ldsm4(bl, st + S64_BLO + off);
#pragma unroll
                for (int mt = 0; mt < 2; mt++)
#pragma unroll
                    for (int nf = 0; nf < 2; nf++)
                        mma16816(acc[mt][ng * 2 + nf], ahi[mt], &bh[nf * 2]);
#pragma unroll
                for (int mt = 0; mt < 2; mt++)
#pragma unroll
                    for (int nf = 0; nf < 2; nf++)
                        mma16816(acc[mt][ng * 2 + nf], ahi[mt], &bl[nf * 2]);
#pragma unroll
                for (int mt = 0; mt < 2; mt++)
#pragma unroll
                    for (int nf = 0; nf < 2; nf++)
                        mma16816(acc[mt][ng * 2 + nf], alo[mt], &bh[nf * 2]);
            }
        }
    };

    load_stage(0, 0);
    load_stage(1, 1);
    for (int kc = 0; kc < 16; kc++) {
        cpa_wait<1>();
        __syncthreads();
        if (kc + 2 < 16) load_stage(kc + 2, (kc + 2) % NSTAGE);
        compute(kc % NSTAGE);
    }
    __syncthreads();

    float* Cs = (float*)dsm;
#pragma unroll
    for (int mt = 0; mt < 2; mt++)
#pragma unroll
        for (int nf = 0; nf < 4; nf++) {
            int row = wm + mt * 16 + (lane >> 2);
            int col = wn + nf * 8 + (lane & 3) * 2;
            Cs[row * CSTRIDE + col]           = acc[mt][nf][0];
            Cs[row * CSTRIDE + col + 1]       = acc[mt][nf][1];
            Cs[(row + 8) * CSTRIDE + col]     = acc[mt][nf][2];
            Cs[(row + 8) * CSTRIDE + col + 1] = acc[mt][nf][3];
        }
    __syncthreads();

    const int ml = tid >> 2;
    const int colbase = (tid & 3) * 32;
    const int m = m0 + ml;
#pragma unroll
    for (int q = 0; q < 8; q++) {
        int ncol = colbase + q * 4;
        float4 v  = *(float4*)&Cs[ml * CSTRIDE + ncol];
        float4 bv = *(const float4*)&bias[n0 + ncol];
        v.x += bv.x; v.y += bv.y; v.z += bv.z; v.w += bv.w;
        *(float4*)&Cout[(size_t)m * Ntot + n0 + ncol] = v;
    }
}

// ============ halt + compact: partials-based, latency-parallel stitch ============
__global__ void halt_compact(int n, const float* __restrict__ bhalt)
{
    __shared__ int s_cnt[NCB];
    __shared__ int s_pfx[NCB + 1];     // exclusive prefix
    __shared__ int s_last;

    const int tid = threadIdx.x;   // 256 threads
    const int b = blockIdx.x;

    const int mact = g_mact[n];
    if (mact == 0) {
        if (b == 0 && tid == 0) g_mact[n + 1] = 0;
        return;
    }
    const int* list = g_list[n & 1];
    const float thresh = 1.0f - 0.01f;

    // warp 0: one thread per list position (32 per block)
    if (tid < 32) {
        int i = b * 32 + tid;
        int flag = 0, m = -1;
        if (i < mact) {
            m = list[i];
            const float4* pp = (const float4*)&g_part[(size_t)m * NB];
            float4 p0 = pp[0], p1 = pp[1], p2 = pp[2], p3 = pp[3];
            float d = ((p0.x + p0.y) + (p0.z + p0.w)) + ((p1.x + p1.y) + (p1.z + p1.w))
                    + ((p2.x + p2.y) + (p2.z + p2.w)) + ((p3.x + p3.y) + (p3.z + p3.w));
            float halt = sigf(d + bhalt[0]);
            float cum = g_cum[m] + halt;
            g_cum[m] = cum;
            g_halt[n * BD + m] = halt;
            flag = (cum < thresh) ? 1 : 0;
        }
        unsigned mask = __ballot_sync(0xffffffffu, flag);
        int pre = __popc(mask & ((1u << tid) - 1u));
        if (flag) g_seg[b * 32 + pre] = m;
        if (tid == 0) g_bcnt[b] = __popc(mask);
    }
    __syncthreads();

    if (tid == 0) {
        __threadfence();
        int old = atomicAdd(&g_arrive[n], 1);
        s_last = (old == (int)gridDim.x - 1) ? 1 : 0;
    }
    __syncthreads();

    if (s_last) {
        // parallel count load
        if (tid < NCB) s_cnt[tid] = __ldcg(&g_bcnt[tid]);
        __syncthreads();
        // Hillis-Steele inclusive scan over 128 counts -> exclusive prefix
        if (tid < NCB) s_pfx[tid + 1] = s_cnt[tid];
        if (tid == 0) s_pfx[0] = 0;
        __syncthreads();
#pragma unroll
        for (int d2 = 1; d2 < NCB; d2 <<= 1) {
            int v = 0;
            if (tid < NCB && tid + 1 > d2) v = s_pfx[tid + 1 - d2];
            __syncthreads();
            if (tid < NCB) s_pfx[tid + 1] += v;
            __syncthreads();
        }
        const int total = s_pfx[NCB];
        if (tid == 0) g_mact[n + 1] = total;

        // latency-parallel gather by OUTPUT index: each iteration issues an
        // independent seg load (MLP across the o-loop hides L2 latency)
        int* outl = g_list[(n + 1) & 1];
        for (int o = tid; o < total; o += 256) {
            // binary search largest s with s_pfx[s] <= o
            int lo = 0, hi = NCB;
#pragma unroll
            for (int it = 0; it < 7; it++) {
                int mid = (lo + hi) >> 1;
                if (s_pfx[mid] <= o) lo = mid; else hi = mid;
            }
            outl[o] = __ldcg(&g_seg[lo * 32 + (o - s_pfx[lo])]);
        }
    }
}

// ============ persistent tail: steps TAIL0..15 (fp32 SIMT straggler path) ============
__device__ __forceinline__ void tail_barrier(int idx) {
    __threadfence();
    __syncthreads();
    if (threadIdx.x == 0) {
        atomicAdd(&g_bar[idx], 1);
        while (*(volatile int*)&g_bar[idx] < (int)gridDim.x) { }
    }
    __syncthreads();
}

__global__ void __launch_bounds__(256, 1)
act_tail(const float* __restrict__ Whalt, const float* __restrict__ bhalt)
{
    if (*(volatile int*)&g_mact[TAIL0] == 0) return;

    extern __shared__ char dsm[];
    float* Ws   = (float*)(dsm + TS_WS);
    float* hs_s = (float*)(dsm + TS_HS);
    float* gsum = (float*)(dsm + TS_GS);
    int*   m_s  = (int*)  (dsm + TS_MS);
    char*  flg  = (char*) (dsm + TS_FLAG);

    const int tid = threadIdx.x;
    const int wid = tid >> 5;
    const int lane = tid & 31;
    const int b = blockIdx.x;
    const size_t HBUF = (size_t)BD * HD;
    const int np0 = b * 16;

    for (int idx = tid; idx < 16 * 512; idx += 256) {
        int col = idx >> 9, k = idx & 511;
        size_t o = (size_t)(np0 + col) * 512 + k;
        Ws[col * 516 + k] = __half2float(g_Whh_hi[o]) + __half2float(g_Whh_lo[o]);
    }
    __syncthreads();

    for (int n = TAIL0; n < NS; n++) {
        const int mact = *(volatile int*)&g_mact[n];
        if (mact == 0) break;
        const int* list = g_list[n & 1];
        const float* hprev = g_hs + (size_t)(n - 1) * HBUF;
        const float* cprev = g_cs + (size_t)(n - 1) * HBUF;
        float* hout = g_hs + (size_t)n * HBUF;
        float* cout = g_cs + (size_t)n * HBUF;

        for (int rc = 0; rc < mact; rc += 16) {
            for (int rr = wid; rr < 16; rr += 8) {
                int i = rc + rr;
                if (i < mact) {
                    int m = __ldcg(&list[i]);
                    if (lane == 0) m_s[rr] = m;
                    const float4* src = (const float4*)(hprev + (size_t)m * HD);
                    float4* dst = (float4*)(hs_s + rr * 512);
                    for (int q = lane; q < 128; q += 32) dst[q] = src[q];
                }
            }
            __syncthreads();
            const int col = tid & 15, rg = tid >> 4;
            if (rc + rg < mact) {
                const float4* hv = (const float4*)(hs_s + rg * 512);
                const float4* wv = (const float4*)(Ws + col * 516);
                float d = 0.f;
                for (int q = 0; q < 128; q++) {
                    float4 a = hv[q], w = wv[q];
                    d += a.x * w.x + a.y * w.y + a.z * w.z + a.w * w.w;
                }
                gsum[rg * 16 + col] = d + g_xb[(size_t)m_s[rg] * G4 + np0 + col];
            }
            __syncthreads();
            if (tid < 64) {
                int rg2 = tid >> 2, jj = tid & 3;
                if (rc + rg2 < mact) {
                    int m = m_s[rg2];
                    float gi = gsum[rg2 * 16 + jj * 4 + 0];
                    float gf = gsum[rg2 * 16 + jj * 4 + 1];
                    float gg = gsum[rg2 * 16 + jj * 4 + 2];
                    float go = gsum[rg2 * 16 + jj * 4 + 3];
                    int j = (np0 >> 2) + jj;
                    float co = cprev[(size_t)m * HD + j];
                    float cn = sigf(gf) * co + sigf(gi) * tanh_acc(gg);
                    float hn = sigf(go) * tanh_acc(cn);
                    hout[(size_t)m * HD + j] = hn;
                    cout[(size_t)m * HD + j] = cn;
                }
            }
            __syncthreads();
        }

        tail_barrier(2 * n);

        if (b == 0) {
            const float4* w4 = (const float4*)Whalt;
            for (int i = wid; i < mact; i += 8) {
                int m = __ldcg(&list[i]);
                const float4* h4 = (const float4*)(hout + (size_t)m * HD);
                float sdot = 0.f;
#pragma unroll
                for (int it = 0; it < 4; it++) {
                    float4 a = h4[lane + it * 32];
                    float4 w = w4[lane + it * 32];
                    sdot += a.x * w.x + a.y * w.y + a.z * w.z + a.w * w.w;
                }
#pragma unroll
                for (int off = 16; off; off >>= 1) sdot += __shfl_xor_sync(0xffffffffu, sdot, off);
                if (lane == 0) {
                    float halt = sigf(sdot + bhalt[0]);
                    float cum = g_cum[m] + halt;
                    g_cum[m] = cum;
                    g_halt[n * BD + m] = halt;
                    flg[i] = (cum < 1.0f - 0.01f) ? 1 : 0;
                }
            }
            __syncthreads();
            if (wid == 0) {
                int* outl = g_list[(n + 1) & 1];
                int pos = 0;
                for (int c2 = 0; c2 < mact; c2 += 32) {
                    int i2 = c2 + lane;
                    int f = (i2 < mact) ? flg[i2] : 0;
                    unsigned msk = __ballot_sync(0xffffffffu, f);
                    if (f) outl[pos + __popc(msk & ((1u << lane) - 1u))] = __ldcg(&list[i2]);
                    pos += __popc(msk);
                }
                if (lane == 0) g_mact[n + 1] = pos;
            }
        }
        tail_barrier(2 * n + 1);
    }
}

// ======= pfin: halting scan + weighted reduce + fp16 split =======
__global__ void pfin(float* __restrict__ hfin, float* __restrict__ cfin,
                     float* __restrict__ ponder_out)
{
    int m = blockIdx.x;
    int j = threadIdx.x;
    __shared__ float ps[NS];
    if (j == 0) {
        const float thresh = 1.0f - 0.01f;
        float halts[NS];
        float cum = 0.f; int nh = NS - 1; bool found = false;
#pragma unroll
        for (int n = 0; n < NS; n++) {
            halts[n] = g_halt[n * BD + m];
            cum += halts[n];
            if (!found && cum >= thresh) { nh = n; found = true; }
        }
        float s = 0.f;
#pragma unroll
        for (int n = 0; n < NS; n++) {
            float p = (n < nh) ? halts[n] : 0.f;
            if (n < nh) s += p;
            ps[n] = p;
        }
        float r = 1.f - s;
        ps[nh] = r;
        ponder_out[m] = (float)nh + 1.f + r;
    }
    __syncthreads();
    float ah = 0.f, ac = 0.f;
#pragma unroll
    for (int n = 0; n < NS; n++) {
        float p = ps[n];
        if (p != 0.f) {
            size_t o = ((size_t)n * BD + m) * HD + j;
            ah += p * g_hs[o];
            ac += p * g_cs[o];
        }
    }
    hfin[(size_t)m * HD + j] = ah;
    cfin[(size_t)m * HD + j] = ac;
    __half hh = __float2half(ah);
    g_hf_hi[(size_t)m * HD + j] = hh;
    g_hf_lo[(size_t)m * HD + j] = __float2half(ah - __half2float(hh));
}

// ======================= launcher =======================
extern "C" void kernel_launch(void* const* d_in, const int* in_sizes, int n_in,
                              void* d_out, int out_size)
{
    const float* x     = (const float*)d_in[0];
    const float* h0    = (const float*)d_in[1];
    const float* c0    = (const float*)d_in[2];
    const float* Wih   = (const float*)d_in[3];
    const float* bih   = (const float*)d_in[4];
    const float* Whh   = (const float*)d_in[5];
    const float* bhh   = (const float*)d_in[6];
    const float* Whalt = (const float*)d_in[7];
    const float* bhalt = (const float*)d_in[8];
    const float* Wout  = (const float*)d_in[9];
    const float* bout  = (const float*)d_in[10];
    (void)in_sizes; (void)n_in; (void)out_size;

    float* out   = (float*)d_out;
    float* out_y = out;
    float* out_h = out + (size_t)BD * HD;
    float* out_c = out + (size_t)BD * HD * 2;
    float* out_p = out + (size_t)BD * HD * 3;

    cudaFuncSetAttribute(mma_gemm<0>, cudaFuncAttributeMaxDynamicSharedMemorySize, DSMEM_BYTES);
    cudaFuncSetAttribute(mma_gemm<1>, cudaFuncAttributeMaxDynamicSharedMemorySize, DSMEM_BYTES);
    cudaFuncSetAttribute(gemm_n64, cudaFuncAttributeMaxDynamicSharedMemorySize, DSMEM64);
    cudaFuncSetAttribute(act_tail, cudaFuncAttributeMaxDynamicSharedMemorySize, TAIL_SMEM);

    __half *Whh_hi, *Whh_lo, *Wih_hi, *Wih_lo, *Wout_hi, *Wout_lo;
    __half *x_hi, *x_lo, *h_hi, *h_lo, *hf_hi, *hf_lo;
    float *wflag, *biasp, *xb, *hs, *cs;
    int *listb;
    cudaGetSymbolAddress((void**)&Whh_hi, g_Whh_hi);
    cudaGetSymbolAddress((void**)&Whh_lo, g_Whh_lo);
    cudaGetSymbolAddress((void**)&Wih_hi, g_Wih_hi);
    cudaGetSymbolAddress((void**)&Wih_lo, g_Wih_lo);
    cudaGetSymbolAddress((void**)&Wout_hi, g_Wout_hi);
    cudaGetSymbolAddress((void**)&Wout_lo, g_Wout_lo);
    cudaGetSymbolAddress((void**)&x_hi, g_x_hi);
    cudaGetSymbolAddress((void**)&x_lo, g_x_lo);
    cudaGetSymbolAddress((void**)&h_hi, g_h_hi);
    cudaGetSymbolAddress((void**)&h_lo, g_h_lo);
    cudaGetSymbolAddress((void**)&hf_hi, g_hf_hi);
    cudaGetSymbolAddress((void**)&hf_lo, g_hf_lo);
    cudaGetSymbolAddress((void**)&wflag, g_wflag);
    cudaGetSymbolAddress((void**)&biasp, g_bias);
    cudaGetSymbolAddress((void**)&xb, g_xb);
    cudaGetSymbolAddress((void**)&hs, g_hs);
    cudaGetSymbolAddress((void**)&cs, g_cs);
    cudaGetSymbolAddress((void**)&listb, g_list);

    const size_t HBUF = (size_t)BD * HD;

    // 1) merged prep
    prep_all<<<(BD * HD + 255) / 256, 256>>>(Wih, Whh, bih, bhh, x, h0, Wout);

    // 2) x-part GEMM
    dim3 gridG(G4 / 128, BD / 128);
    mma_gemm<0><<<gridG, 256, DSMEM_BYTES>>>(x_hi, x_lo, Wih_hi, Wih_lo, G4, biasp, xb,
                                             nullptr, nullptr, -1, nullptr, nullptr, nullptr,
                                             nullptr, nullptr, nullptr, nullptr);

    // 3) steps 0..TAIL0-1: GEMM (writes halt partials from registers) + cheap compact
    for (int n = 0; n < TAIL0; n++) {
        const float* c_i = (n == 0) ? c0 : (cs + (size_t)(n - 1) * HBUF);
        mma_gemm<1><<<gridG, 256, DSMEM_BYTES>>>(
            h_hi + (size_t)(n & 1) * HBUF, h_lo + (size_t)(n & 1) * HBUF,
            Whh_hi, Whh_lo, G4, nullptr, nullptr,
            xb, wflag, n,
            c_i, hs + (size_t)n * HBUF, cs + (size_t)n * HBUF,
            h_hi + (size_t)((n + 1) & 1) * HBUF, h_lo + (size_t)((n + 1) & 1) * HBUF,
            listb + (size_t)(n & 1) * BD, Whalt);
        halt_compact<<<NCB, 256>>>(n, bhalt);
    }

    // 4) persistent straggler tail (typically instant exit)
    act_tail<<<TAILG, 256, TAIL_SMEM>>>(Whalt, bhalt);

    // 5) halting scan + h_fin / c_fin (+ fp16 split)
    pfin<<<BD, HD>>>(out_h, out_c, out_p);

    // 6) output GEMM
    dim3 gridO(HD / 128, BD / 64);
    gemm_n64<<<gridO, 256, DSMEM64>>>(hf_hi, hf_lo, Wout_hi, Wout_lo, HD, bout, out_y);
}